// round 1
// baseline (speedup 1.0000x reference)
#include <cuda_runtime.h>
#include <cuda_bf16.h>

// Problem shape (fixed by reference)
#define BB 2
#define LL 2048
#define DD 1024
#define HH 16
#define HD 64
#define MM (BB*LL)   // 4096

// Scratch (allocation-free rule: __device__ globals)
__device__ float g_Q[MM*DD];
__device__ float g_K[MM*DD];
__device__ float g_V[MM*DD];
__device__ float g_Mix[MM*DD];

// ---------------------------------------------------------------------------
// GEMM: C[M,N] = A[M,K] @ W[N,K]^T + bias[N]   (M=4096, N=K=1024)
// 64x64 block tile, BK=16, 256 threads, 4x4 microtile per thread.
// ---------------------------------------------------------------------------
__global__ __launch_bounds__(256) void gemm64(const float* __restrict__ A,
                                              const float* __restrict__ W,
                                              const float* __restrict__ bias,
                                              float* __restrict__ C) {
    const int K = 1024, N = 1024;
    __shared__ float As[16][64];
    __shared__ float Bs[16][64];

    int bm = blockIdx.y * 64;
    int bn = blockIdx.x * 64;
    int tid = threadIdx.x;
    int tx = tid & 15;       // 0..15 -> N direction
    int ty = tid >> 4;       // 0..15 -> M direction

    int lr = tid >> 2;       // 0..63 : row within tile for loads
    int lq = tid & 3;        // 0..3  : float4 index within 16-wide K slab

    const float4* Arow = reinterpret_cast<const float4*>(A + (size_t)(bm + lr) * K);
    const float4* Wrow = reinterpret_cast<const float4*>(W + (size_t)(bn + lr) * K);

    float acc[4][4];
#pragma unroll
    for (int i = 0; i < 4; i++)
#pragma unroll
        for (int j = 0; j < 4; j++) acc[i][j] = 0.f;

    for (int k0 = 0; k0 < K; k0 += 16) {
        float4 a = Arow[(k0 >> 2) + lq];
        float4 w = Wrow[(k0 >> 2) + lq];
        As[lq*4+0][lr] = a.x; As[lq*4+1][lr] = a.y;
        As[lq*4+2][lr] = a.z; As[lq*4+3][lr] = a.w;
        Bs[lq*4+0][lr] = w.x; Bs[lq*4+1][lr] = w.y;
        Bs[lq*4+2][lr] = w.z; Bs[lq*4+3][lr] = w.w;
        __syncthreads();

#pragma unroll
        for (int k = 0; k < 16; k++) {
            float4 av = *reinterpret_cast<const float4*>(&As[k][ty*4]);
            float4 bv = *reinterpret_cast<const float4*>(&Bs[k][tx*4]);
            float ar[4] = {av.x, av.y, av.z, av.w};
            float br[4] = {bv.x, bv.y, bv.z, bv.w};
#pragma unroll
            for (int i = 0; i < 4; i++)
#pragma unroll
                for (int j = 0; j < 4; j++) acc[i][j] += ar[i] * br[j];
        }
        __syncthreads();
    }

#pragma unroll
    for (int i = 0; i < 4; i++) {
        int m = bm + ty*4 + i;
#pragma unroll
        for (int j = 0; j < 4; j++) {
            int n = bn + tx*4 + j;
            float v = acc[i][j];
            if (bias) v += bias[n];
            C[(size_t)m * N + n] = v;
        }
    }
}

// ---------------------------------------------------------------------------
// Fused causal attention with online softmax (flash-attention style), fp32.
// Grid: (L/32, H, B). Block: 256 threads. One block = 32 query rows of one
// (batch, head). KV tiles of 32 rows streamed through shared memory.
// ---------------------------------------------------------------------------
__global__ __launch_bounds__(256) void attn_kernel(const float* __restrict__ Q,
                                                   const float* __restrict__ K,
                                                   const float* __restrict__ V,
                                                   float* __restrict__ Out) {
    int i0 = blockIdx.x * 32;
    int h  = blockIdx.y;
    int b  = blockIdx.z;

    __shared__ float Qs[32][64];
    __shared__ float Ks[32][65];   // +1 pad: conflict-free column reads in S
    __shared__ float Vs[32][64];
    __shared__ float S[32][32];
    __shared__ float Oacc[32][64];
    __shared__ float mrow[32], lrow[32], arow[32];

    int tid = threadIdx.x;
    const float scale = 0.125f;  // 1/sqrt(64)

    const size_t base_q = ((size_t)(b * LL + i0)) * DD + h * HD;

    for (int e = tid; e < 32*64; e += 256) {
        int r = e >> 6, d = e & 63;
        Qs[r][d] = Q[base_q + (size_t)r * DD + d] * scale;
        Oacc[r][d] = 0.f;
    }
    if (tid < 32) { mrow[tid] = -1e30f; lrow[tid] = 0.f; }
    __syncthreads();

    for (int j0 = 0; j0 <= i0; j0 += 32) {
        const size_t base_kv = ((size_t)(b * LL + j0)) * DD + h * HD;
        for (int e = tid; e < 32*64; e += 256) {
            int r = e >> 6, d = e & 63;
            Ks[r][d] = K[base_kv + (size_t)r * DD + d];
            Vs[r][d] = V[base_kv + (size_t)r * DD + d];
        }
        __syncthreads();

        // S = Q K^T with causal mask. 1024 elems / 256 thr = 4 each.
        for (int e = tid; e < 32*32; e += 256) {
            int r = e >> 5, c = e & 31;
            float s;
            if (j0 + c <= i0 + r) {
                s = 0.f;
#pragma unroll
                for (int d = 0; d < 64; d++) s += Qs[r][d] * Ks[c][d];
            } else {
                s = -1e30f;
            }
            S[r][c] = s;
        }
        __syncthreads();

        // Online softmax: one thread per row.
        if (tid < 32) {
            int r = tid;
            float mold = mrow[r];
            float mn = mold;
#pragma unroll
            for (int c = 0; c < 32; c++) mn = fmaxf(mn, S[r][c]);
            float alpha = __expf(mold - mn);
            float ls = lrow[r] * alpha;
#pragma unroll
            for (int c = 0; c < 32; c++) {
                float p = __expf(S[r][c] - mn);
                S[r][c] = p;
                ls += p;
            }
            mrow[r] = mn; lrow[r] = ls; arow[r] = alpha;
        }
        __syncthreads();

        // O = O*alpha + P @ V. 2048 elems / 256 thr = 8 each.
        for (int e = tid; e < 32*64; e += 256) {
            int r = e >> 6, d = e & 63;
            float o = Oacc[r][d] * arow[r];
#pragma unroll
            for (int c = 0; c < 32; c++) o += S[r][c] * Vs[c][d];
            Oacc[r][d] = o;
        }
        __syncthreads();
    }

    for (int e = tid; e < 32*64; e += 256) {
        int r = e >> 6, d = e & 63;
        Out[base_q + (size_t)r * DD + d] = Oacc[r][d] / lrow[r];
    }
}

// ---------------------------------------------------------------------------
extern "C" void kernel_launch(void* const* d_in, const int* in_sizes, int n_in,
                              void* d_out, int out_size) {
    const float* x  = (const float*)d_in[0];
    const float* WQ = (const float*)d_in[1];
    const float* bQ = (const float*)d_in[2];
    const float* WK = (const float*)d_in[3];
    const float* bK = (const float*)d_in[4];
    const float* WV = (const float*)d_in[5];
    const float* bV = (const float*)d_in[6];
    const float* Wc = (const float*)d_in[7];
    float* out = (float*)d_out;

    float *Q, *K, *V, *Mix;
    cudaGetSymbolAddress((void**)&Q,   g_Q);
    cudaGetSymbolAddress((void**)&K,   g_K);
    cudaGetSymbolAddress((void**)&V,   g_V);
    cudaGetSymbolAddress((void**)&Mix, g_Mix);

    dim3 gg(1024/64, MM/64);   // (16, 64)
    gemm64<<<gg, 256>>>(x, WQ, bQ, Q);
    gemm64<<<gg, 256>>>(x, WK, bK, K);
    gemm64<<<gg, 256>>>(x, WV, bV, V);

    dim3 ga(LL/32, HH, BB);    // (64, 16, 2)
    attn_kernel<<<ga, 256>>>(Q, K, V, Mix);

    gemm64<<<gg, 256>>>(Mix, Wc, nullptr, out);
}

// round 3
// speedup vs baseline: 2.1366x; 2.1366x over previous
#include <cuda_runtime.h>
#include <cuda_bf16.h>
#include <cstdint>

// Problem shape (fixed)
#define BB 2
#define LL 2048
#define DD 1024
#define HH 16
#define HD 64
#define MM (BB*LL)   // 4096

// ---------------------------------------------------------------------------
// Scratch (__device__ globals: allocation-free rule)
// ---------------------------------------------------------------------------
__device__ float g_Q[MM*DD];
__device__ float g_K[MM*DD];
__device__ float g_V[MM*DD];
__device__ float g_Mix[MM*DD];
__device__ __nv_bfloat16 g_xhi[MM*DD];
__device__ __nv_bfloat16 g_xlo[MM*DD];
__device__ __nv_bfloat16 g_mhi[MM*DD];
__device__ __nv_bfloat16 g_mlo[MM*DD];
__device__ __nv_bfloat16 g_whi[4*DD*DD];
__device__ __nv_bfloat16 g_wlo[4*DD*DD];

// ---------------------------------------------------------------------------
// Portable-ISA helpers (NO tcgen05 / NO 'a'-gated features)
// ---------------------------------------------------------------------------
__device__ __forceinline__ uint32_t smem_u32(const void* p) {
    uint32_t a;
    asm("{ .reg .u64 t; cvta.to.shared.u64 t, %1; cvt.u32.u64 %0, t; }" : "=r"(a) : "l"(p));
    return a;
}
__device__ __forceinline__ void ldsm_x4(uint32_t& r0, uint32_t& r1, uint32_t& r2, uint32_t& r3,
                                        uint32_t addr) {
    asm volatile("ldmatrix.sync.aligned.m8n8.x4.shared.b16 {%0,%1,%2,%3}, [%4];"
                 : "=r"(r0), "=r"(r1), "=r"(r2), "=r"(r3) : "r"(addr));
}
__device__ __forceinline__ void mma16816(float& c0, float& c1, float& c2, float& c3,
                                         uint32_t a0, uint32_t a1, uint32_t a2, uint32_t a3,
                                         uint32_t b0, uint32_t b1) {
    asm volatile("mma.sync.aligned.m16n8k16.row.col.f32.bf16.bf16.f32 "
                 "{%0,%1,%2,%3}, {%4,%5,%6,%7}, {%8,%9}, {%0,%1,%2,%3};"
                 : "+f"(c0), "+f"(c1), "+f"(c2), "+f"(c3)
                 : "r"(a0), "r"(a1), "r"(a2), "r"(a3), "r"(b0), "r"(b1));
}

// ---------------------------------------------------------------------------
// fp32 -> (bf16 hi, bf16 lo) split, vectorized
// ---------------------------------------------------------------------------
__global__ __launch_bounds__(256) void split_kernel(const float* __restrict__ in,
                                                    __nv_bfloat16* __restrict__ hi,
                                                    __nv_bfloat16* __restrict__ lo,
                                                    int n4) {
    int i = blockIdx.x * 256 + threadIdx.x;
    if (i >= n4) return;
    float4 v = reinterpret_cast<const float4*>(in)[i];
    __nv_bfloat16 h0 = __float2bfloat16(v.x), h1 = __float2bfloat16(v.y);
    __nv_bfloat16 h2 = __float2bfloat16(v.z), h3 = __float2bfloat16(v.w);
    __nv_bfloat16 l0 = __float2bfloat16(v.x - __bfloat162float(h0));
    __nv_bfloat16 l1 = __float2bfloat16(v.y - __bfloat162float(h1));
    __nv_bfloat16 l2 = __float2bfloat16(v.z - __bfloat162float(h2));
    __nv_bfloat16 l3 = __float2bfloat16(v.w - __bfloat162float(h3));
    __nv_bfloat162* H = reinterpret_cast<__nv_bfloat162*>(hi);
    __nv_bfloat162* L = reinterpret_cast<__nv_bfloat162*>(lo);
    H[2*i]   = __nv_bfloat162(h0, h1);
    H[2*i+1] = __nv_bfloat162(h2, h3);
    L[2*i]   = __nv_bfloat162(l0, l1);
    L[2*i+1] = __nv_bfloat162(l2, l3);
}

// ---------------------------------------------------------------------------
// HMMA GEMM: C[M,1024] = (Ahi+Alo)[M,1024] @ (Whi+Wlo)[1024,1024]^T + bias
// 3-pass split-bf16 via mma.sync.m16n8k16, fp32 accumulate.
// CTA tile 128x64, BK=32, 256 threads (8 warps, 4x2 warp grid, 32x32/warp).
// ---------------------------------------------------------------------------
#define GK 1024
#define BM 128
#define BN 64
#define BK 32
#define APAD 40   // bf16 row stride: banks hit by ldmatrix rows = 20r mod 32, all distinct

__global__ __launch_bounds__(256) void gemm_hmma(const __nv_bfloat16* __restrict__ Ahi,
                                                 const __nv_bfloat16* __restrict__ Alo,
                                                 const __nv_bfloat16* __restrict__ Whi,
                                                 const __nv_bfloat16* __restrict__ Wlo,
                                                 const float* __restrict__ bias,
                                                 float* __restrict__ C) {
    __shared__ __nv_bfloat16 sAhi[BM][APAD];
    __shared__ __nv_bfloat16 sAlo[BM][APAD];
    __shared__ __nv_bfloat16 sWhi[BN][APAD];
    __shared__ __nv_bfloat16 sWlo[BN][APAD];

    const int tid  = threadIdx.x;
    const int wid  = tid >> 5;
    const int lane = tid & 31;
    const int wm   = wid >> 1;     // 0..3 -> 32-row slab
    const int wn   = wid & 1;      // 0..1 -> 32-col slab
    const int bm   = blockIdx.y * BM;
    const int bn   = blockIdx.x * BN;

    const uint32_t aAhi = smem_u32(sAhi);
    const uint32_t aAlo = smem_u32(sAlo);
    const uint32_t aWhi = smem_u32(sWhi);
    const uint32_t aWlo = smem_u32(sWlo);

    float acc[2][4][4];
#pragma unroll
    for (int i = 0; i < 2; i++)
#pragma unroll
        for (int j = 0; j < 4; j++)
#pragma unroll
            for (int k = 0; k < 4; k++) acc[i][j][k] = 0.f;

    const int lr = tid >> 2;       // 0..63
    const int lq = tid & 3;        // 0..3 (16B chunk within 32-col slab)

    // ldmatrix source addresses (per lane)
    // A frag (m16k16): r=lane&15, half=lane>>4 -> row wm*32+mt*16+r, col kk+half*8
    const int a_r    = lane & 15;
    const int a_half = lane >> 4;
    // B frag x4 (two n-tiles): quad=lane>>3, rr=lane&7
    const int b_rr   = lane & 7;
    const int b_nt   = (lane >> 4) & 1;   // which of the 2 ntiles in this x4
    const int b_kh   = (lane >> 3) & 1;   // k half

    for (int k0 = 0; k0 < GK; k0 += BK) {
        // ---- load tiles ----
#pragma unroll
        for (int half = 0; half < 2; half++) {
            int r = lr + half * 64;
            const size_t off = (size_t)(bm + r) * GK + k0 + lq * 8;
            *reinterpret_cast<uint4*>(&sAhi[r][lq * 8]) =
                *reinterpret_cast<const uint4*>(Ahi + off);
            *reinterpret_cast<uint4*>(&sAlo[r][lq * 8]) =
                *reinterpret_cast<const uint4*>(Alo + off);
        }
        {
            const size_t off = (size_t)(bn + lr) * GK + k0 + lq * 8;
            *reinterpret_cast<uint4*>(&sWhi[lr][lq * 8]) =
                *reinterpret_cast<const uint4*>(Whi + off);
            *reinterpret_cast<uint4*>(&sWlo[lr][lq * 8]) =
                *reinterpret_cast<const uint4*>(Wlo + off);
        }
        __syncthreads();

#pragma unroll
        for (int ks = 0; ks < 2; ks++) {
            const int kk = ks * 16;
            // A fragments hi/lo for 2 m-tiles
            uint32_t ah[2][4], al[2][4];
#pragma unroll
            for (int mt = 0; mt < 2; mt++) {
                uint32_t off = (uint32_t)(wm * 32 + mt * 16 + a_r) * (APAD * 2)
                             + (kk + a_half * 8) * 2;
                ldsm_x4(ah[mt][0], ah[mt][1], ah[mt][2], ah[mt][3], aAhi + off);
                ldsm_x4(al[mt][0], al[mt][1], al[mt][2], al[mt][3], aAlo + off);
            }
            // B fragments hi/lo for 4 n-tiles (two x4 loads each)
            uint32_t bh[4][2], bl[4][2];
#pragma unroll
            for (int p = 0; p < 2; p++) {
                uint32_t off = (uint32_t)(wn * 32 + p * 16 + b_nt * 8 + b_rr) * (APAD * 2)
                             + (kk + b_kh * 8) * 2;
                ldsm_x4(bh[p*2][0], bh[p*2][1], bh[p*2+1][0], bh[p*2+1][1], aWhi + off);
                ldsm_x4(bl[p*2][0], bl[p*2][1], bl[p*2+1][0], bl[p*2+1][1], aWlo + off);
            }
            // 3-pass MMAs
#pragma unroll
            for (int mt = 0; mt < 2; mt++)
#pragma unroll
                for (int nt = 0; nt < 4; nt++) {
                    float* c = acc[mt][nt];
                    mma16816(c[0], c[1], c[2], c[3],
                             ah[mt][0], ah[mt][1], ah[mt][2], ah[mt][3],
                             bh[nt][0], bh[nt][1]);
                    mma16816(c[0], c[1], c[2], c[3],
                             ah[mt][0], ah[mt][1], ah[mt][2], ah[mt][3],
                             bl[nt][0], bl[nt][1]);
                    mma16816(c[0], c[1], c[2], c[3],
                             al[mt][0], al[mt][1], al[mt][2], al[mt][3],
                             bh[nt][0], bh[nt][1]);
                }
        }
        __syncthreads();
    }

    // ---- epilogue ----
    const int gid = lane >> 2;
    const int tig = lane & 3;
#pragma unroll
    for (int mt = 0; mt < 2; mt++) {
#pragma unroll
        for (int nt = 0; nt < 4; nt++) {
            int row = bm + wm * 32 + mt * 16 + gid;
            int col = bn + wn * 32 + nt * 8 + 2 * tig;
            float b0 = bias ? bias[col]     : 0.f;
            float b1 = bias ? bias[col + 1] : 0.f;
            float2 v0 = make_float2(acc[mt][nt][0] + b0, acc[mt][nt][1] + b1);
            float2 v1 = make_float2(acc[mt][nt][2] + b0, acc[mt][nt][3] + b1);
            *reinterpret_cast<float2*>(C + (size_t)row * GK + col)       = v0;
            *reinterpret_cast<float2*>(C + (size_t)(row + 8) * GK + col) = v1;
        }
    }
}

// ---------------------------------------------------------------------------
// Attention: 4 warps x 8 query rows, register O accumulators,
// warp-private online softmax (shuffle reductions), fp32.
// ---------------------------------------------------------------------------
__global__ __launch_bounds__(128) void attn2(const float* __restrict__ Q,
                                             const float* __restrict__ K,
                                             const float* __restrict__ V,
                                             float* __restrict__ Out) {
    __shared__ float Qs[32][64];
    __shared__ float Ks[32][68];
    __shared__ float Vs[32][68];
    __shared__ float Ps[32][36];

    const int i0 = blockIdx.x * 32;
    const int h  = blockIdx.y;
    const int b  = blockIdx.z;
    const int tid  = threadIdx.x;
    const int w    = tid >> 5;
    const int lane = tid & 31;
    const float scale = 0.125f;

    const size_t base_q = ((size_t)(b * LL + i0)) * DD + h * HD;

#pragma unroll
    for (int it = 0; it < 4; it++) {
        int e = it * 128 + tid;
        int r = e >> 4, d4 = e & 15;
        float4 v = *reinterpret_cast<const float4*>(Q + base_q + (size_t)r * DD + d4 * 4);
        v.x *= scale; v.y *= scale; v.z *= scale; v.w *= scale;
        *reinterpret_cast<float4*>(&Qs[r][d4 * 4]) = v;
    }

    float o[8][2];
    float mr[8], lr[8];
#pragma unroll
    for (int r = 0; r < 8; r++) { o[r][0] = 0.f; o[r][1] = 0.f; mr[r] = -1e30f; lr[r] = 0.f; }

    const int myrow0 = i0 + w * 8;

    for (int j0 = 0; j0 <= i0; j0 += 32) {
        const size_t base_kv = ((size_t)(b * LL + j0)) * DD + h * HD;
#pragma unroll
        for (int it = 0; it < 4; it++) {
            int e = it * 128 + tid;
            int r = e >> 4, d4 = e & 15;
            *reinterpret_cast<float4*>(&Ks[r][d4 * 4]) =
                *reinterpret_cast<const float4*>(K + base_kv + (size_t)r * DD + d4 * 4);
            *reinterpret_cast<float4*>(&Vs[r][d4 * 4]) =
                *reinterpret_cast<const float4*>(V + base_kv + (size_t)r * DD + d4 * 4);
        }
        __syncthreads();

        // ---- S = Q K^T : lane = key column c ----
        const int c = lane;
        float s[8];
#pragma unroll
        for (int r = 0; r < 8; r++) s[r] = 0.f;
#pragma unroll
        for (int d4 = 0; d4 < 16; d4++) {
            float4 kk = *reinterpret_cast<const float4*>(&Ks[c][d4 * 4]);
#pragma unroll
            for (int r = 0; r < 8; r++) {
                float4 qq = *reinterpret_cast<const float4*>(&Qs[w * 8 + r][d4 * 4]);
                s[r] += qq.x * kk.x + qq.y * kk.y + qq.z * kk.z + qq.w * kk.w;
            }
        }
#pragma unroll
        for (int r = 0; r < 8; r++)
            if (j0 + c > myrow0 + r) s[r] = -1e30f;

        // ---- warp-private online softmax over 32 cols ----
        float mnew[8];
#pragma unroll
        for (int r = 0; r < 8; r++) mnew[r] = s[r];
#pragma unroll
        for (int st = 16; st >= 1; st >>= 1)
#pragma unroll
            for (int r = 0; r < 8; r++)
                mnew[r] = fmaxf(mnew[r], __shfl_xor_sync(0xFFFFFFFFu, mnew[r], st));
        float al[8], p[8];
#pragma unroll
        for (int r = 0; r < 8; r++) {
            float mn = fmaxf(mr[r], mnew[r]);
            al[r] = __expf(mr[r] - mn);
            p[r]  = __expf(s[r] - mn);
            mr[r] = mn;
        }
        float psum[8];
#pragma unroll
        for (int r = 0; r < 8; r++) psum[r] = p[r];
#pragma unroll
        for (int st = 16; st >= 1; st >>= 1)
#pragma unroll
            for (int r = 0; r < 8; r++)
                psum[r] += __shfl_xor_sync(0xFFFFFFFFu, psum[r], st);
#pragma unroll
        for (int r = 0; r < 8; r++) {
            lr[r] = lr[r] * al[r] + psum[r];
            Ps[w * 8 + r][c] = p[r];
        }
        __syncwarp();

        // ---- O += P @ V : lane owns cols d0=2*lane, d0+1 ----
#pragma unroll
        for (int r = 0; r < 8; r++) { o[r][0] *= al[r]; o[r][1] *= al[r]; }
        const int d0 = 2 * lane;
#pragma unroll
        for (int c4 = 0; c4 < 32; c4 += 4) {
            float2 v0 = *reinterpret_cast<const float2*>(&Vs[c4 + 0][d0]);
            float2 v1 = *reinterpret_cast<const float2*>(&Vs[c4 + 1][d0]);
            float2 v2 = *reinterpret_cast<const float2*>(&Vs[c4 + 2][d0]);
            float2 v3 = *reinterpret_cast<const float2*>(&Vs[c4 + 3][d0]);
#pragma unroll
            for (int r = 0; r < 8; r++) {
                float4 pf = *reinterpret_cast<const float4*>(&Ps[w * 8 + r][c4]);
                o[r][0] += pf.x * v0.x + pf.y * v1.x + pf.z * v2.x + pf.w * v3.x;
                o[r][1] += pf.x * v0.y + pf.y * v1.y + pf.z * v2.y + pf.w * v3.y;
            }
        }
        __syncthreads();
    }

#pragma unroll
    for (int r = 0; r < 8; r++) {
        float inv = 1.0f / lr[r];
        float2 v = make_float2(o[r][0] * inv, o[r][1] * inv);
        *reinterpret_cast<float2*>(Out + base_q + (size_t)(w * 8 + r) * DD + 2 * lane) = v;
    }
}

// ---------------------------------------------------------------------------
extern "C" void kernel_launch(void* const* d_in, const int* in_sizes, int n_in,
                              void* d_out, int out_size) {
    const float* x  = (const float*)d_in[0];
    const float* WQ = (const float*)d_in[1];
    const float* bQ = (const float*)d_in[2];
    const float* WK = (const float*)d_in[3];
    const float* bK = (const float*)d_in[4];
    const float* WV = (const float*)d_in[5];
    const float* bV = (const float*)d_in[6];
    const float* Wc = (const float*)d_in[7];
    float* out = (float*)d_out;

    float *Q, *K, *V, *Mix;
    __nv_bfloat16 *xhi, *xlo, *mhi, *mlo, *whi, *wlo;
    cudaGetSymbolAddress((void**)&Q,   g_Q);
    cudaGetSymbolAddress((void**)&K,   g_K);
    cudaGetSymbolAddress((void**)&V,   g_V);
    cudaGetSymbolAddress((void**)&Mix, g_Mix);
    cudaGetSymbolAddress((void**)&xhi, g_xhi);
    cudaGetSymbolAddress((void**)&xlo, g_xlo);
    cudaGetSymbolAddress((void**)&mhi, g_mhi);
    cudaGetSymbolAddress((void**)&mlo, g_mlo);
    cudaGetSymbolAddress((void**)&whi, g_whi);
    cudaGetSymbolAddress((void**)&wlo, g_wlo);

    const int nx4 = MM * DD / 4;
    const int nw4 = DD * DD / 4;

    split_kernel<<<(nx4 + 255) / 256, 256>>>(x,  xhi, xlo, nx4);
    split_kernel<<<(nw4 + 255) / 256, 256>>>(WQ, whi + 0*DD*DD, wlo + 0*DD*DD, nw4);
    split_kernel<<<(nw4 + 255) / 256, 256>>>(WK, whi + 1*DD*DD, wlo + 1*DD*DD, nw4);
    split_kernel<<<(nw4 + 255) / 256, 256>>>(WV, whi + 2*DD*DD, wlo + 2*DD*DD, nw4);
    split_kernel<<<(nw4 + 255) / 256, 256>>>(Wc, whi + 3*DD*DD, wlo + 3*DD*DD, nw4);

    dim3 gg(DD / BN, MM / BM);         // (16, 32)
    gemm_hmma<<<gg, 256>>>(xhi, xlo, whi + 0*DD*DD, wlo + 0*DD*DD, bQ, Q);
    gemm_hmma<<<gg, 256>>>(xhi, xlo, whi + 1*DD*DD, wlo + 1*DD*DD, bK, K);
    gemm_hmma<<<gg, 256>>>(xhi, xlo, whi + 2*DD*DD, wlo + 2*DD*DD, bV, V);

    dim3 ga(LL / 32, HH, BB);          // (64, 16, 2)
    attn2<<<ga, 128>>>(Q, K, V, Mix);

    split_kernel<<<(nx4 + 255) / 256, 256>>>(Mix, mhi, mlo, nx4);
    gemm_hmma<<<gg, 256>>>(mhi, mlo, whi + 3*DD*DD, wlo + 3*DD*DD, nullptr, out);
}

// round 4
// speedup vs baseline: 4.3906x; 2.0550x over previous
#include <cuda_runtime.h>
#include <cuda_bf16.h>
#include <cstdint>

// Problem shape (fixed)
#define BB 2
#define LL 2048
#define DD 1024
#define HH 16
#define HD 64
#define MM (BB*LL)   // 4096

typedef __nv_bfloat16 bf16;

// ---------------------------------------------------------------------------
// Scratch (__device__ globals: allocation-free rule)
// ---------------------------------------------------------------------------
__device__ bf16 g_xhi[MM*DD], g_xlo[MM*DD];
__device__ bf16 g_whi[4*DD*DD], g_wlo[4*DD*DD];
__device__ bf16 g_qhi[MM*DD], g_qlo[MM*DD];
__device__ bf16 g_khi[MM*DD], g_klo[MM*DD];
__device__ bf16 g_vhi[MM*DD], g_vlo[MM*DD];
__device__ bf16 g_mhi[MM*DD], g_mlo[MM*DD];

// ---------------------------------------------------------------------------
// Helpers (portable ISA only; no 'a'-gated features)
// ---------------------------------------------------------------------------
__device__ __forceinline__ uint32_t smem_u32(const void* p) {
    uint32_t a;
    asm("{ .reg .u64 t; cvta.to.shared.u64 t, %1; cvt.u32.u64 %0, t; }" : "=r"(a) : "l"(p));
    return a;
}
__device__ __forceinline__ void ldsm_x4(uint32_t& r0, uint32_t& r1, uint32_t& r2, uint32_t& r3,
                                        uint32_t addr) {
    asm volatile("ldmatrix.sync.aligned.m8n8.x4.shared.b16 {%0,%1,%2,%3}, [%4];"
                 : "=r"(r0), "=r"(r1), "=r"(r2), "=r"(r3) : "r"(addr));
}
__device__ __forceinline__ void ldsm_x4t(uint32_t& r0, uint32_t& r1, uint32_t& r2, uint32_t& r3,
                                         uint32_t addr) {
    asm volatile("ldmatrix.sync.aligned.m8n8.x4.trans.shared.b16 {%0,%1,%2,%3}, [%4];"
                 : "=r"(r0), "=r"(r1), "=r"(r2), "=r"(r3) : "r"(addr));
}
__device__ __forceinline__ void mma4(float* c, const uint32_t* a, const uint32_t* b) {
    asm volatile("mma.sync.aligned.m16n8k16.row.col.f32.bf16.bf16.f32 "
                 "{%0,%1,%2,%3}, {%4,%5,%6,%7}, {%8,%9}, {%0,%1,%2,%3};"
                 : "+f"(c[0]), "+f"(c[1]), "+f"(c[2]), "+f"(c[3])
                 : "r"(a[0]), "r"(a[1]), "r"(a[2]), "r"(a[3]), "r"(b[0]), "r"(b[1]));
}
__device__ __forceinline__ void cp16(uint32_t dst, const void* src) {
    asm volatile("cp.async.cg.shared.global [%0], [%1], 16;" :: "r"(dst), "l"(src));
}
#define CP_COMMIT() asm volatile("cp.async.commit_group;" ::: "memory")
#define CP_WAIT0()  asm volatile("cp.async.wait_group 0;" ::: "memory")

__device__ __forceinline__ uint32_t packbf2(float a, float b) {
    __nv_bfloat162 t = __floats2bfloat162_rn(a, b);
    return *reinterpret_cast<uint32_t*>(&t);
}

// ---------------------------------------------------------------------------
// fp32 -> (bf16 hi, bf16 lo) split (for x and the weights)
// ---------------------------------------------------------------------------
__global__ __launch_bounds__(256) void split_kernel(const float* __restrict__ in,
                                                    bf16* __restrict__ hi,
                                                    bf16* __restrict__ lo,
                                                    int n4) {
    int i = blockIdx.x * 256 + threadIdx.x;
    if (i >= n4) return;
    float4 v = reinterpret_cast<const float4*>(in)[i];
    bf16 h0 = __float2bfloat16(v.x), h1 = __float2bfloat16(v.y);
    bf16 h2 = __float2bfloat16(v.z), h3 = __float2bfloat16(v.w);
    bf16 l0 = __float2bfloat16(v.x - __bfloat162float(h0));
    bf16 l1 = __float2bfloat16(v.y - __bfloat162float(h1));
    bf16 l2 = __float2bfloat16(v.z - __bfloat162float(h2));
    bf16 l3 = __float2bfloat16(v.w - __bfloat162float(h3));
    __nv_bfloat162* H = reinterpret_cast<__nv_bfloat162*>(hi);
    __nv_bfloat162* L = reinterpret_cast<__nv_bfloat162*>(lo);
    H[2*i]   = __nv_bfloat162(h0, h1);
    H[2*i+1] = __nv_bfloat162(h2, h3);
    L[2*i]   = __nv_bfloat162(l0, l1);
    L[2*i+1] = __nv_bfloat162(l2, l3);
}

// ---------------------------------------------------------------------------
// HMMA GEMM, cp.async double-buffered.
// C = (Ahi+Alo) @ (Whi+Wlo)^T + bias ; epilogue: fp32 OR scaled split-bf16.
// CTA 128x64, BK=32, 256 threads (8 warps, 4x2, 32x32 each).
// ---------------------------------------------------------------------------
#define GK 1024
#define BM 128
#define BN 64
#define BK 32
#define APAD 40                       // row stride (bf16): conflict-free ldsm
#define SZ_A (BM*APAD*2)              // 10240 B
#define SZ_W (BN*APAD*2)              // 5120 B
#define STG  (2*SZ_A + 2*SZ_W)        // 30720 B per stage
#define GEMM_SMEM (2*STG)             // 61440 B

__global__ __launch_bounds__(256) void gemm_hmma(const bf16* __restrict__ Ahi,
                                                 const bf16* __restrict__ Alo,
                                                 const bf16* __restrict__ Whi,
                                                 const bf16* __restrict__ Wlo,
                                                 const float* __restrict__ bias,
                                                 float scale,
                                                 float* __restrict__ Cf,
                                                 bf16* __restrict__ Chi,
                                                 bf16* __restrict__ Clo) {
    extern __shared__ __align__(16) char dsm[];
    const uint32_t sb0 = smem_u32(dsm);
    const int tid  = threadIdx.x;
    const int wid  = tid >> 5;
    const int lane = tid & 31;
    const int wm   = wid >> 1;
    const int wn   = wid & 1;
    const int bm   = blockIdx.y * BM;
    const int bn   = blockIdx.x * BN;

    float acc[2][4][4];
#pragma unroll
    for (int i = 0; i < 2; i++)
#pragma unroll
        for (int j = 0; j < 4; j++)
#pragma unroll
            for (int k = 0; k < 4; k++) acc[i][j][k] = 0.f;

    auto issue = [&](int stg, int k0) {
        uint32_t base = sb0 + stg * STG;
        // A tiles: 512 16B-chunks each, 2 per thread
#pragma unroll
        for (int i = 0; i < 2; i++) {
            int c = tid + 256 * i;
            int r = c >> 2, q = c & 3;
            const size_t off = (size_t)(bm + r) * GK + k0 + q * 8;
            cp16(base + r * 80 + q * 16,          Ahi + off);
            cp16(base + SZ_A + r * 80 + q * 16,   Alo + off);
        }
        // W tiles: 256 chunks each, 1 per thread
        {
            int r = tid >> 2, q = tid & 3;
            const size_t off = (size_t)(bn + r) * GK + k0 + q * 8;
            cp16(base + 2*SZ_A + r * 80 + q * 16,        Whi + off);
            cp16(base + 2*SZ_A + SZ_W + r * 80 + q * 16, Wlo + off);
        }
        CP_COMMIT();
    };

    const int a_r    = lane & 15;
    const int a_half = lane >> 4;
    const int b_rr   = lane & 7;
    const int b_nt   = (lane >> 4) & 1;
    const int b_kh   = (lane >> 3) & 1;

    issue(0, 0);
    const int NIT = GK / BK;
    for (int it = 0; it < NIT; it++) {
        CP_WAIT0();
        __syncthreads();
        if (it + 1 < NIT) issue((it + 1) & 1, (it + 1) * BK);

        const uint32_t base = sb0 + (it & 1) * STG;
        const uint32_t aAhi = base;
        const uint32_t aAlo = base + SZ_A;
        const uint32_t aWhi = base + 2*SZ_A;
        const uint32_t aWlo = base + 2*SZ_A + SZ_W;

#pragma unroll
        for (int ks = 0; ks < 2; ks++) {
            const int kk = ks * 16;
            uint32_t ah[2][4], al[2][4];
#pragma unroll
            for (int mt = 0; mt < 2; mt++) {
                uint32_t off = (uint32_t)(wm * 32 + mt * 16 + a_r) * 80 + (kk + a_half * 8) * 2;
                ldsm_x4(ah[mt][0], ah[mt][1], ah[mt][2], ah[mt][3], aAhi + off);
                ldsm_x4(al[mt][0], al[mt][1], al[mt][2], al[mt][3], aAlo + off);
            }
            uint32_t bh[4][2], bl[4][2];
#pragma unroll
            for (int p = 0; p < 2; p++) {
                uint32_t off = (uint32_t)(wn * 32 + p * 16 + b_nt * 8 + b_rr) * 80
                             + (kk + b_kh * 8) * 2;
                ldsm_x4(bh[p*2][0], bh[p*2][1], bh[p*2+1][0], bh[p*2+1][1], aWhi + off);
                ldsm_x4(bl[p*2][0], bl[p*2][1], bl[p*2+1][0], bl[p*2+1][1], aWlo + off);
            }
#pragma unroll
            for (int mt = 0; mt < 2; mt++)
#pragma unroll
                for (int nt = 0; nt < 4; nt++) {
                    mma4(acc[mt][nt], ah[mt], bh[nt]);
                    mma4(acc[mt][nt], ah[mt], bl[nt]);
                    mma4(acc[mt][nt], al[mt], bh[nt]);
                }
        }
        __syncthreads();
    }

    // ---- epilogue ----
    const int gid = lane >> 2;
    const int tig = lane & 3;
#pragma unroll
    for (int mt = 0; mt < 2; mt++) {
#pragma unroll
        for (int nt = 0; nt < 4; nt++) {
            int row = bm + wm * 32 + mt * 16 + gid;
            int col = bn + wn * 32 + nt * 8 + 2 * tig;
            float b0 = bias ? bias[col]     : 0.f;
            float b1 = bias ? bias[col + 1] : 0.f;
            float v00 = (acc[mt][nt][0] + b0) * scale;
            float v01 = (acc[mt][nt][1] + b1) * scale;
            float v10 = (acc[mt][nt][2] + b0) * scale;
            float v11 = (acc[mt][nt][3] + b1) * scale;
            if (Cf) {
                *reinterpret_cast<float2*>(Cf + (size_t)row * GK + col)       = make_float2(v00, v01);
                *reinterpret_cast<float2*>(Cf + (size_t)(row + 8) * GK + col) = make_float2(v10, v11);
            } else {
                __nv_bfloat162 h0 = __floats2bfloat162_rn(v00, v01);
                __nv_bfloat162 h1 = __floats2bfloat162_rn(v10, v11);
                __nv_bfloat162 l0 = __floats2bfloat162_rn(v00 - __bfloat162float(h0.x),
                                                          v01 - __bfloat162float(h0.y));
                __nv_bfloat162 l1 = __floats2bfloat162_rn(v10 - __bfloat162float(h1.x),
                                                          v11 - __bfloat162float(h1.y));
                *reinterpret_cast<__nv_bfloat162*>(Chi + (size_t)row * GK + col)       = h0;
                *reinterpret_cast<__nv_bfloat162*>(Clo + (size_t)row * GK + col)       = l0;
                *reinterpret_cast<__nv_bfloat162*>(Chi + (size_t)(row + 8) * GK + col) = h1;
                *reinterpret_cast<__nv_bfloat162*>(Clo + (size_t)(row + 8) * GK + col) = l1;
            }
        }
    }
}

// ---------------------------------------------------------------------------
// HMMA flash attention. Block = 128 threads (4 warps), 64 query rows,
// KV tiles of 64. Split-bf16 3-pass for S and PV; fp32 softmax.
// smem: K/V hi/lo tiles, 64 x (64+8) bf16 each; Q staged through K buffers.
// ---------------------------------------------------------------------------
#define ASTRIDE 72                     // bf16 elems per row (144 B)
#define ATILE (64*ASTRIDE)             // elems per tile

__global__ __launch_bounds__(128) void attn_mma(const bf16* __restrict__ Qhi,
                                                const bf16* __restrict__ Qlo,
                                                const bf16* __restrict__ Khi,
                                                const bf16* __restrict__ Klo,
                                                const bf16* __restrict__ Vhi,
                                                const bf16* __restrict__ Vlo,
                                                bf16* __restrict__ Ohi,
                                                bf16* __restrict__ Olo) {
    __shared__ __align__(16) bf16 sm[4 * ATILE];   // Kh, Kl, Vh, Vl

    const int i0 = blockIdx.x * 64;
    const int h  = blockIdx.y;
    const int b  = blockIdx.z;
    const int tid  = threadIdx.x;
    const int w    = tid >> 5;
    const int lane = tid & 31;
    const int gid  = lane >> 2;
    const int tig  = lane & 3;
    const int r0   = w * 16;

    const uint32_t aKh = smem_u32(sm);
    const uint32_t aKl = aKh + ATILE * 2;
    const uint32_t aVh = aKh + 2 * ATILE * 2;
    const uint32_t aVl = aKh + 3 * ATILE * 2;

    const size_t baseq = ((size_t)(b * LL + i0)) * DD + h * HD;

    // ---- stage Q into K buffers, pull fragments, release ----
#pragma unroll
    for (int i = 0; i < 4; i++) {
        int c = tid + 128 * i;         // 0..511
        int r = c >> 3, q = c & 7;
        const size_t off = baseq + (size_t)r * DD + q * 8;
        cp16(aKh + r * 144 + q * 16, Qhi + off);
        cp16(aKl + r * 144 + q * 16, Qlo + off);
    }
    CP_COMMIT(); CP_WAIT0();
    __syncthreads();

    const int a_r = lane & 15, a_h = lane >> 4;
    uint32_t qh[4][4], ql[4][4];
#pragma unroll
    for (int ks = 0; ks < 4; ks++) {
        uint32_t off = (uint32_t)(r0 + a_r) * 144 + (ks * 16 + a_h * 8) * 2;
        ldsm_x4(qh[ks][0], qh[ks][1], qh[ks][2], qh[ks][3], aKh + off);
        ldsm_x4(ql[ks][0], ql[ks][1], ql[ks][2], ql[ks][3], aKl + off);
    }
    __syncthreads();

    float o[8][4];
#pragma unroll
    for (int nt = 0; nt < 8; nt++)
#pragma unroll
        for (int k = 0; k < 4; k++) o[nt][k] = 0.f;
    float mrow0 = -1e30f, mrow1 = -1e30f, lrow0 = 0.f, lrow1 = 0.f;

    const int b_rr = lane & 7;
    const int b_nt = (lane >> 4) & 1;
    const int b_kh = (lane >> 3) & 1;

    for (int j0 = 0; j0 <= i0; j0 += 64) {
        const size_t basekv = ((size_t)(b * LL + j0)) * DD + h * HD;
#pragma unroll
        for (int i = 0; i < 4; i++) {
            int c = tid + 128 * i;
            int r = c >> 3, q = c & 7;
            const size_t off = basekv + (size_t)r * DD + q * 8;
            const uint32_t d = r * 144 + q * 16;
            cp16(aKh + d, Khi + off);
            cp16(aKl + d, Klo + off);
            cp16(aVh + d, Vhi + off);
            cp16(aVl + d, Vlo + off);
        }
        CP_COMMIT(); CP_WAIT0();
        __syncthreads();

        // ---- S = Q K^T (3-pass split) ----
        float s[8][4];
#pragma unroll
        for (int nt = 0; nt < 8; nt++)
#pragma unroll
            for (int k = 0; k < 4; k++) s[nt][k] = 0.f;

#pragma unroll
        for (int ks = 0; ks < 4; ks++) {
            const int kk = ks * 16;
            uint32_t kh[8][2], kl[8][2];
#pragma unroll
            for (int p = 0; p < 4; p++) {
                uint32_t off = (uint32_t)(p * 16 + b_nt * 8 + b_rr) * 144 + (kk + b_kh * 8) * 2;
                ldsm_x4(kh[p*2][0], kh[p*2][1], kh[p*2+1][0], kh[p*2+1][1], aKh + off);
                ldsm_x4(kl[p*2][0], kl[p*2][1], kl[p*2+1][0], kl[p*2+1][1], aKl + off);
            }
#pragma unroll
            for (int nt = 0; nt < 8; nt++) {
                mma4(s[nt], qh[ks], kh[nt]);
                mma4(s[nt], qh[ks], kl[nt]);
                mma4(s[nt], ql[ks], kh[nt]);
            }
        }

        // ---- causal mask (diagonal tile only) ----
        if (j0 == i0) {
#pragma unroll
            for (int nt = 0; nt < 8; nt++) {
                int col0 = nt * 8 + 2 * tig;
                int rowa = r0 + gid, rowb = rowa + 8;
                if (col0     > rowa) s[nt][0] = -1e30f;
                if (col0 + 1 > rowa) s[nt][1] = -1e30f;
                if (col0     > rowb) s[nt][2] = -1e30f;
                if (col0 + 1 > rowb) s[nt][3] = -1e30f;
            }
        }

        // ---- online softmax (quad reduction over tig) ----
        float mxa = -1e30f, mxb = -1e30f;
#pragma unroll
        for (int nt = 0; nt < 8; nt++) {
            mxa = fmaxf(mxa, fmaxf(s[nt][0], s[nt][1]));
            mxb = fmaxf(mxb, fmaxf(s[nt][2], s[nt][3]));
        }
        mxa = fmaxf(mxa, __shfl_xor_sync(0xFFFFFFFFu, mxa, 1));
        mxa = fmaxf(mxa, __shfl_xor_sync(0xFFFFFFFFu, mxa, 2));
        mxb = fmaxf(mxb, __shfl_xor_sync(0xFFFFFFFFu, mxb, 1));
        mxb = fmaxf(mxb, __shfl_xor_sync(0xFFFFFFFFu, mxb, 2));

        float mna = fmaxf(mrow0, mxa), mnb = fmaxf(mrow1, mxb);
        float ala = __expf(mrow0 - mna), alb = __expf(mrow1 - mnb);
        float suma = 0.f, sumb = 0.f;
#pragma unroll
        for (int nt = 0; nt < 8; nt++) {
            s[nt][0] = __expf(s[nt][0] - mna); suma += s[nt][0];
            s[nt][1] = __expf(s[nt][1] - mna); suma += s[nt][1];
            s[nt][2] = __expf(s[nt][2] - mnb); sumb += s[nt][2];
            s[nt][3] = __expf(s[nt][3] - mnb); sumb += s[nt][3];
        }
        suma += __shfl_xor_sync(0xFFFFFFFFu, suma, 1);
        suma += __shfl_xor_sync(0xFFFFFFFFu, suma, 2);
        sumb += __shfl_xor_sync(0xFFFFFFFFu, sumb, 1);
        sumb += __shfl_xor_sync(0xFFFFFFFFu, sumb, 2);
        lrow0 = lrow0 * ala + suma; mrow0 = mna;
        lrow1 = lrow1 * alb + sumb; mrow1 = mnb;

#pragma unroll
        for (int nt = 0; nt < 8; nt++) {
            o[nt][0] *= ala; o[nt][1] *= ala;
            o[nt][2] *= alb; o[nt][3] *= alb;
        }

        // ---- O += P V (3-pass split; P frags from S regs) ----
#pragma unroll
        for (int ks2 = 0; ks2 < 4; ks2++) {
            const float* sa = s[2*ks2];
            const float* sb2 = s[2*ks2 + 1];
            uint32_t phi[4], plo[4];
            {
                __nv_bfloat162 h0 = __floats2bfloat162_rn(sa[0], sa[1]);
                __nv_bfloat162 h1 = __floats2bfloat162_rn(sa[2], sa[3]);
                __nv_bfloat162 h2 = __floats2bfloat162_rn(sb2[0], sb2[1]);
                __nv_bfloat162 h3 = __floats2bfloat162_rn(sb2[2], sb2[3]);
                phi[0] = *reinterpret_cast<uint32_t*>(&h0);
                phi[1] = *reinterpret_cast<uint32_t*>(&h1);
                phi[2] = *reinterpret_cast<uint32_t*>(&h2);
                phi[3] = *reinterpret_cast<uint32_t*>(&h3);
                plo[0] = packbf2(sa[0] - __bfloat162float(h0.x),  sa[1] - __bfloat162float(h0.y));
                plo[1] = packbf2(sa[2] - __bfloat162float(h1.x),  sa[3] - __bfloat162float(h1.y));
                plo[2] = packbf2(sb2[0] - __bfloat162float(h2.x), sb2[1] - __bfloat162float(h2.y));
                plo[3] = packbf2(sb2[2] - __bfloat162float(h3.x), sb2[3] - __bfloat162float(h3.y));
            }
            uint32_t vh[8][2], vl[8][2];
#pragma unroll
            for (int p = 0; p < 4; p++) {
                // transposed fragments of V (B operand = V^T)
                uint32_t off = (uint32_t)(ks2 * 16 + b_kh * 8 + b_rr) * 144
                             + (p * 16 + b_nt * 8) * 2;
                ldsm_x4t(vh[p*2][0], vh[p*2][1], vh[p*2+1][0], vh[p*2+1][1], aVh + off);
                ldsm_x4t(vl[p*2][0], vl[p*2][1], vl[p*2+1][0], vl[p*2+1][1], aVl + off);
            }
#pragma unroll
            for (int nt = 0; nt < 8; nt++) {
                mma4(o[nt], phi, vh[nt]);
                mma4(o[nt], phi, vl[nt]);
                mma4(o[nt], plo, vh[nt]);
            }
        }
        __syncthreads();
    }

    // ---- epilogue: normalize, split to hi/lo, store ----
    const float inv0 = 1.0f / lrow0;
    const float inv1 = 1.0f / lrow1;
    const size_t rowa = (size_t)(b * LL + i0 + r0 + gid) * DD + h * HD;
    const size_t rowb = rowa + (size_t)8 * DD;
#pragma unroll
    for (int nt = 0; nt < 8; nt++) {
        int col = nt * 8 + 2 * tig;
        float v0 = o[nt][0] * inv0, v1 = o[nt][1] * inv0;
        float v2 = o[nt][2] * inv1, v3 = o[nt][3] * inv1;
        __nv_bfloat162 ha = __floats2bfloat162_rn(v0, v1);
        __nv_bfloat162 hb = __floats2bfloat162_rn(v2, v3);
        __nv_bfloat162 la = __floats2bfloat162_rn(v0 - __bfloat162float(ha.x),
                                                  v1 - __bfloat162float(ha.y));
        __nv_bfloat162 lb = __floats2bfloat162_rn(v2 - __bfloat162float(hb.x),
                                                  v3 - __bfloat162float(hb.y));
        *reinterpret_cast<__nv_bfloat162*>(Ohi + rowa + col) = ha;
        *reinterpret_cast<__nv_bfloat162*>(Olo + rowa + col) = la;
        *reinterpret_cast<__nv_bfloat162*>(Ohi + rowb + col) = hb;
        *reinterpret_cast<__nv_bfloat162*>(Olo + rowb + col) = lb;
    }
}

// ---------------------------------------------------------------------------
extern "C" void kernel_launch(void* const* d_in, const int* in_sizes, int n_in,
                              void* d_out, int out_size) {
    const float* x  = (const float*)d_in[0];
    const float* WQ = (const float*)d_in[1];
    const float* bQ = (const float*)d_in[2];
    const float* WK = (const float*)d_in[3];
    const float* bK = (const float*)d_in[4];
    const float* WV = (const float*)d_in[5];
    const float* bV = (const float*)d_in[6];
    const float* Wc = (const float*)d_in[7];
    float* out = (float*)d_out;

    cudaFuncSetAttribute(gemm_hmma, cudaFuncAttributeMaxDynamicSharedMemorySize, GEMM_SMEM);

    bf16 *xhi, *xlo, *whi, *wlo, *qhi, *qlo, *khi, *klo, *vhi, *vlo, *mhi, *mlo;
    cudaGetSymbolAddress((void**)&xhi, g_xhi);
    cudaGetSymbolAddress((void**)&xlo, g_xlo);
    cudaGetSymbolAddress((void**)&whi, g_whi);
    cudaGetSymbolAddress((void**)&wlo, g_wlo);
    cudaGetSymbolAddress((void**)&qhi, g_qhi);
    cudaGetSymbolAddress((void**)&qlo, g_qlo);
    cudaGetSymbolAddress((void**)&khi, g_khi);
    cudaGetSymbolAddress((void**)&klo, g_klo);
    cudaGetSymbolAddress((void**)&vhi, g_vhi);
    cudaGetSymbolAddress((void**)&vlo, g_vlo);
    cudaGetSymbolAddress((void**)&mhi, g_mhi);
    cudaGetSymbolAddress((void**)&mlo, g_mlo);

    const int nx4 = MM * DD / 4;
    const int nw4 = DD * DD / 4;

    split_kernel<<<(nx4 + 255) / 256, 256>>>(x,  xhi, xlo, nx4);
    split_kernel<<<(nw4 + 255) / 256, 256>>>(WQ, whi + 0*DD*DD, wlo + 0*DD*DD, nw4);
    split_kernel<<<(nw4 + 255) / 256, 256>>>(WK, whi + 1*DD*DD, wlo + 1*DD*DD, nw4);
    split_kernel<<<(nw4 + 255) / 256, 256>>>(WV, whi + 2*DD*DD, wlo + 2*DD*DD, nw4);
    split_kernel<<<(nw4 + 255) / 256, 256>>>(Wc, whi + 3*DD*DD, wlo + 3*DD*DD, nw4);

    dim3 gg(DD / BN, MM / BM);   // (16, 32)
    gemm_hmma<<<gg, 256, GEMM_SMEM>>>(xhi, xlo, whi + 0*DD*DD, wlo + 0*DD*DD, bQ, 0.125f,
                                      nullptr, qhi, qlo);
    gemm_hmma<<<gg, 256, GEMM_SMEM>>>(xhi, xlo, whi + 1*DD*DD, wlo + 1*DD*DD, bK, 1.0f,
                                      nullptr, khi, klo);
    gemm_hmma<<<gg, 256, GEMM_SMEM>>>(xhi, xlo, whi + 2*DD*DD, wlo + 2*DD*DD, bV, 1.0f,
                                      nullptr, vhi, vlo);

    dim3 ga(LL / 64, HH, BB);    // (32, 16, 2)
    attn_mma<<<ga, 128>>>(qhi, qlo, khi, klo, vhi, vlo, mhi, mlo);

    gemm_hmma<<<gg, 256, GEMM_SMEM>>>(mhi, mlo, whi + 3*DD*DD, wlo + 3*DD*DD, nullptr, 1.0f,
                                      out, nullptr, nullptr);
}

// round 5
// speedup vs baseline: 4.5193x; 1.0293x over previous
#include <cuda_runtime.h>
#include <cuda_bf16.h>
#include <cstdint>

// Problem shape (fixed)
#define BB 2
#define LL 2048
#define DD 1024
#define HH 16
#define HD 64
#define MM (BB*LL)   // 4096

typedef __nv_bfloat16 bf16;

// ---------------------------------------------------------------------------
// Scratch (__device__ globals: allocation-free rule)
// ---------------------------------------------------------------------------
__device__ bf16 g_xhi[MM*DD], g_xlo[MM*DD];
__device__ bf16 g_whi[4*DD*DD], g_wlo[4*DD*DD];
__device__ bf16 g_qhi[MM*DD], g_qlo[MM*DD];
__device__ bf16 g_khi[MM*DD], g_klo[MM*DD];
__device__ bf16 g_vhi[MM*DD], g_vlo[MM*DD];
__device__ bf16 g_mhi[MM*DD], g_mlo[MM*DD];

// ---------------------------------------------------------------------------
// Helpers (portable ISA only)
// ---------------------------------------------------------------------------
__device__ __forceinline__ uint32_t smem_u32(const void* p) {
    uint32_t a;
    asm("{ .reg .u64 t; cvta.to.shared.u64 t, %1; cvt.u32.u64 %0, t; }" : "=r"(a) : "l"(p));
    return a;
}
__device__ __forceinline__ void ldsm_x4(uint32_t& r0, uint32_t& r1, uint32_t& r2, uint32_t& r3,
                                        uint32_t addr) {
    asm volatile("ldmatrix.sync.aligned.m8n8.x4.shared.b16 {%0,%1,%2,%3}, [%4];"
                 : "=r"(r0), "=r"(r1), "=r"(r2), "=r"(r3) : "r"(addr));
}
__device__ __forceinline__ void ldsm_x4t(uint32_t& r0, uint32_t& r1, uint32_t& r2, uint32_t& r3,
                                         uint32_t addr) {
    asm volatile("ldmatrix.sync.aligned.m8n8.x4.trans.shared.b16 {%0,%1,%2,%3}, [%4];"
                 : "=r"(r0), "=r"(r1), "=r"(r2), "=r"(r3) : "r"(addr));
}
__device__ __forceinline__ void mma4(float* c, const uint32_t* a, const uint32_t* b) {
    asm volatile("mma.sync.aligned.m16n8k16.row.col.f32.bf16.bf16.f32 "
                 "{%0,%1,%2,%3}, {%4,%5,%6,%7}, {%8,%9}, {%0,%1,%2,%3};"
                 : "+f"(c[0]), "+f"(c[1]), "+f"(c[2]), "+f"(c[3])
                 : "r"(a[0]), "r"(a[1]), "r"(a[2]), "r"(a[3]), "r"(b[0]), "r"(b[1]));
}
__device__ __forceinline__ void cp16(uint32_t dst, const void* src) {
    asm volatile("cp.async.cg.shared.global [%0], [%1], 16;" :: "r"(dst), "l"(src));
}
#define CP_COMMIT() asm volatile("cp.async.commit_group;" ::: "memory")
#define CP_WAIT(N)  asm volatile("cp.async.wait_group %0;" :: "n"(N) : "memory")

__device__ __forceinline__ uint32_t packbf2(float a, float b) {
    __nv_bfloat162 t = __floats2bfloat162_rn(a, b);
    return *reinterpret_cast<uint32_t*>(&t);
}

// ---------------------------------------------------------------------------
// fp32 -> (bf16 hi, bf16 lo) splits
// ---------------------------------------------------------------------------
__device__ __forceinline__ void split4(const float* in, bf16* hi, bf16* lo, int i) {
    float4 v = reinterpret_cast<const float4*>(in)[i];
    bf16 h0 = __float2bfloat16(v.x), h1 = __float2bfloat16(v.y);
    bf16 h2 = __float2bfloat16(v.z), h3 = __float2bfloat16(v.w);
    bf16 l0 = __float2bfloat16(v.x - __bfloat162float(h0));
    bf16 l1 = __float2bfloat16(v.y - __bfloat162float(h1));
    bf16 l2 = __float2bfloat16(v.z - __bfloat162float(h2));
    bf16 l3 = __float2bfloat16(v.w - __bfloat162float(h3));
    __nv_bfloat162* H = reinterpret_cast<__nv_bfloat162*>(hi);
    __nv_bfloat162* L = reinterpret_cast<__nv_bfloat162*>(lo);
    H[2*i]   = __nv_bfloat162(h0, h1);
    H[2*i+1] = __nv_bfloat162(h2, h3);
    L[2*i]   = __nv_bfloat162(l0, l1);
    L[2*i+1] = __nv_bfloat162(l2, l3);
}

__global__ __launch_bounds__(256) void split_x(const float* __restrict__ in,
                                               bf16* __restrict__ hi,
                                               bf16* __restrict__ lo, int n4) {
    int i = blockIdx.x * 256 + threadIdx.x;
    if (i < n4) split4(in, hi, lo, i);
}

// 4 weight matrices in one launch (blockIdx.y selects)
__global__ __launch_bounds__(256) void split_w(const float* __restrict__ w0,
                                               const float* __restrict__ w1,
                                               const float* __restrict__ w2,
                                               const float* __restrict__ w3,
                                               bf16* __restrict__ hi,
                                               bf16* __restrict__ lo, int n4) {
    int i = blockIdx.x * 256 + threadIdx.x;
    if (i >= n4) return;
    int z = blockIdx.y;
    const float* src = z == 0 ? w0 : z == 1 ? w1 : z == 2 ? w2 : w3;
    split4(src, hi + (size_t)z * DD * DD, lo + (size_t)z * DD * DD, i);
}

// ---------------------------------------------------------------------------
// HMMA GEMM, 3-stage cp.async pipeline, multi-task via blockIdx.z.
// C = (Ahi+Alo) @ (Whi+Wlo)^T + bias ; epilogue fp32 OR scaled split-bf16.
// CTA 128x64, BK=32, 256 threads (8 warps, 4x2, 32x32 each).
// ---------------------------------------------------------------------------
#define GK 1024
#define BM 128
#define BN 64
#define BK 32
#define SZ_A (BM*40*2)                // 10240 B (row stride 80 B)
#define SZ_W (BN*40*2)                // 5120 B
#define STG  (2*SZ_A + 2*SZ_W)        // 30720 B per stage
#define NSTG 3
#define GEMM_SMEM (NSTG*STG)          // 92160 B

struct GemmTask {
    const bf16* Whi; const bf16* Wlo;
    const float* bias; float scale;
    float* Cf; bf16* Chi; bf16* Clo;
};

__global__ __launch_bounds__(256) void gemm_hmma(const bf16* __restrict__ Ahi,
                                                 const bf16* __restrict__ Alo,
                                                 GemmTask t0, GemmTask t1, GemmTask t2) {
    extern __shared__ __align__(16) char dsm[];
    const GemmTask tk = blockIdx.z == 0 ? t0 : blockIdx.z == 1 ? t1 : t2;
    const bf16* __restrict__ Whi = tk.Whi;
    const bf16* __restrict__ Wlo = tk.Wlo;

    const uint32_t sb0 = smem_u32(dsm);
    const int tid  = threadIdx.x;
    const int wid  = tid >> 5;
    const int lane = tid & 31;
    const int wm   = wid >> 1;
    const int wn   = wid & 1;
    const int bm   = blockIdx.y * BM;
    const int bn   = blockIdx.x * BN;

    float acc[2][4][4];
#pragma unroll
    for (int i = 0; i < 2; i++)
#pragma unroll
        for (int j = 0; j < 4; j++)
#pragma unroll
            for (int k = 0; k < 4; k++) acc[i][j][k] = 0.f;

    auto issue = [&](int stg, int k0) {
        uint32_t base = sb0 + stg * STG;
#pragma unroll
        for (int i = 0; i < 2; i++) {
            int c = tid + 256 * i;
            int r = c >> 2, q = c & 3;
            const size_t off = (size_t)(bm + r) * GK + k0 + q * 8;
            cp16(base + r * 80 + q * 16,        Ahi + off);
            cp16(base + SZ_A + r * 80 + q * 16, Alo + off);
        }
        {
            int r = tid >> 2, q = tid & 3;
            const size_t off = (size_t)(bn + r) * GK + k0 + q * 8;
            cp16(base + 2*SZ_A + r * 80 + q * 16,        Whi + off);
            cp16(base + 2*SZ_A + SZ_W + r * 80 + q * 16, Wlo + off);
        }
        CP_COMMIT();
    };

    const int a_r    = lane & 15;
    const int a_half = lane >> 4;
    const int b_rr   = lane & 7;
    const int b_nt   = (lane >> 4) & 1;
    const int b_kh   = (lane >> 3) & 1;

    const int NIT = GK / BK;     // 32
    issue(0, 0);
    issue(1, BK);
    for (int it = 0; it < NIT; it++) {
        if (it + 2 < NIT) { issue((it + 2) % NSTG, (it + 2) * BK); CP_WAIT(2); }
        else if (it + 1 < NIT) { CP_WAIT(1); }
        else { CP_WAIT(0); }
        __syncthreads();

        const uint32_t base = sb0 + (it % NSTG) * STG;
        const uint32_t aAhi = base;
        const uint32_t aAlo = base + SZ_A;
        const uint32_t aWhi = base + 2*SZ_A;
        const uint32_t aWlo = base + 2*SZ_A + SZ_W;

#pragma unroll
        for (int ks = 0; ks < 2; ks++) {
            const int kk = ks * 16;
            uint32_t ah[2][4], al[2][4];
#pragma unroll
            for (int mt = 0; mt < 2; mt++) {
                uint32_t off = (uint32_t)(wm * 32 + mt * 16 + a_r) * 80 + (kk + a_half * 8) * 2;
                ldsm_x4(ah[mt][0], ah[mt][1], ah[mt][2], ah[mt][3], aAhi + off);
                ldsm_x4(al[mt][0], al[mt][1], al[mt][2], al[mt][3], aAlo + off);
            }
            uint32_t bh[4][2], bl[4][2];
#pragma unroll
            for (int p = 0; p < 2; p++) {
                uint32_t off = (uint32_t)(wn * 32 + p * 16 + b_nt * 8 + b_rr) * 80
                             + (kk + b_kh * 8) * 2;
                ldsm_x4(bh[p*2][0], bh[p*2][1], bh[p*2+1][0], bh[p*2+1][1], aWhi + off);
                ldsm_x4(bl[p*2][0], bl[p*2][1], bl[p*2+1][0], bl[p*2+1][1], aWlo + off);
            }
#pragma unroll
            for (int mt = 0; mt < 2; mt++)
#pragma unroll
                for (int nt = 0; nt < 4; nt++) {
                    mma4(acc[mt][nt], ah[mt], bh[nt]);
                    mma4(acc[mt][nt], ah[mt], bl[nt]);
                    mma4(acc[mt][nt], al[mt], bh[nt]);
                }
        }
        __syncthreads();
    }

    // ---- epilogue ----
    const int gid = lane >> 2;
    const int tig = lane & 3;
#pragma unroll
    for (int mt = 0; mt < 2; mt++) {
#pragma unroll
        for (int nt = 0; nt < 4; nt++) {
            int row = bm + wm * 32 + mt * 16 + gid;
            int col = bn + wn * 32 + nt * 8 + 2 * tig;
            float b0 = tk.bias ? tk.bias[col]     : 0.f;
            float b1 = tk.bias ? tk.bias[col + 1] : 0.f;
            float v00 = (acc[mt][nt][0] + b0) * tk.scale;
            float v01 = (acc[mt][nt][1] + b1) * tk.scale;
            float v10 = (acc[mt][nt][2] + b0) * tk.scale;
            float v11 = (acc[mt][nt][3] + b1) * tk.scale;
            if (tk.Cf) {
                *reinterpret_cast<float2*>(tk.Cf + (size_t)row * GK + col)       = make_float2(v00, v01);
                *reinterpret_cast<float2*>(tk.Cf + (size_t)(row + 8) * GK + col) = make_float2(v10, v11);
            } else {
                __nv_bfloat162 h0 = __floats2bfloat162_rn(v00, v01);
                __nv_bfloat162 h1 = __floats2bfloat162_rn(v10, v11);
                __nv_bfloat162 l0 = __floats2bfloat162_rn(v00 - __bfloat162float(h0.x),
                                                          v01 - __bfloat162float(h0.y));
                __nv_bfloat162 l1 = __floats2bfloat162_rn(v10 - __bfloat162float(h1.x),
                                                          v11 - __bfloat162float(h1.y));
                *reinterpret_cast<__nv_bfloat162*>(tk.Chi + (size_t)row * GK + col)       = h0;
                *reinterpret_cast<__nv_bfloat162*>(tk.Clo + (size_t)row * GK + col)       = l0;
                *reinterpret_cast<__nv_bfloat162*>(tk.Chi + (size_t)(row + 8) * GK + col) = h1;
                *reinterpret_cast<__nv_bfloat162*>(tk.Clo + (size_t)(row + 8) * GK + col) = l1;
            }
        }
    }
}

// ---------------------------------------------------------------------------
// HMMA flash attention, double-buffered KV (cp.async 2 stages).
// Block = 128 threads (4 warps), 64 query rows, KV tiles of 64.
// Q is staged through the (initially idle) stage-1 K buffers.
// Blocks run in REVERSED i0 order (largest workload first).
// ---------------------------------------------------------------------------
#define AROWB 144                       // bytes per 64-col bf16 row (72 elems)
#define ATILE_B (64*AROWB)              // 9216 B per array
#define ASTG_B (4*ATILE_B)              // Kh,Kl,Vh,Vl per stage = 36864 B
#define ATTN_SMEM (2*ASTG_B)            // 73728 B

__global__ __launch_bounds__(128) void attn_mma(const bf16* __restrict__ Qhi,
                                                const bf16* __restrict__ Qlo,
                                                const bf16* __restrict__ Khi,
                                                const bf16* __restrict__ Klo,
                                                const bf16* __restrict__ Vhi,
                                                const bf16* __restrict__ Vlo,
                                                bf16* __restrict__ Ohi,
                                                bf16* __restrict__ Olo) {
    extern __shared__ __align__(16) char asm_[];
    const uint32_t sb = smem_u32(asm_);

    const int i0 = (int)(gridDim.x - 1 - blockIdx.x) * 64;   // reversed order
    const int h  = blockIdx.y;
    const int b  = blockIdx.z;
    const int tid  = threadIdx.x;
    const int w    = tid >> 5;
    const int lane = tid & 31;
    const int gid  = lane >> 2;
    const int tig  = lane & 3;
    const int r0   = w * 16;

    const size_t baseq = ((size_t)(b * LL + i0)) * DD + h * HD;

    auto issueKV = [&](uint32_t stg, int j0) {
        const size_t basekv = ((size_t)(b * LL + j0)) * DD + h * HD;
#pragma unroll
        for (int i = 0; i < 4; i++) {
            int c = tid + 128 * i;
            int r = c >> 3, q = c & 7;
            const size_t off = basekv + (size_t)r * DD + q * 8;
            const uint32_t d = stg + r * AROWB + q * 16;
            cp16(d,               Khi + off);
            cp16(d + ATILE_B,     Klo + off);
            cp16(d + 2*ATILE_B,   Vhi + off);
            cp16(d + 3*ATILE_B,   Vlo + off);
        }
        CP_COMMIT();
    };

    // ---- stage Q through stage-1 K buffers; prefetch KV tile 0 into stage 0 ----
#pragma unroll
    for (int i = 0; i < 4; i++) {
        int c = tid + 128 * i;
        int r = c >> 3, q = c & 7;
        const size_t off = baseq + (size_t)r * DD + q * 8;
        cp16(sb + ASTG_B + r * AROWB + q * 16,           Qhi + off);
        cp16(sb + ASTG_B + ATILE_B + r * AROWB + q * 16, Qlo + off);
    }
    CP_COMMIT();
    issueKV(sb, 0);
    CP_WAIT(1);               // Q ready (KV0 may still be in flight)
    __syncthreads();

    const int a_r = lane & 15, a_h = lane >> 4;
    uint32_t qh[4][4], ql[4][4];
#pragma unroll
    for (int ks = 0; ks < 4; ks++) {
        uint32_t off = (uint32_t)(r0 + a_r) * AROWB + (ks * 16 + a_h * 8) * 2;
        ldsm_x4(qh[ks][0], qh[ks][1], qh[ks][2], qh[ks][3], sb + ASTG_B + off);
        ldsm_x4(ql[ks][0], ql[ks][1], ql[ks][2], ql[ks][3], sb + ASTG_B + ATILE_B + off);
    }
    __syncthreads();          // Q buffers free for KV reuse

    float o[8][4];
#pragma unroll
    for (int nt = 0; nt < 8; nt++)
#pragma unroll
        for (int k = 0; k < 4; k++) o[nt][k] = 0.f;
    float mrow0 = -1e30f, mrow1 = -1e30f, lrow0 = 0.f, lrow1 = 0.f;

    const int b_rr = lane & 7;
    const int b_nt = (lane >> 4) & 1;
    const int b_kh = (lane >> 3) & 1;

    const int T = i0 / 64 + 1;
    for (int t = 0; t < T; t++) {
        if (t + 1 < T) { issueKV(sb + ((t + 1) & 1) * ASTG_B, (t + 1) * 64); CP_WAIT(1); }
        else           { CP_WAIT(0); }
        __syncthreads();

        const uint32_t aKh = sb + (t & 1) * ASTG_B;
        const uint32_t aKl = aKh + ATILE_B;
        const uint32_t aVh = aKh + 2*ATILE_B;
        const uint32_t aVl = aKh + 3*ATILE_B;

        // ---- S = Q K^T (3-pass split) ----
        float s[8][4];
#pragma unroll
        for (int nt = 0; nt < 8; nt++)
#pragma unroll
            for (int k = 0; k < 4; k++) s[nt][k] = 0.f;

#pragma unroll
        for (int ks = 0; ks < 4; ks++) {
            const int kk = ks * 16;
            uint32_t kh[8][2], kl[8][2];
#pragma unroll
            for (int p = 0; p < 4; p++) {
                uint32_t off = (uint32_t)(p * 16 + b_nt * 8 + b_rr) * AROWB + (kk + b_kh * 8) * 2;
                ldsm_x4(kh[p*2][0], kh[p*2][1], kh[p*2+1][0], kh[p*2+1][1], aKh + off);
                ldsm_x4(kl[p*2][0], kl[p*2][1], kl[p*2+1][0], kl[p*2+1][1], aKl + off);
            }
#pragma unroll
            for (int nt = 0; nt < 8; nt++) {
                mma4(s[nt], qh[ks], kh[nt]);
                mma4(s[nt], qh[ks], kl[nt]);
                mma4(s[nt], ql[ks], kh[nt]);
            }
        }

        // ---- causal mask (diagonal tile only; reversed order: t==T-1) ----
        if (t == T - 1) {
#pragma unroll
            for (int nt = 0; nt < 8; nt++) {
                int col0 = nt * 8 + 2 * tig;
                int rowa = r0 + gid, rowb = rowa + 8;
                if (col0     > rowa) s[nt][0] = -1e30f;
                if (col0 + 1 > rowa) s[nt][1] = -1e30f;
                if (col0     > rowb) s[nt][2] = -1e30f;
                if (col0 + 1 > rowb) s[nt][3] = -1e30f;
            }
        }

        // ---- online softmax (quad reduction) ----
        float mxa = -1e30f, mxb = -1e30f;
#pragma unroll
        for (int nt = 0; nt < 8; nt++) {
            mxa = fmaxf(mxa, fmaxf(s[nt][0], s[nt][1]));
            mxb = fmaxf(mxb, fmaxf(s[nt][2], s[nt][3]));
        }
        mxa = fmaxf(mxa, __shfl_xor_sync(0xFFFFFFFFu, mxa, 1));
        mxa = fmaxf(mxa, __shfl_xor_sync(0xFFFFFFFFu, mxa, 2));
        mxb = fmaxf(mxb, __shfl_xor_sync(0xFFFFFFFFu, mxb, 1));
        mxb = fmaxf(mxb, __shfl_xor_sync(0xFFFFFFFFu, mxb, 2));

        float mna = fmaxf(mrow0, mxa), mnb = fmaxf(mrow1, mxb);
        float ala = __expf(mrow0 - mna), alb = __expf(mrow1 - mnb);
        float suma = 0.f, sumb = 0.f;
#pragma unroll
        for (int nt = 0; nt < 8; nt++) {
            s[nt][0] = __expf(s[nt][0] - mna); suma += s[nt][0];
            s[nt][1] = __expf(s[nt][1] - mna); suma += s[nt][1];
            s[nt][2] = __expf(s[nt][2] - mnb); sumb += s[nt][2];
            s[nt][3] = __expf(s[nt][3] - mnb); sumb += s[nt][3];
        }
        suma += __shfl_xor_sync(0xFFFFFFFFu, suma, 1);
        suma += __shfl_xor_sync(0xFFFFFFFFu, suma, 2);
        sumb += __shfl_xor_sync(0xFFFFFFFFu, sumb, 1);
        sumb += __shfl_xor_sync(0xFFFFFFFFu, sumb, 2);
        lrow0 = lrow0 * ala + suma; mrow0 = mna;
        lrow1 = lrow1 * alb + sumb; mrow1 = mnb;

#pragma unroll
        for (int nt = 0; nt < 8; nt++) {
            o[nt][0] *= ala; o[nt][1] *= ala;
            o[nt][2] *= alb; o[nt][3] *= alb;
        }

        // ---- O += P V (3-pass split; P frags from S regs) ----
#pragma unroll
        for (int ks2 = 0; ks2 < 4; ks2++) {
            const float* sa  = s[2*ks2];
            const float* sb2 = s[2*ks2 + 1];
            uint32_t phi[4], plo[4];
            {
                __nv_bfloat162 h0 = __floats2bfloat162_rn(sa[0], sa[1]);
                __nv_bfloat162 h1 = __floats2bfloat162_rn(sa[2], sa[3]);
                __nv_bfloat162 h2 = __floats2bfloat162_rn(sb2[0], sb2[1]);
                __nv_bfloat162 h3 = __floats2bfloat162_rn(sb2[2], sb2[3]);
                phi[0] = *reinterpret_cast<uint32_t*>(&h0);
                phi[1] = *reinterpret_cast<uint32_t*>(&h1);
                phi[2] = *reinterpret_cast<uint32_t*>(&h2);
                phi[3] = *reinterpret_cast<uint32_t*>(&h3);
                plo[0] = packbf2(sa[0]  - __bfloat162float(h0.x), sa[1]  - __bfloat162float(h0.y));
                plo[1] = packbf2(sa[2]  - __bfloat162float(h1.x), sa[3]  - __bfloat162float(h1.y));
                plo[2] = packbf2(sb2[0] - __bfloat162float(h2.x), sb2[1] - __bfloat162float(h2.y));
                plo[3] = packbf2(sb2[2] - __bfloat162float(h3.x), sb2[3] - __bfloat162float(h3.y));
            }
            uint32_t vh[8][2], vl[8][2];
#pragma unroll
            for (int p = 0; p < 4; p++) {
                uint32_t off = (uint32_t)(ks2 * 16 + b_kh * 8 + b_rr) * AROWB
                             + (p * 16 + b_nt * 8) * 2;
                ldsm_x4t(vh[p*2][0], vh[p*2][1], vh[p*2+1][0], vh[p*2+1][1], aVh + off);
                ldsm_x4t(vl[p*2][0], vl[p*2][1], vl[p*2+1][0], vl[p*2+1][1], aVl + off);
            }
#pragma unroll
            for (int nt = 0; nt < 8; nt++) {
                mma4(o[nt], phi, vh[nt]);
                mma4(o[nt], phi, vl[nt]);
                mma4(o[nt], plo, vh[nt]);
            }
        }
        __syncthreads();
    }

    // ---- epilogue: normalize, split to hi/lo, store ----
    const float inv0 = 1.0f / lrow0;
    const float inv1 = 1.0f / lrow1;
    const size_t rowa = (size_t)(b * LL + i0 + r0 + gid) * DD + h * HD;
    const size_t rowb = rowa + (size_t)8 * DD;
#pragma unroll
    for (int nt = 0; nt < 8; nt++) {
        int col = nt * 8 + 2 * tig;
        float v0 = o[nt][0] * inv0, v1 = o[nt][1] * inv0;
        float v2 = o[nt][2] * inv1, v3 = o[nt][3] * inv1;
        __nv_bfloat162 ha = __floats2bfloat162_rn(v0, v1);
        __nv_bfloat162 hb = __floats2bfloat162_rn(v2, v3);
        __nv_bfloat162 la = __floats2bfloat162_rn(v0 - __bfloat162float(ha.x),
                                                  v1 - __bfloat162float(ha.y));
        __nv_bfloat162 lb = __floats2bfloat162_rn(v2 - __bfloat162float(hb.x),
                                                  v3 - __bfloat162float(hb.y));
        *reinterpret_cast<__nv_bfloat162*>(Ohi + rowa + col) = ha;
        *reinterpret_cast<__nv_bfloat162*>(Olo + rowa + col) = la;
        *reinterpret_cast<__nv_bfloat162*>(Ohi + rowb + col) = hb;
        *reinterpret_cast<__nv_bfloat162*>(Olo + rowb + col) = lb;
    }
}

// ---------------------------------------------------------------------------
extern "C" void kernel_launch(void* const* d_in, const int* in_sizes, int n_in,
                              void* d_out, int out_size) {
    const float* x  = (const float*)d_in[0];
    const float* WQ = (const float*)d_in[1];
    const float* bQ = (const float*)d_in[2];
    const float* WK = (const float*)d_in[3];
    const float* bK = (const float*)d_in[4];
    const float* WV = (const float*)d_in[5];
    const float* bV = (const float*)d_in[6];
    const float* Wc = (const float*)d_in[7];
    float* out = (float*)d_out;

    cudaFuncSetAttribute(gemm_hmma, cudaFuncAttributeMaxDynamicSharedMemorySize, GEMM_SMEM);
    cudaFuncSetAttribute(attn_mma,  cudaFuncAttributeMaxDynamicSharedMemorySize, ATTN_SMEM);

    bf16 *xhi, *xlo, *whi, *wlo, *qhi, *qlo, *khi, *klo, *vhi, *vlo, *mhi, *mlo;
    cudaGetSymbolAddress((void**)&xhi, g_xhi);
    cudaGetSymbolAddress((void**)&xlo, g_xlo);
    cudaGetSymbolAddress((void**)&whi, g_whi);
    cudaGetSymbolAddress((void**)&wlo, g_wlo);
    cudaGetSymbolAddress((void**)&qhi, g_qhi);
    cudaGetSymbolAddress((void**)&qlo, g_qlo);
    cudaGetSymbolAddress((void**)&khi, g_khi);
    cudaGetSymbolAddress((void**)&klo, g_klo);
    cudaGetSymbolAddress((void**)&vhi, g_vhi);
    cudaGetSymbolAddress((void**)&vlo, g_vlo);
    cudaGetSymbolAddress((void**)&mhi, g_mhi);
    cudaGetSymbolAddress((void**)&mlo, g_mlo);

    const int nx4 = MM * DD / 4;
    const int nw4 = DD * DD / 4;

    split_x<<<(nx4 + 255) / 256, 256>>>(x, xhi, xlo, nx4);
    dim3 gw((nw4 + 255) / 256, 4);
    split_w<<<gw, 256>>>(WQ, WK, WV, Wc, whi, wlo, nw4);

    GemmTask tq = {whi + 0*DD*DD, wlo + 0*DD*DD, bQ, 0.125f, nullptr, qhi, qlo};
    GemmTask tk = {whi + 1*DD*DD, wlo + 1*DD*DD, bK, 1.0f,   nullptr, khi, klo};
    GemmTask tv = {whi + 2*DD*DD, wlo + 2*DD*DD, bV, 1.0f,   nullptr, vhi, vlo};
    dim3 gqkv(DD / BN, MM / BM, 3);    // (16, 32, 3)
    gemm_hmma<<<gqkv, 256, GEMM_SMEM>>>(xhi, xlo, tq, tk, tv);

    dim3 ga(LL / 64, HH, BB);          // (32, 16, 2)
    attn_mma<<<ga, 128, ATTN_SMEM>>>(qhi, qlo, khi, klo, vhi, vlo, mhi, mlo);

    GemmTask tc = {whi + 3*DD*DD, wlo + 3*DD*DD, nullptr, 1.0f, out, nullptr, nullptr};
    dim3 go(DD / BN, MM / BM, 1);      // (16, 32, 1)
    gemm_hmma<<<go, 256, GEMM_SMEM>>>(mhi, mlo, tc, tc, tc);
}

// round 6
// speedup vs baseline: 4.9423x; 1.0936x over previous
#include <cuda_runtime.h>
#include <cuda_fp16.h>
#include <cstdint>

// Problem shape (fixed)
#define BB 2
#define LL 2048
#define DD 1024
#define HH 16
#define HD 64
#define MM (BB*LL)   // 4096

typedef __half fp16;

// ---------------------------------------------------------------------------
// Scratch (__device__ globals: allocation-free rule)
// ---------------------------------------------------------------------------
__device__ fp16 g_xhi[MM*DD], g_xlo[MM*DD];
__device__ fp16 g_whi[4*DD*DD], g_wlo[4*DD*DD];
__device__ fp16 g_qhi[MM*DD], g_qlo[MM*DD];
__device__ fp16 g_khi[MM*DD];
__device__ fp16 g_vhi[MM*DD], g_vlo[MM*DD];
__device__ fp16 g_mhi[MM*DD], g_mlo[MM*DD];

// ---------------------------------------------------------------------------
// Helpers (portable ISA only)
// ---------------------------------------------------------------------------
__device__ __forceinline__ uint32_t smem_u32(const void* p) {
    uint32_t a;
    asm("{ .reg .u64 t; cvta.to.shared.u64 t, %1; cvt.u32.u64 %0, t; }" : "=r"(a) : "l"(p));
    return a;
}
__device__ __forceinline__ void ldsm_x4(uint32_t& r0, uint32_t& r1, uint32_t& r2, uint32_t& r3,
                                        uint32_t addr) {
    asm volatile("ldmatrix.sync.aligned.m8n8.x4.shared.b16 {%0,%1,%2,%3}, [%4];"
                 : "=r"(r0), "=r"(r1), "=r"(r2), "=r"(r3) : "r"(addr));
}
__device__ __forceinline__ void ldsm_x4t(uint32_t& r0, uint32_t& r1, uint32_t& r2, uint32_t& r3,
                                         uint32_t addr) {
    asm volatile("ldmatrix.sync.aligned.m8n8.x4.trans.shared.b16 {%0,%1,%2,%3}, [%4];"
                 : "=r"(r0), "=r"(r1), "=r"(r2), "=r"(r3) : "r"(addr));
}
__device__ __forceinline__ void mma4(float* c, const uint32_t* a, const uint32_t* b) {
    asm volatile("mma.sync.aligned.m16n8k16.row.col.f32.f16.f16.f32 "
                 "{%0,%1,%2,%3}, {%4,%5,%6,%7}, {%8,%9}, {%0,%1,%2,%3};"
                 : "+f"(c[0]), "+f"(c[1]), "+f"(c[2]), "+f"(c[3])
                 : "r"(a[0]), "r"(a[1]), "r"(a[2]), "r"(a[3]), "r"(b[0]), "r"(b[1]));
}
__device__ __forceinline__ void cp16(uint32_t dst, const void* src) {
    asm volatile("cp.async.cg.shared.global [%0], [%1], 16;" :: "r"(dst), "l"(src));
}
#define CP_COMMIT() asm volatile("cp.async.commit_group;" ::: "memory")
#define CP_WAIT(N)  asm volatile("cp.async.wait_group %0;" :: "n"(N) : "memory")

__device__ __forceinline__ uint32_t packh2(float a, float b) {
    __half2 t = __floats2half2_rn(a, b);
    return *reinterpret_cast<uint32_t*>(&t);
}

// ---------------------------------------------------------------------------
// fp32 -> (fp16 hi, fp16 lo) splits
// ---------------------------------------------------------------------------
__device__ __forceinline__ void split4(const float* in, fp16* hi, fp16* lo, int i) {
    float4 v = reinterpret_cast<const float4*>(in)[i];
    fp16 h0 = __float2half_rn(v.x), h1 = __float2half_rn(v.y);
    fp16 h2 = __float2half_rn(v.z), h3 = __float2half_rn(v.w);
    fp16 l0 = __float2half_rn(v.x - __half2float(h0));
    fp16 l1 = __float2half_rn(v.y - __half2float(h1));
    fp16 l2 = __float2half_rn(v.z - __half2float(h2));
    fp16 l3 = __float2half_rn(v.w - __half2float(h3));
    __half2* H = reinterpret_cast<__half2*>(hi);
    __half2* L = reinterpret_cast<__half2*>(lo);
    H[2*i]   = __halves2half2(h0, h1);
    H[2*i+1] = __halves2half2(h2, h3);
    L[2*i]   = __halves2half2(l0, l1);
    L[2*i+1] = __halves2half2(l2, l3);
}

__global__ __launch_bounds__(256) void split_x(const float* __restrict__ in,
                                               fp16* __restrict__ hi,
                                               fp16* __restrict__ lo, int n4) {
    int i = blockIdx.x * 256 + threadIdx.x;
    if (i < n4) split4(in, hi, lo, i);
}

__global__ __launch_bounds__(256) void split_w(const float* __restrict__ w0,
                                               const float* __restrict__ w1,
                                               const float* __restrict__ w2,
                                               const float* __restrict__ w3,
                                               fp16* __restrict__ hi,
                                               fp16* __restrict__ lo, int n4) {
    int i = blockIdx.x * 256 + threadIdx.x;
    if (i >= n4) return;
    int z = blockIdx.y;
    const float* src = z == 0 ? w0 : z == 1 ? w1 : z == 2 ? w2 : w3;
    split4(src, hi + (size_t)z * DD * DD, lo + (size_t)z * DD * DD, i);
}

// ---------------------------------------------------------------------------
// HMMA GEMM, 3-stage cp.async pipeline, multi-task via blockIdx.z.
// C = A @ W^T + bias; per-task pass count: p3 ? (ah*bh + al*bh + ah*bl)
//                                             : (ah*bh + al*bh)
// Epilogue fp32 OR scaled split-fp16 (lo store optional).
// CTA 128x64, BK=32, 256 threads (8 warps, 4x2, 32x32 each).
// ---------------------------------------------------------------------------
#define GK 1024
#define BM 128
#define BN 64
#define BK 32
#define SZ_A (BM*40*2)                // 10240 B (row stride 80 B)
#define SZ_W (BN*40*2)                // 5120 B
#define STG  (2*SZ_A + 2*SZ_W)       // 30720 B per stage
#define NSTG 3
#define GEMM_SMEM (NSTG*STG)          // 92160 B

struct GemmTask {
    const fp16* Whi; const fp16* Wlo;
    const float* bias; float scale;
    float* Cf; fp16* Chi; fp16* Clo;
    int p3;
};

__global__ __launch_bounds__(256) void gemm_hmma(const fp16* __restrict__ Ahi,
                                                 const fp16* __restrict__ Alo,
                                                 GemmTask t0, GemmTask t1, GemmTask t2) {
    extern __shared__ __align__(16) char dsm[];
    const GemmTask tk = blockIdx.z == 0 ? t0 : blockIdx.z == 1 ? t1 : t2;
    const fp16* __restrict__ Whi = tk.Whi;
    const fp16* __restrict__ Wlo = tk.Wlo;
    const bool p3 = tk.p3 != 0;

    const uint32_t sb0 = smem_u32(dsm);
    const int tid  = threadIdx.x;
    const int wid  = tid >> 5;
    const int lane = tid & 31;
    const int wm   = wid >> 1;
    const int wn   = wid & 1;
    const int bm   = blockIdx.y * BM;
    const int bn   = blockIdx.x * BN;

    float acc[2][4][4];
#pragma unroll
    for (int i = 0; i < 2; i++)
#pragma unroll
        for (int j = 0; j < 4; j++)
#pragma unroll
            for (int k = 0; k < 4; k++) acc[i][j][k] = 0.f;

    auto issue = [&](int stg, int k0) {
        uint32_t base = sb0 + stg * STG;
#pragma unroll
        for (int i = 0; i < 2; i++) {
            int c = tid + 256 * i;
            int r = c >> 2, q = c & 3;
            const size_t off = (size_t)(bm + r) * GK + k0 + q * 8;
            cp16(base + r * 80 + q * 16,        Ahi + off);
            cp16(base + SZ_A + r * 80 + q * 16, Alo + off);
        }
        {
            int r = tid >> 2, q = tid & 3;
            const size_t off = (size_t)(bn + r) * GK + k0 + q * 8;
            cp16(base + 2*SZ_A + r * 80 + q * 16, Whi + off);
            if (p3)
                cp16(base + 2*SZ_A + SZ_W + r * 80 + q * 16, Wlo + off);
        }
        CP_COMMIT();
    };

    const int a_r    = lane & 15;
    const int a_half = lane >> 4;
    const int b_rr   = lane & 7;
    const int b_nt   = (lane >> 4) & 1;
    const int b_kh   = (lane >> 3) & 1;

    const int NIT = GK / BK;     // 32
    issue(0, 0);
    issue(1, BK);
    for (int it = 0; it < NIT; it++) {
        if (it + 2 < NIT) { issue((it + 2) % NSTG, (it + 2) * BK); CP_WAIT(2); }
        else if (it + 1 < NIT) { CP_WAIT(1); }
        else { CP_WAIT(0); }
        __syncthreads();

        const uint32_t base = sb0 + (it % NSTG) * STG;
        const uint32_t aAhi = base;
        const uint32_t aAlo = base + SZ_A;
        const uint32_t aWhi = base + 2*SZ_A;
        const uint32_t aWlo = base + 2*SZ_A + SZ_W;

#pragma unroll
        for (int ks = 0; ks < 2; ks++) {
            const int kk = ks * 16;
            uint32_t ah[2][4], al[2][4];
#pragma unroll
            for (int mt = 0; mt < 2; mt++) {
                uint32_t off = (uint32_t)(wm * 32 + mt * 16 + a_r) * 80 + (kk + a_half * 8) * 2;
                ldsm_x4(ah[mt][0], ah[mt][1], ah[mt][2], ah[mt][3], aAhi + off);
                ldsm_x4(al[mt][0], al[mt][1], al[mt][2], al[mt][3], aAlo + off);
            }
            uint32_t bh[4][2], bl[4][2];
#pragma unroll
            for (int p = 0; p < 2; p++) {
                uint32_t off = (uint32_t)(wn * 32 + p * 16 + b_nt * 8 + b_rr) * 80
                             + (kk + b_kh * 8) * 2;
                ldsm_x4(bh[p*2][0], bh[p*2][1], bh[p*2+1][0], bh[p*2+1][1], aWhi + off);
                if (p3)
                    ldsm_x4(bl[p*2][0], bl[p*2][1], bl[p*2+1][0], bl[p*2+1][1], aWlo + off);
            }
#pragma unroll
            for (int mt = 0; mt < 2; mt++)
#pragma unroll
                for (int nt = 0; nt < 4; nt++) {
                    mma4(acc[mt][nt], ah[mt], bh[nt]);
                    mma4(acc[mt][nt], al[mt], bh[nt]);
                }
            if (p3) {
#pragma unroll
                for (int mt = 0; mt < 2; mt++)
#pragma unroll
                    for (int nt = 0; nt < 4; nt++)
                        mma4(acc[mt][nt], ah[mt], bl[nt]);
            }
        }
        __syncthreads();
    }

    // ---- epilogue ----
    const int gid = lane >> 2;
    const int tig = lane & 3;
#pragma unroll
    for (int mt = 0; mt < 2; mt++) {
#pragma unroll
        for (int nt = 0; nt < 4; nt++) {
            int row = bm + wm * 32 + mt * 16 + gid;
            int col = bn + wn * 32 + nt * 8 + 2 * tig;
            float b0 = tk.bias ? tk.bias[col]     : 0.f;
            float b1 = tk.bias ? tk.bias[col + 1] : 0.f;
            float v00 = (acc[mt][nt][0] + b0) * tk.scale;
            float v01 = (acc[mt][nt][1] + b1) * tk.scale;
            float v10 = (acc[mt][nt][2] + b0) * tk.scale;
            float v11 = (acc[mt][nt][3] + b1) * tk.scale;
            if (tk.Cf) {
                *reinterpret_cast<float2*>(tk.Cf + (size_t)row * GK + col)       = make_float2(v00, v01);
                *reinterpret_cast<float2*>(tk.Cf + (size_t)(row + 8) * GK + col) = make_float2(v10, v11);
            } else {
                __half2 h0 = __floats2half2_rn(v00, v01);
                __half2 h1 = __floats2half2_rn(v10, v11);
                *reinterpret_cast<__half2*>(tk.Chi + (size_t)row * GK + col)       = h0;
                *reinterpret_cast<__half2*>(tk.Chi + (size_t)(row + 8) * GK + col) = h1;
                if (tk.Clo) {
                    __half2 l0 = __floats2half2_rn(v00 - __half2float(h0.x),
                                                   v01 - __half2float(h0.y));
                    __half2 l1 = __floats2half2_rn(v10 - __half2float(h1.x),
                                                   v11 - __half2float(h1.y));
                    *reinterpret_cast<__half2*>(tk.Clo + (size_t)row * GK + col)       = l0;
                    *reinterpret_cast<__half2*>(tk.Clo + (size_t)(row + 8) * GK + col) = l1;
                }
            }
        }
    }
}

// ---------------------------------------------------------------------------
// HMMA flash attention, double-buffered KV.
// S = (Qhi+Qlo) K_hi^T (2-pass, no K_lo anywhere);
// O += P V (3-pass: Ph Vh + Ph Vl + Pl Vh).
// Block = 128 threads (4 warps), 64 query rows, KV tiles of 64.
// smem/stage: Kh, Vh, Vl (3 arrays) -> 54 KB total, 4 CTAs/SM.
// Blocks run in REVERSED i0 order (largest workload first).
// ---------------------------------------------------------------------------
#define AROWB 144                       // bytes per 64-col fp16 row (72 elems)
#define ATILE_B (64*AROWB)              // 9216 B per array
#define ASTG_B (3*ATILE_B)              // Kh,Vh,Vl per stage = 27648 B
#define ATTN_SMEM (2*ASTG_B)            // 55296 B

__global__ __launch_bounds__(128, 4) void attn_mma(const fp16* __restrict__ Qhi,
                                                   const fp16* __restrict__ Qlo,
                                                   const fp16* __restrict__ Khi,
                                                   const fp16* __restrict__ Vhi,
                                                   const fp16* __restrict__ Vlo,
                                                   fp16* __restrict__ Ohi,
                                                   fp16* __restrict__ Olo) {
    extern __shared__ __align__(16) char asm_[];
    const uint32_t sb = smem_u32(asm_);

    const int i0 = (int)(gridDim.x - 1 - blockIdx.x) * 64;   // reversed order
    const int h  = blockIdx.y;
    const int b  = blockIdx.z;
    const int tid  = threadIdx.x;
    const int w    = tid >> 5;
    const int lane = tid & 31;
    const int gid  = lane >> 2;
    const int tig  = lane & 3;
    const int r0   = w * 16;

    const size_t baseq = ((size_t)(b * LL + i0)) * DD + h * HD;

    auto issueKV = [&](uint32_t stg, int j0) {
        const size_t basekv = ((size_t)(b * LL + j0)) * DD + h * HD;
#pragma unroll
        for (int i = 0; i < 4; i++) {
            int c = tid + 128 * i;
            int r = c >> 3, q = c & 7;
            const size_t off = basekv + (size_t)r * DD + q * 8;
            const uint32_t d = stg + r * AROWB + q * 16;
            cp16(d,               Khi + off);
            cp16(d + ATILE_B,     Vhi + off);
            cp16(d + 2*ATILE_B,   Vlo + off);
        }
        CP_COMMIT();
    };

    // ---- stage Q through stage-1 buffers; prefetch KV tile 0 into stage 0 ----
#pragma unroll
    for (int i = 0; i < 4; i++) {
        int c = tid + 128 * i;
        int r = c >> 3, q = c & 7;
        const size_t off = baseq + (size_t)r * DD + q * 8;
        cp16(sb + ASTG_B + r * AROWB + q * 16,           Qhi + off);
        cp16(sb + ASTG_B + ATILE_B + r * AROWB + q * 16, Qlo + off);
    }
    CP_COMMIT();
    issueKV(sb, 0);
    CP_WAIT(1);               // Q ready (KV0 may still be in flight)
    __syncthreads();

    const int a_r = lane & 15, a_h = lane >> 4;
    uint32_t qh[4][4], ql[4][4];
#pragma unroll
    for (int ks = 0; ks < 4; ks++) {
        uint32_t off = (uint32_t)(r0 + a_r) * AROWB + (ks * 16 + a_h * 8) * 2;
        ldsm_x4(qh[ks][0], qh[ks][1], qh[ks][2], qh[ks][3], sb + ASTG_B + off);
        ldsm_x4(ql[ks][0], ql[ks][1], ql[ks][2], ql[ks][3], sb + ASTG_B + ATILE_B + off);
    }
    __syncthreads();          // Q buffers free for KV reuse

    float o[8][4];
#pragma unroll
    for (int nt = 0; nt < 8; nt++)
#pragma unroll
        for (int k = 0; k < 4; k++) o[nt][k] = 0.f;
    float mrow0 = -1e30f, mrow1 = -1e30f, lrow0 = 0.f, lrow1 = 0.f;

    const int b_rr = lane & 7;
    const int b_nt = (lane >> 4) & 1;
    const int b_kh = (lane >> 3) & 1;

    const int T = i0 / 64 + 1;
    for (int t = 0; t < T; t++) {
        if (t + 1 < T) { issueKV(sb + ((t + 1) & 1) * ASTG_B, (t + 1) * 64); CP_WAIT(1); }
        else           { CP_WAIT(0); }
        __syncthreads();

        const uint32_t aKh = sb + (t & 1) * ASTG_B;
        const uint32_t aVh = aKh + ATILE_B;
        const uint32_t aVl = aKh + 2*ATILE_B;

        // ---- S = Q K^T (2-pass: qh*kh + ql*kh) ----
        float s[8][4];
#pragma unroll
        for (int nt = 0; nt < 8; nt++)
#pragma unroll
            for (int k = 0; k < 4; k++) s[nt][k] = 0.f;

#pragma unroll
        for (int ks = 0; ks < 4; ks++) {
            const int kk = ks * 16;
            uint32_t kh[8][2];
#pragma unroll
            for (int p = 0; p < 4; p++) {
                uint32_t off = (uint32_t)(p * 16 + b_nt * 8 + b_rr) * AROWB + (kk + b_kh * 8) * 2;
                ldsm_x4(kh[p*2][0], kh[p*2][1], kh[p*2+1][0], kh[p*2+1][1], aKh + off);
            }
#pragma unroll
            for (int nt = 0; nt < 8; nt++) {
                mma4(s[nt], qh[ks], kh[nt]);
                mma4(s[nt], ql[ks], kh[nt]);
            }
        }

        // ---- causal mask (diagonal tile only; reversed order: t==T-1) ----
        if (t == T - 1) {
#pragma unroll
            for (int nt = 0; nt < 8; nt++) {
                int col0 = nt * 8 + 2 * tig;
                int rowa = r0 + gid, rowb = rowa + 8;
                if (col0     > rowa) s[nt][0] = -1e30f;
                if (col0 + 1 > rowa) s[nt][1] = -1e30f;
                if (col0     > rowb) s[nt][2] = -1e30f;
                if (col0 + 1 > rowb) s[nt][3] = -1e30f;
            }
        }

        // ---- online softmax (quad reduction) ----
        float mxa = -1e30f, mxb = -1e30f;
#pragma unroll
        for (int nt = 0; nt < 8; nt++) {
            mxa = fmaxf(mxa, fmaxf(s[nt][0], s[nt][1]));
            mxb = fmaxf(mxb, fmaxf(s[nt][2], s[nt][3]));
        }
        mxa = fmaxf(mxa, __shfl_xor_sync(0xFFFFFFFFu, mxa, 1));
        mxa = fmaxf(mxa, __shfl_xor_sync(0xFFFFFFFFu, mxa, 2));
        mxb = fmaxf(mxb, __shfl_xor_sync(0xFFFFFFFFu, mxb, 1));
        mxb = fmaxf(mxb, __shfl_xor_sync(0xFFFFFFFFu, mxb, 2));

        float mna = fmaxf(mrow0, mxa), mnb = fmaxf(mrow1, mxb);
        float ala = __expf(mrow0 - mna), alb = __expf(mrow1 - mnb);
        float suma = 0.f, sumb = 0.f;
#pragma unroll
        for (int nt = 0; nt < 8; nt++) {
            s[nt][0] = __expf(s[nt][0] - mna); suma += s[nt][0];
            s[nt][1] = __expf(s[nt][1] - mna); suma += s[nt][1];
            s[nt][2] = __expf(s[nt][2] - mnb); sumb += s[nt][2];
            s[nt][3] = __expf(s[nt][3] - mnb); sumb += s[nt][3];
        }
        suma += __shfl_xor_sync(0xFFFFFFFFu, suma, 1);
        suma += __shfl_xor_sync(0xFFFFFFFFu, suma, 2);
        sumb += __shfl_xor_sync(0xFFFFFFFFu, sumb, 1);
        sumb += __shfl_xor_sync(0xFFFFFFFFu, sumb, 2);
        lrow0 = lrow0 * ala + suma; mrow0 = mna;
        lrow1 = lrow1 * alb + sumb; mrow1 = mnb;

#pragma unroll
        for (int nt = 0; nt < 8; nt++) {
            o[nt][0] *= ala; o[nt][1] *= ala;
            o[nt][2] *= alb; o[nt][3] *= alb;
        }

        // ---- O += P V (3-pass; P frags from S regs) ----
#pragma unroll
        for (int ks2 = 0; ks2 < 4; ks2++) {
            const float* sa  = s[2*ks2];
            const float* sb2 = s[2*ks2 + 1];
            uint32_t phi[4], plo[4];
            {
                __half2 h0 = __floats2half2_rn(sa[0], sa[1]);
                __half2 h1 = __floats2half2_rn(sa[2], sa[3]);
                __half2 h2 = __floats2half2_rn(sb2[0], sb2[1]);
                __half2 h3 = __floats2half2_rn(sb2[2], sb2[3]);
                phi[0] = *reinterpret_cast<uint32_t*>(&h0);
                phi[1] = *reinterpret_cast<uint32_t*>(&h1);
                phi[2] = *reinterpret_cast<uint32_t*>(&h2);
                phi[3] = *reinterpret_cast<uint32_t*>(&h3);
                plo[0] = packh2(sa[0]  - __half2float(h0.x), sa[1]  - __half2float(h0.y));
                plo[1] = packh2(sa[2]  - __half2float(h1.x), sa[3]  - __half2float(h1.y));
                plo[2] = packh2(sb2[0] - __half2float(h2.x), sb2[1] - __half2float(h2.y));
                plo[3] = packh2(sb2[2] - __half2float(h3.x), sb2[3] - __half2float(h3.y));
            }
            uint32_t vh[8][2], vl[8][2];
#pragma unroll
            for (int p = 0; p < 4; p++) {
                uint32_t off = (uint32_t)(ks2 * 16 + b_kh * 8 + b_rr) * AROWB
                             + (p * 16 + b_nt * 8) * 2;
                ldsm_x4t(vh[p*2][0], vh[p*2][1], vh[p*2+1][0], vh[p*2+1][1], aVh + off);
                ldsm_x4t(vl[p*2][0], vl[p*2][1], vl[p*2+1][0], vl[p*2+1][1], aVl + off);
            }
#pragma unroll
            for (int nt = 0; nt < 8; nt++) {
                mma4(o[nt], phi, vh[nt]);
                mma4(o[nt], phi, vl[nt]);
                mma4(o[nt], plo, vh[nt]);
            }
        }
        __syncthreads();
    }

    // ---- epilogue: normalize, split to hi/lo, store ----
    const float inv0 = 1.0f / lrow0;
    const float inv1 = 1.0f / lrow1;
    const size_t rowa = (size_t)(b * LL + i0 + r0 + gid) * DD + h * HD;
    const size_t rowb = rowa + (size_t)8 * DD;
#pragma unroll
    for (int nt = 0; nt < 8; nt++) {
        int col = nt * 8 + 2 * tig;
        float v0 = o[nt][0] * inv0, v1 = o[nt][1] * inv0;
        float v2 = o[nt][2] * inv1, v3 = o[nt][3] * inv1;
        __half2 ha = __floats2half2_rn(v0, v1);
        __half2 hb = __floats2half2_rn(v2, v3);
        __half2 la = __floats2half2_rn(v0 - __half2float(ha.x), v1 - __half2float(ha.y));
        __half2 lb = __floats2half2_rn(v2 - __half2float(hb.x), v3 - __half2float(hb.y));
        *reinterpret_cast<__half2*>(Ohi + rowa + col) = ha;
        *reinterpret_cast<__half2*>(Olo + rowa + col) = la;
        *reinterpret_cast<__half2*>(Ohi + rowb + col) = hb;
        *reinterpret_cast<__half2*>(Olo + rowb + col) = lb;
    }
}

// ---------------------------------------------------------------------------
extern "C" void kernel_launch(void* const* d_in, const int* in_sizes, int n_in,
                              void* d_out, int out_size) {
    const float* x  = (const float*)d_in[0];
    const float* WQ = (const float*)d_in[1];
    const float* bQ = (const float*)d_in[2];
    const float* WK = (const float*)d_in[3];
    const float* bK = (const float*)d_in[4];
    const float* WV = (const float*)d_in[5];
    const float* bV = (const float*)d_in[6];
    const float* Wc = (const float*)d_in[7];
    float* out = (float*)d_out;

    cudaFuncSetAttribute(gemm_hmma, cudaFuncAttributeMaxDynamicSharedMemorySize, GEMM_SMEM);
    cudaFuncSetAttribute(attn_mma,  cudaFuncAttributeMaxDynamicSharedMemorySize, ATTN_SMEM);

    fp16 *xhi, *xlo, *whi, *wlo, *qhi, *qlo, *khi, *vhi, *vlo, *mhi, *mlo;
    cudaGetSymbolAddress((void**)&xhi, g_xhi);
    cudaGetSymbolAddress((void**)&xlo, g_xlo);
    cudaGetSymbolAddress((void**)&whi, g_whi);
    cudaGetSymbolAddress((void**)&wlo, g_wlo);
    cudaGetSymbolAddress((void**)&qhi, g_qhi);
    cudaGetSymbolAddress((void**)&qlo, g_qlo);
    cudaGetSymbolAddress((void**)&khi, g_khi);
    cudaGetSymbolAddress((void**)&vhi, g_vhi);
    cudaGetSymbolAddress((void**)&vlo, g_vlo);
    cudaGetSymbolAddress((void**)&mhi, g_mhi);
    cudaGetSymbolAddress((void**)&mlo, g_mlo);

    const int nx4 = MM * DD / 4;
    const int nw4 = DD * DD / 4;

    split_x<<<(nx4 + 255) / 256, 256>>>(x, xhi, xlo, nx4);
    dim3 gw((nw4 + 255) / 256, 4);
    split_w<<<gw, 256>>>(WQ, WK, WV, Wc, whi, wlo, nw4);

    // Q,K: 2-pass (softmax damps their error); V: 3-pass (flows to output).
    GemmTask tq = {whi + 0*DD*DD, wlo + 0*DD*DD, bQ, 0.125f, nullptr, qhi, qlo,   0};
    GemmTask tk = {whi + 1*DD*DD, wlo + 1*DD*DD, bK, 1.0f,   nullptr, khi, nullptr, 0};
    GemmTask tv = {whi + 2*DD*DD, wlo + 2*DD*DD, bV, 1.0f,   nullptr, vhi, vlo,   1};
    dim3 gqkv(DD / BN, MM / BM, 3);    // (16, 32, 3)
    gemm_hmma<<<gqkv, 256, GEMM_SMEM>>>(xhi, xlo, tq, tk, tv);

    dim3 ga(LL / 64, HH, BB);          // (32, 16, 2)
    attn_mma<<<ga, 128, ATTN_SMEM>>>(qhi, qlo, khi, vhi, vlo, mhi, mlo);

    // Final channel mix: 3-pass, fp32 out.
    GemmTask tc = {whi + 3*DD*DD, wlo + 3*DD*DD, nullptr, 1.0f, out, nullptr, nullptr, 1};
    dim3 go(DD / BN, MM / BM, 1);      // (16, 32, 1)
    gemm_hmma<<<go, 256, GEMM_SMEM>>>(mhi, mlo, tc, tc, tc);
}

// round 7
// speedup vs baseline: 6.4072x; 1.2964x over previous
#include <cuda_runtime.h>
#include <cuda_fp16.h>
#include <cstdint>

// Problem shape (fixed)
#define BB 2
#define LL 2048
#define DD 1024
#define HH 16
#define HD 64
#define MM (BB*LL)   // 4096

typedef __half fp16;

// ---------------------------------------------------------------------------
// Scratch (__device__ globals: allocation-free rule)
// ---------------------------------------------------------------------------
__device__ fp16 g_xhi[MM*DD], g_xlo[MM*DD];
__device__ fp16 g_whi[4*DD*DD];
__device__ fp16 g_qhi[MM*DD], g_qlo[MM*DD];
__device__ fp16 g_khi[MM*DD];
__device__ fp16 g_vhi[MM*DD];
__device__ fp16 g_mhi[MM*DD], g_mlo[MM*DD];

// ---------------------------------------------------------------------------
// Helpers (portable ISA only)
// ---------------------------------------------------------------------------
__device__ __forceinline__ uint32_t smem_u32(const void* p) {
    uint32_t a;
    asm("{ .reg .u64 t; cvta.to.shared.u64 t, %1; cvt.u32.u64 %0, t; }" : "=r"(a) : "l"(p));
    return a;
}
__device__ __forceinline__ void ldsm_x4(uint32_t& r0, uint32_t& r1, uint32_t& r2, uint32_t& r3,
                                        uint32_t addr) {
    asm volatile("ldmatrix.sync.aligned.m8n8.x4.shared.b16 {%0,%1,%2,%3}, [%4];"
                 : "=r"(r0), "=r"(r1), "=r"(r2), "=r"(r3) : "r"(addr));
}
__device__ __forceinline__ void ldsm_x4t(uint32_t& r0, uint32_t& r1, uint32_t& r2, uint32_t& r3,
                                         uint32_t addr) {
    asm volatile("ldmatrix.sync.aligned.m8n8.x4.trans.shared.b16 {%0,%1,%2,%3}, [%4];"
                 : "=r"(r0), "=r"(r1), "=r"(r2), "=r"(r3) : "r"(addr));
}
__device__ __forceinline__ void mma4(float* c, const uint32_t* a, const uint32_t* b) {
    asm volatile("mma.sync.aligned.m16n8k16.row.col.f32.f16.f16.f32 "
                 "{%0,%1,%2,%3}, {%4,%5,%6,%7}, {%8,%9}, {%0,%1,%2,%3};"
                 : "+f"(c[0]), "+f"(c[1]), "+f"(c[2]), "+f"(c[3])
                 : "r"(a[0]), "r"(a[1]), "r"(a[2]), "r"(a[3]), "r"(b[0]), "r"(b[1]));
}
__device__ __forceinline__ void cp16(uint32_t dst, const void* src) {
    asm volatile("cp.async.cg.shared.global [%0], [%1], 16;" :: "r"(dst), "l"(src));
}
#define CP_COMMIT() asm volatile("cp.async.commit_group;" ::: "memory")
#define CP_WAIT(N)  asm volatile("cp.async.wait_group %0;" :: "n"(N) : "memory")

__device__ __forceinline__ uint32_t packh2(float a, float b) {
    __half2 t = __floats2half2_rn(a, b);
    return *reinterpret_cast<uint32_t*>(&t);
}

// ---------------------------------------------------------------------------
// fp32 -> fp16 splits
// ---------------------------------------------------------------------------
__device__ __forceinline__ void split4(const float* in, fp16* hi, fp16* lo, int i) {
    float4 v = reinterpret_cast<const float4*>(in)[i];
    fp16 h0 = __float2half_rn(v.x), h1 = __float2half_rn(v.y);
    fp16 h2 = __float2half_rn(v.z), h3 = __float2half_rn(v.w);
    fp16 l0 = __float2half_rn(v.x - __half2float(h0));
    fp16 l1 = __float2half_rn(v.y - __half2float(h1));
    fp16 l2 = __float2half_rn(v.z - __half2float(h2));
    fp16 l3 = __float2half_rn(v.w - __half2float(h3));
    __half2* H = reinterpret_cast<__half2*>(hi);
    __half2* L = reinterpret_cast<__half2*>(lo);
    H[2*i]   = __halves2half2(h0, h1);
    H[2*i+1] = __halves2half2(h2, h3);
    L[2*i]   = __halves2half2(l0, l1);
    L[2*i+1] = __halves2half2(l2, l3);
}

__global__ __launch_bounds__(256) void split_x(const float* __restrict__ in,
                                               fp16* __restrict__ hi,
                                               fp16* __restrict__ lo, int n4) {
    int i = blockIdx.x * 256 + threadIdx.x;
    if (i < n4) split4(in, hi, lo, i);
}

// 4 weight matrices, hi (rounded fp16) only — lo never consumed anywhere.
__global__ __launch_bounds__(256) void split_w(const float* __restrict__ w0,
                                               const float* __restrict__ w1,
                                               const float* __restrict__ w2,
                                               const float* __restrict__ w3,
                                               fp16* __restrict__ hi, int n4) {
    int i = blockIdx.x * 256 + threadIdx.x;
    if (i >= n4) return;
    int z = blockIdx.y;
    const float* src = z == 0 ? w0 : z == 1 ? w1 : z == 2 ? w2 : w3;
    float4 v = reinterpret_cast<const float4*>(src)[i];
    __half2* H = reinterpret_cast<__half2*>(hi + (size_t)z * DD * DD);
    H[2*i]   = __floats2half2_rn(v.x, v.y);
    H[2*i+1] = __floats2half2_rn(v.z, v.w);
}

// ---------------------------------------------------------------------------
// HMMA GEMM, 3-stage cp.async pipeline, multi-task via blockIdx.z.
// C = (Ahi+Alo) @ Whi^T + bias  (uniform 2-pass; W rounded to fp16)
// Epilogue fp32 OR scaled fp16 (hi, optional lo).
// CTA 128x64, BK=32, 256 threads (8 warps, 4x2, 32x32 each).
// ---------------------------------------------------------------------------
#define GK 1024
#define BM 128
#define BN 64
#define BK 32
#define SZ_A (BM*40*2)                // 10240 B (row stride 80 B)
#define SZ_W (BN*40*2)                // 5120 B
#define STG  (2*SZ_A + SZ_W)          // 25600 B per stage
#define NSTG 3
#define GEMM_SMEM (NSTG*STG)          // 76800 B

struct GemmTask {
    const fp16* Whi;
    const float* bias; float scale;
    float* Cf; fp16* Chi; fp16* Clo;
};

__global__ __launch_bounds__(256) void gemm_hmma(const fp16* __restrict__ Ahi,
                                                 const fp16* __restrict__ Alo,
                                                 GemmTask t0, GemmTask t1, GemmTask t2) {
    extern __shared__ __align__(16) char dsm[];
    const GemmTask tk = blockIdx.z == 0 ? t0 : blockIdx.z == 1 ? t1 : t2;
    const fp16* __restrict__ Whi = tk.Whi;

    const uint32_t sb0 = smem_u32(dsm);
    const int tid  = threadIdx.x;
    const int wid  = tid >> 5;
    const int lane = tid & 31;
    const int wm   = wid >> 1;
    const int wn   = wid & 1;
    const int bm   = blockIdx.y * BM;
    const int bn   = blockIdx.x * BN;

    float acc[2][4][4];
#pragma unroll
    for (int i = 0; i < 2; i++)
#pragma unroll
        for (int j = 0; j < 4; j++)
#pragma unroll
            for (int k = 0; k < 4; k++) acc[i][j][k] = 0.f;

    auto issue = [&](int stg, int k0) {
        uint32_t base = sb0 + stg * STG;
#pragma unroll
        for (int i = 0; i < 2; i++) {
            int c = tid + 256 * i;
            int r = c >> 2, q = c & 3;
            const size_t off = (size_t)(bm + r) * GK + k0 + q * 8;
            cp16(base + r * 80 + q * 16,        Ahi + off);
            cp16(base + SZ_A + r * 80 + q * 16, Alo + off);
        }
        {
            int r = tid >> 2, q = tid & 3;
            const size_t off = (size_t)(bn + r) * GK + k0 + q * 8;
            cp16(base + 2*SZ_A + r * 80 + q * 16, Whi + off);
        }
        CP_COMMIT();
    };

    const int a_r    = lane & 15;
    const int a_half = lane >> 4;
    const int b_rr   = lane & 7;
    const int b_nt   = (lane >> 4) & 1;
    const int b_kh   = (lane >> 3) & 1;

    const int NIT = GK / BK;     // 32
    issue(0, 0);
    issue(1, BK);
    for (int it = 0; it < NIT; it++) {
        if (it + 2 < NIT) { issue((it + 2) % NSTG, (it + 2) * BK); CP_WAIT(2); }
        else if (it + 1 < NIT) { CP_WAIT(1); }
        else { CP_WAIT(0); }
        __syncthreads();

        const uint32_t base = sb0 + (it % NSTG) * STG;
        const uint32_t aAhi = base;
        const uint32_t aAlo = base + SZ_A;
        const uint32_t aWhi = base + 2*SZ_A;

#pragma unroll
        for (int ks = 0; ks < 2; ks++) {
            const int kk = ks * 16;
            uint32_t ah[2][4], al[2][4];
#pragma unroll
            for (int mt = 0; mt < 2; mt++) {
                uint32_t off = (uint32_t)(wm * 32 + mt * 16 + a_r) * 80 + (kk + a_half * 8) * 2;
                ldsm_x4(ah[mt][0], ah[mt][1], ah[mt][2], ah[mt][3], aAhi + off);
                ldsm_x4(al[mt][0], al[mt][1], al[mt][2], al[mt][3], aAlo + off);
            }
            uint32_t bh[4][2];
#pragma unroll
            for (int p = 0; p < 2; p++) {
                uint32_t off = (uint32_t)(wn * 32 + p * 16 + b_nt * 8 + b_rr) * 80
                             + (kk + b_kh * 8) * 2;
                ldsm_x4(bh[p*2][0], bh[p*2][1], bh[p*2+1][0], bh[p*2+1][1], aWhi + off);
            }
#pragma unroll
            for (int mt = 0; mt < 2; mt++)
#pragma unroll
                for (int nt = 0; nt < 4; nt++) {
                    mma4(acc[mt][nt], ah[mt], bh[nt]);
                    mma4(acc[mt][nt], al[mt], bh[nt]);
                }
        }
        __syncthreads();
    }

    // ---- epilogue ----
    const int gid = lane >> 2;
    const int tig = lane & 3;
#pragma unroll
    for (int mt = 0; mt < 2; mt++) {
#pragma unroll
        for (int nt = 0; nt < 4; nt++) {
            int row = bm + wm * 32 + mt * 16 + gid;
            int col = bn + wn * 32 + nt * 8 + 2 * tig;
            float b0 = tk.bias ? tk.bias[col]     : 0.f;
            float b1 = tk.bias ? tk.bias[col + 1] : 0.f;
            float v00 = (acc[mt][nt][0] + b0) * tk.scale;
            float v01 = (acc[mt][nt][1] + b1) * tk.scale;
            float v10 = (acc[mt][nt][2] + b0) * tk.scale;
            float v11 = (acc[mt][nt][3] + b1) * tk.scale;
            if (tk.Cf) {
                *reinterpret_cast<float2*>(tk.Cf + (size_t)row * GK + col)       = make_float2(v00, v01);
                *reinterpret_cast<float2*>(tk.Cf + (size_t)(row + 8) * GK + col) = make_float2(v10, v11);
            } else {
                __half2 h0 = __floats2half2_rn(v00, v01);
                __half2 h1 = __floats2half2_rn(v10, v11);
                *reinterpret_cast<__half2*>(tk.Chi + (size_t)row * GK + col)       = h0;
                *reinterpret_cast<__half2*>(tk.Chi + (size_t)(row + 8) * GK + col) = h1;
                if (tk.Clo) {
                    __half2 l0 = __floats2half2_rn(v00 - __half2float(h0.x),
                                                   v01 - __half2float(h0.y));
                    __half2 l1 = __floats2half2_rn(v10 - __half2float(h1.x),
                                                   v11 - __half2float(h1.y));
                    *reinterpret_cast<__half2*>(tk.Clo + (size_t)row * GK + col)       = l0;
                    *reinterpret_cast<__half2*>(tk.Clo + (size_t)(row + 8) * GK + col) = l1;
                }
            }
        }
    }
}

// ---------------------------------------------------------------------------
// HMMA flash attention, double-buffered KV.
// S = (Qhi+Qlo) Khi^T (2-pass); O += (Phi+Plo) Vhi (2-pass, V fp16-rounded).
// Block = 128 threads (4 warps), 64 query rows, KV tiles of 64.
// smem/stage: Kh, Vh (2 arrays) -> 36 KB total, 4 CTAs/SM.
// Blocks run in REVERSED i0 order (largest workload first).
// ---------------------------------------------------------------------------
#define AROWB 144                       // bytes per 64-col fp16 row (72 elems)
#define ATILE_B (64*AROWB)              // 9216 B per array
#define ASTG_B (2*ATILE_B)              // Kh,Vh per stage = 18432 B
#define ATTN_SMEM (2*ASTG_B)            // 36864 B

__global__ __launch_bounds__(128, 4) void attn_mma(const fp16* __restrict__ Qhi,
                                                   const fp16* __restrict__ Qlo,
                                                   const fp16* __restrict__ Khi,
                                                   const fp16* __restrict__ Vhi,
                                                   fp16* __restrict__ Ohi,
                                                   fp16* __restrict__ Olo) {
    extern __shared__ __align__(16) char asm_[];
    const uint32_t sb = smem_u32(asm_);

    const int i0 = (int)(gridDim.x - 1 - blockIdx.x) * 64;   // reversed order
    const int h  = blockIdx.y;
    const int b  = blockIdx.z;
    const int tid  = threadIdx.x;
    const int w    = tid >> 5;
    const int lane = tid & 31;
    const int gid  = lane >> 2;
    const int tig  = lane & 3;
    const int r0   = w * 16;

    const size_t baseq = ((size_t)(b * LL + i0)) * DD + h * HD;

    auto issueKV = [&](uint32_t stg, int j0) {
        const size_t basekv = ((size_t)(b * LL + j0)) * DD + h * HD;
#pragma unroll
        for (int i = 0; i < 4; i++) {
            int c = tid + 128 * i;
            int r = c >> 3, q = c & 7;
            const size_t off = basekv + (size_t)r * DD + q * 8;
            const uint32_t d = stg + r * AROWB + q * 16;
            cp16(d,           Khi + off);
            cp16(d + ATILE_B, Vhi + off);
        }
        CP_COMMIT();
    };

    // ---- stage Q through stage-1 buffers; prefetch KV tile 0 into stage 0 ----
#pragma unroll
    for (int i = 0; i < 4; i++) {
        int c = tid + 128 * i;
        int r = c >> 3, q = c & 7;
        const size_t off = baseq + (size_t)r * DD + q * 8;
        cp16(sb + ASTG_B + r * AROWB + q * 16,           Qhi + off);
        cp16(sb + ASTG_B + ATILE_B + r * AROWB + q * 16, Qlo + off);
    }
    CP_COMMIT();
    issueKV(sb, 0);
    CP_WAIT(1);               // Q ready (KV0 may still be in flight)
    __syncthreads();

    const int a_r = lane & 15, a_h = lane >> 4;
    uint32_t qh[4][4], ql[4][4];
#pragma unroll
    for (int ks = 0; ks < 4; ks++) {
        uint32_t off = (uint32_t)(r0 + a_r) * AROWB + (ks * 16 + a_h * 8) * 2;
        ldsm_x4(qh[ks][0], qh[ks][1], qh[ks][2], qh[ks][3], sb + ASTG_B + off);
        ldsm_x4(ql[ks][0], ql[ks][1], ql[ks][2], ql[ks][3], sb + ASTG_B + ATILE_B + off);
    }
    __syncthreads();          // Q buffers free for KV reuse

    float o[8][4];
#pragma unroll
    for (int nt = 0; nt < 8; nt++)
#pragma unroll
        for (int k = 0; k < 4; k++) o[nt][k] = 0.f;
    float mrow0 = -1e30f, mrow1 = -1e30f, lrow0 = 0.f, lrow1 = 0.f;

    const int b_rr = lane & 7;
    const int b_nt = (lane >> 4) & 1;
    const int b_kh = (lane >> 3) & 1;

    const int T = i0 / 64 + 1;
    for (int t = 0; t < T; t++) {
        if (t + 1 < T) { issueKV(sb + ((t + 1) & 1) * ASTG_B, (t + 1) * 64); CP_WAIT(1); }
        else           { CP_WAIT(0); }
        __syncthreads();

        const uint32_t aKh = sb + (t & 1) * ASTG_B;
        const uint32_t aVh = aKh + ATILE_B;

        // ---- S = Q K^T (2-pass: qh*kh + ql*kh) ----
        float s[8][4];
#pragma unroll
        for (int nt = 0; nt < 8; nt++)
#pragma unroll
            for (int k = 0; k < 4; k++) s[nt][k] = 0.f;

#pragma unroll
        for (int ks = 0; ks < 4; ks++) {
            const int kk = ks * 16;
            uint32_t kh[8][2];
#pragma unroll
            for (int p = 0; p < 4; p++) {
                uint32_t off = (uint32_t)(p * 16 + b_nt * 8 + b_rr) * AROWB + (kk + b_kh * 8) * 2;
                ldsm_x4(kh[p*2][0], kh[p*2][1], kh[p*2+1][0], kh[p*2+1][1], aKh + off);
            }
#pragma unroll
            for (int nt = 0; nt < 8; nt++) {
                mma4(s[nt], qh[ks], kh[nt]);
                mma4(s[nt], ql[ks], kh[nt]);
            }
        }

        // ---- causal mask (diagonal tile only; reversed order: t==T-1) ----
        if (t == T - 1) {
#pragma unroll
            for (int nt = 0; nt < 8; nt++) {
                int col0 = nt * 8 + 2 * tig;
                int rowa = r0 + gid, rowb = rowa + 8;
                if (col0     > rowa) s[nt][0] = -1e30f;
                if (col0 + 1 > rowa) s[nt][1] = -1e30f;
                if (col0     > rowb) s[nt][2] = -1e30f;
                if (col0 + 1 > rowb) s[nt][3] = -1e30f;
            }
        }

        // ---- online softmax (quad reduction) ----
        float mxa = -1e30f, mxb = -1e30f;
#pragma unroll
        for (int nt = 0; nt < 8; nt++) {
            mxa = fmaxf(mxa, fmaxf(s[nt][0], s[nt][1]));
            mxb = fmaxf(mxb, fmaxf(s[nt][2], s[nt][3]));
        }
        mxa = fmaxf(mxa, __shfl_xor_sync(0xFFFFFFFFu, mxa, 1));
        mxa = fmaxf(mxa, __shfl_xor_sync(0xFFFFFFFFu, mxa, 2));
        mxb = fmaxf(mxb, __shfl_xor_sync(0xFFFFFFFFu, mxb, 1));
        mxb = fmaxf(mxb, __shfl_xor_sync(0xFFFFFFFFu, mxb, 2));

        float mna = fmaxf(mrow0, mxa), mnb = fmaxf(mrow1, mxb);
        float ala = __expf(mrow0 - mna), alb = __expf(mrow1 - mnb);
        float suma = 0.f, sumb = 0.f;
#pragma unroll
        for (int nt = 0; nt < 8; nt++) {
            s[nt][0] = __expf(s[nt][0] - mna); suma += s[nt][0];
            s[nt][1] = __expf(s[nt][1] - mna); suma += s[nt][1];
            s[nt][2] = __expf(s[nt][2] - mnb); sumb += s[nt][2];
            s[nt][3] = __expf(s[nt][3] - mnb); sumb += s[nt][3];
        }
        suma += __shfl_xor_sync(0xFFFFFFFFu, suma, 1);
        suma += __shfl_xor_sync(0xFFFFFFFFu, suma, 2);
        sumb += __shfl_xor_sync(0xFFFFFFFFu, sumb, 1);
        sumb += __shfl_xor_sync(0xFFFFFFFFu, sumb, 2);
        lrow0 = lrow0 * ala + suma; mrow0 = mna;
        lrow1 = lrow1 * alb + sumb; mrow1 = mnb;

#pragma unroll
        for (int nt = 0; nt < 8; nt++) {
            o[nt][0] *= ala; o[nt][1] *= ala;
            o[nt][2] *= alb; o[nt][3] *= alb;
        }

        // ---- O += P V (2-pass: (Ph + Pl) Vh; P frags from S regs) ----
#pragma unroll
        for (int ks2 = 0; ks2 < 4; ks2++) {
            const float* sa  = s[2*ks2];
            const float* sb2 = s[2*ks2 + 1];
            uint32_t phi[4], plo[4];
            {
                __half2 h0 = __floats2half2_rn(sa[0], sa[1]);
                __half2 h1 = __floats2half2_rn(sa[2], sa[3]);
                __half2 h2 = __floats2half2_rn(sb2[0], sb2[1]);
                __half2 h3 = __floats2half2_rn(sb2[2], sb2[3]);
                phi[0] = *reinterpret_cast<uint32_t*>(&h0);
                phi[1] = *reinterpret_cast<uint32_t*>(&h1);
                phi[2] = *reinterpret_cast<uint32_t*>(&h2);
                phi[3] = *reinterpret_cast<uint32_t*>(&h3);
                plo[0] = packh2(sa[0]  - __half2float(h0.x), sa[1]  - __half2float(h0.y));
                plo[1] = packh2(sa[2]  - __half2float(h1.x), sa[3]  - __half2float(h1.y));
                plo[2] = packh2(sb2[0] - __half2float(h2.x), sb2[1] - __half2float(h2.y));
                plo[3] = packh2(sb2[2] - __half2float(h3.x), sb2[3] - __half2float(h3.y));
            }
            uint32_t vh[8][2];
#pragma unroll
            for (int p = 0; p < 4; p++) {
                uint32_t off = (uint32_t)(ks2 * 16 + b_kh * 8 + b_rr) * AROWB
                             + (p * 16 + b_nt * 8) * 2;
                ldsm_x4t(vh[p*2][0], vh[p*2][1], vh[p*2+1][0], vh[p*2+1][1], aVh + off);
            }
#pragma unroll
            for (int nt = 0; nt < 8; nt++) {
                mma4(o[nt], phi, vh[nt]);
                mma4(o[nt], plo, vh[nt]);
            }
        }
        __syncthreads();
    }

    // ---- epilogue: normalize, split to hi/lo, store ----
    const float inv0 = 1.0f / lrow0;
    const float inv1 = 1.0f / lrow1;
    const size_t rowa = (size_t)(b * LL + i0 + r0 + gid) * DD + h * HD;
    const size_t rowb = rowa + (size_t)8 * DD;
#pragma unroll
    for (int nt = 0; nt < 8; nt++) {
        int col = nt * 8 + 2 * tig;
        float v0 = o[nt][0] * inv0, v1 = o[nt][1] * inv0;
        float v2 = o[nt][2] * inv1, v3 = o[nt][3] * inv1;
        __half2 ha = __floats2half2_rn(v0, v1);
        __half2 hb = __floats2half2_rn(v2, v3);
        __half2 la = __floats2half2_rn(v0 - __half2float(ha.x), v1 - __half2float(ha.y));
        __half2 lb = __floats2half2_rn(v2 - __half2float(hb.x), v3 - __half2float(hb.y));
        *reinterpret_cast<__half2*>(Ohi + rowa + col) = ha;
        *reinterpret_cast<__half2*>(Olo + rowa + col) = la;
        *reinterpret_cast<__half2*>(Ohi + rowb + col) = hb;
        *reinterpret_cast<__half2*>(Olo + rowb + col) = lb;
    }
}

// ---------------------------------------------------------------------------
extern "C" void kernel_launch(void* const* d_in, const int* in_sizes, int n_in,
                              void* d_out, int out_size) {
    const float* x  = (const float*)d_in[0];
    const float* WQ = (const float*)d_in[1];
    const float* bQ = (const float*)d_in[2];
    const float* WK = (const float*)d_in[3];
    const float* bK = (const float*)d_in[4];
    const float* WV = (const float*)d_in[5];
    const float* bV = (const float*)d_in[6];
    const float* Wc = (const float*)d_in[7];
    float* out = (float*)d_out;

    cudaFuncSetAttribute(gemm_hmma, cudaFuncAttributeMaxDynamicSharedMemorySize, GEMM_SMEM);
    cudaFuncSetAttribute(attn_mma,  cudaFuncAttributeMaxDynamicSharedMemorySize, ATTN_SMEM);

    fp16 *xhi, *xlo, *whi, *qhi, *qlo, *khi, *vhi, *mhi, *mlo;
    cudaGetSymbolAddress((void**)&xhi, g_xhi);
    cudaGetSymbolAddress((void**)&xlo, g_xlo);
    cudaGetSymbolAddress((void**)&whi, g_whi);
    cudaGetSymbolAddress((void**)&qhi, g_qhi);
    cudaGetSymbolAddress((void**)&qlo, g_qlo);
    cudaGetSymbolAddress((void**)&khi, g_khi);
    cudaGetSymbolAddress((void**)&vhi, g_vhi);
    cudaGetSymbolAddress((void**)&mhi, g_mhi);
    cudaGetSymbolAddress((void**)&mlo, g_mlo);

    const int nx4 = MM * DD / 4;
    const int nw4 = DD * DD / 4;

    split_x<<<(nx4 + 255) / 256, 256>>>(x, xhi, xlo, nx4);
    dim3 gw((nw4 + 255) / 256, 4);
    split_w<<<gw, 256>>>(WQ, WK, WV, Wc, whi, nw4);

    GemmTask tq = {whi + 0*DD*DD, bQ, 0.125f, nullptr, qhi, qlo};
    GemmTask tk = {whi + 1*DD*DD, bK, 1.0f,   nullptr, khi, nullptr};
    GemmTask tv = {whi + 2*DD*DD, bV, 1.0f,   nullptr, vhi, nullptr};
    dim3 gqkv(DD / BN, MM / BM, 3);    // (16, 32, 3)
    gemm_hmma<<<gqkv, 256, GEMM_SMEM>>>(xhi, xlo, tq, tk, tv);

    dim3 ga(LL / 64, HH, BB);          // (32, 16, 2)
    attn_mma<<<ga, 128, ATTN_SMEM>>>(qhi, qlo, khi, vhi, mhi, mlo);

    GemmTask tc = {whi + 3*DD*DD, nullptr, 1.0f, out, nullptr, nullptr};
    dim3 go(DD / BN, MM / BM, 1);      // (16, 32, 1)
    gemm_hmma<<<go, 256, GEMM_SMEM>>>(mhi, mlo, tc, tc, tc);
}

// round 8
// speedup vs baseline: 7.4683x; 1.1656x over previous
#include <cuda_runtime.h>
#include <cuda_fp16.h>
#include <cstdint>

// Problem shape (fixed)
#define BB 2
#define LL 2048
#define DD 1024
#define HH 16
#define HD 64
#define MM (BB*LL)   // 4096

typedef __half fp16;

// ---------------------------------------------------------------------------
// Scratch (__device__ globals: allocation-free rule)
// ---------------------------------------------------------------------------
__device__ fp16 g_xhi[MM*DD], g_xlo[MM*DD];
__device__ fp16 g_whi[4*DD*DD];
__device__ fp16 g_qhi[MM*DD];
__device__ fp16 g_khi[MM*DD];
__device__ fp16 g_vhi[MM*DD];
__device__ fp16 g_mhi[MM*DD], g_mlo[MM*DD];

// ---------------------------------------------------------------------------
// Helpers (portable ISA only)
// ---------------------------------------------------------------------------
__device__ __forceinline__ uint32_t smem_u32(const void* p) {
    uint32_t a;
    asm("{ .reg .u64 t; cvta.to.shared.u64 t, %1; cvt.u32.u64 %0, t; }" : "=r"(a) : "l"(p));
    return a;
}
__device__ __forceinline__ void ldsm_x4(uint32_t& r0, uint32_t& r1, uint32_t& r2, uint32_t& r3,
                                        uint32_t addr) {
    asm volatile("ldmatrix.sync.aligned.m8n8.x4.shared.b16 {%0,%1,%2,%3}, [%4];"
                 : "=r"(r0), "=r"(r1), "=r"(r2), "=r"(r3) : "r"(addr));
}
__device__ __forceinline__ void ldsm_x4t(uint32_t& r0, uint32_t& r1, uint32_t& r2, uint32_t& r3,
                                         uint32_t addr) {
    asm volatile("ldmatrix.sync.aligned.m8n8.x4.trans.shared.b16 {%0,%1,%2,%3}, [%4];"
                 : "=r"(r0), "=r"(r1), "=r"(r2), "=r"(r3) : "r"(addr));
}
__device__ __forceinline__ void mma4(float* c, const uint32_t* a, const uint32_t* b) {
    asm volatile("mma.sync.aligned.m16n8k16.row.col.f32.f16.f16.f32 "
                 "{%0,%1,%2,%3}, {%4,%5,%6,%7}, {%8,%9}, {%0,%1,%2,%3};"
                 : "+f"(c[0]), "+f"(c[1]), "+f"(c[2]), "+f"(c[3])
                 : "r"(a[0]), "r"(a[1]), "r"(a[2]), "r"(a[3]), "r"(b[0]), "r"(b[1]));
}
__device__ __forceinline__ void cp16(uint32_t dst, const void* src) {
    asm volatile("cp.async.cg.shared.global [%0], [%1], 16;" :: "r"(dst), "l"(src));
}
#define CP_COMMIT() asm volatile("cp.async.commit_group;" ::: "memory")
#define CP_WAIT(N)  asm volatile("cp.async.wait_group %0;" :: "n"(N) : "memory")

__device__ __forceinline__ uint32_t packh2(float a, float b) {
    __half2 t = __floats2half2_rn(a, b);
    return *reinterpret_cast<uint32_t*>(&t);
}

// ---------------------------------------------------------------------------
// fp32 -> fp16 splits
// ---------------------------------------------------------------------------
__global__ __launch_bounds__(256) void split_x(const float* __restrict__ in,
                                               fp16* __restrict__ hi,
                                               fp16* __restrict__ lo, int n4) {
    int i = blockIdx.x * 256 + threadIdx.x;
    if (i >= n4) return;
    float4 v = reinterpret_cast<const float4*>(in)[i];
    fp16 h0 = __float2half_rn(v.x), h1 = __float2half_rn(v.y);
    fp16 h2 = __float2half_rn(v.z), h3 = __float2half_rn(v.w);
    __half2* H = reinterpret_cast<__half2*>(hi);
    __half2* L = reinterpret_cast<__half2*>(lo);
    H[2*i]   = __halves2half2(h0, h1);
    H[2*i+1] = __halves2half2(h2, h3);
    L[2*i]   = __floats2half2_rn(v.x - __half2float(h0), v.y - __half2float(h1));
    L[2*i+1] = __floats2half2_rn(v.z - __half2float(h2), v.w - __half2float(h3));
}

// 4 weight matrices, rounded fp16 hi only.
__global__ __launch_bounds__(256) void split_w(const float* __restrict__ w0,
                                               const float* __restrict__ w1,
                                               const float* __restrict__ w2,
                                               const float* __restrict__ w3,
                                               fp16* __restrict__ hi, int n4) {
    int i = blockIdx.x * 256 + threadIdx.x;
    if (i >= n4) return;
    int z = blockIdx.y;
    const float* src = z == 0 ? w0 : z == 1 ? w1 : z == 2 ? w2 : w3;
    float4 v = reinterpret_cast<const float4*>(src)[i];
    __half2* H = reinterpret_cast<__half2*>(hi + (size_t)z * DD * DD);
    H[2*i]   = __floats2half2_rn(v.x, v.y);
    H[2*i+1] = __floats2half2_rn(v.z, v.w);
}

// ---------------------------------------------------------------------------
// HMMA GEMM, 3-stage cp.async pipeline, multi-task via blockIdx.z.
// C = (Ahi [+ Alo if p2]) @ Whi^T + bias.
// Epilogue fp32 OR scaled fp16 (hi, optional lo).
// CTA 128x64, BK=32, 256 threads (8 warps, 4x2, 32x32 each).
// ---------------------------------------------------------------------------
#define GK 1024
#define BM 128
#define BN 64
#define BK 32
#define SZ_A (BM*40*2)                // 10240 B (row stride 80 B)
#define SZ_W (BN*40*2)                // 5120 B
#define STG  (2*SZ_A + SZ_W)          // 25600 B per stage
#define NSTG 3
#define GEMM_SMEM (NSTG*STG)          // 76800 B

struct GemmTask {
    const fp16* Whi;
    const float* bias; float scale;
    float* Cf; fp16* Chi; fp16* Clo;
    int p2;                            // 1 = include Alo correction pass
};

__global__ __launch_bounds__(256) void gemm_hmma(const fp16* __restrict__ Ahi,
                                                 const fp16* __restrict__ Alo,
                                                 GemmTask t0, GemmTask t1, GemmTask t2) {
    extern __shared__ __align__(16) char dsm[];
    const GemmTask tk = blockIdx.z == 0 ? t0 : blockIdx.z == 1 ? t1 : t2;
    const fp16* __restrict__ Whi = tk.Whi;
    const bool p2 = tk.p2 != 0;

    const uint32_t sb0 = smem_u32(dsm);
    const int tid  = threadIdx.x;
    const int wid  = tid >> 5;
    const int lane = tid & 31;
    const int wm   = wid >> 1;
    const int wn   = wid & 1;
    const int bm   = blockIdx.y * BM;
    const int bn   = blockIdx.x * BN;

    float acc[2][4][4];
#pragma unroll
    for (int i = 0; i < 2; i++)
#pragma unroll
        for (int j = 0; j < 4; j++)
#pragma unroll
            for (int k = 0; k < 4; k++) acc[i][j][k] = 0.f;

    auto issue = [&](int stg, int k0) {
        uint32_t base = sb0 + stg * STG;
#pragma unroll
        for (int i = 0; i < 2; i++) {
            int c = tid + 256 * i;
            int r = c >> 2, q = c & 3;
            const size_t off = (size_t)(bm + r) * GK + k0 + q * 8;
            cp16(base + r * 80 + q * 16, Ahi + off);
            if (p2)
                cp16(base + SZ_A + r * 80 + q * 16, Alo + off);
        }
        {
            int r = tid >> 2, q = tid & 3;
            const size_t off = (size_t)(bn + r) * GK + k0 + q * 8;
            cp16(base + 2*SZ_A + r * 80 + q * 16, Whi + off);
        }
        CP_COMMIT();
    };

    const int a_r    = lane & 15;
    const int a_half = lane >> 4;
    const int b_rr   = lane & 7;
    const int b_nt   = (lane >> 4) & 1;
    const int b_kh   = (lane >> 3) & 1;

    const int NIT = GK / BK;     // 32
    issue(0, 0);
    issue(1, BK);
    for (int it = 0; it < NIT; it++) {
        if (it + 2 < NIT) { issue((it + 2) % NSTG, (it + 2) * BK); CP_WAIT(2); }
        else if (it + 1 < NIT) { CP_WAIT(1); }
        else { CP_WAIT(0); }
        __syncthreads();

        const uint32_t base = sb0 + (it % NSTG) * STG;
        const uint32_t aAhi = base;
        const uint32_t aAlo = base + SZ_A;
        const uint32_t aWhi = base + 2*SZ_A;

#pragma unroll
        for (int ks = 0; ks < 2; ks++) {
            const int kk = ks * 16;
            uint32_t ah[2][4], al[2][4];
#pragma unroll
            for (int mt = 0; mt < 2; mt++) {
                uint32_t off = (uint32_t)(wm * 32 + mt * 16 + a_r) * 80 + (kk + a_half * 8) * 2;
                ldsm_x4(ah[mt][0], ah[mt][1], ah[mt][2], ah[mt][3], aAhi + off);
                if (p2)
                    ldsm_x4(al[mt][0], al[mt][1], al[mt][2], al[mt][3], aAlo + off);
            }
            uint32_t bh[4][2];
#pragma unroll
            for (int p = 0; p < 2; p++) {
                uint32_t off = (uint32_t)(wn * 32 + p * 16 + b_nt * 8 + b_rr) * 80
                             + (kk + b_kh * 8) * 2;
                ldsm_x4(bh[p*2][0], bh[p*2][1], bh[p*2+1][0], bh[p*2+1][1], aWhi + off);
            }
#pragma unroll
            for (int mt = 0; mt < 2; mt++)
#pragma unroll
                for (int nt = 0; nt < 4; nt++)
                    mma4(acc[mt][nt], ah[mt], bh[nt]);
            if (p2) {
#pragma unroll
                for (int mt = 0; mt < 2; mt++)
#pragma unroll
                    for (int nt = 0; nt < 4; nt++)
                        mma4(acc[mt][nt], al[mt], bh[nt]);
            }
        }
        __syncthreads();
    }

    // ---- epilogue ----
    const int gid = lane >> 2;
    const int tig = lane & 3;
#pragma unroll
    for (int mt = 0; mt < 2; mt++) {
#pragma unroll
        for (int nt = 0; nt < 4; nt++) {
            int row = bm + wm * 32 + mt * 16 + gid;
            int col = bn + wn * 32 + nt * 8 + 2 * tig;
            float b0 = tk.bias ? tk.bias[col]     : 0.f;
            float b1 = tk.bias ? tk.bias[col + 1] : 0.f;
            float v00 = (acc[mt][nt][0] + b0) * tk.scale;
            float v01 = (acc[mt][nt][1] + b1) * tk.scale;
            float v10 = (acc[mt][nt][2] + b0) * tk.scale;
            float v11 = (acc[mt][nt][3] + b1) * tk.scale;
            if (tk.Cf) {
                *reinterpret_cast<float2*>(tk.Cf + (size_t)row * GK + col)       = make_float2(v00, v01);
                *reinterpret_cast<float2*>(tk.Cf + (size_t)(row + 8) * GK + col) = make_float2(v10, v11);
            } else {
                __half2 h0 = __floats2half2_rn(v00, v01);
                __half2 h1 = __floats2half2_rn(v10, v11);
                *reinterpret_cast<__half2*>(tk.Chi + (size_t)row * GK + col)       = h0;
                *reinterpret_cast<__half2*>(tk.Chi + (size_t)(row + 8) * GK + col) = h1;
                if (tk.Clo) {
                    __half2 l0 = __floats2half2_rn(v00 - __half2float(h0.x),
                                                   v01 - __half2float(h0.y));
                    __half2 l1 = __floats2half2_rn(v10 - __half2float(h1.x),
                                                   v11 - __half2float(h1.y));
                    *reinterpret_cast<__half2*>(tk.Clo + (size_t)row * GK + col)       = l0;
                    *reinterpret_cast<__half2*>(tk.Clo + (size_t)(row + 8) * GK + col) = l1;
                }
            }
        }
    }
}

// ---------------------------------------------------------------------------
// HMMA flash attention, double-buffered KV.
// S = Qhi Khi^T (1-pass; Q,K errors damped by softmax);
// O += (Phi+Plo) Vhi (2-pass; direct path keeps its correction).
// Block = 128 threads (4 warps), 64 query rows, KV tiles of 64.
// smem/stage: Kh, Vh -> 36 KB total. Reversed i0 order.
// ---------------------------------------------------------------------------
#define AROWB 144                       // bytes per 64-col fp16 row (72 elems)
#define ATILE_B (64*AROWB)              // 9216 B per array
#define ASTG_B (2*ATILE_B)              // Kh,Vh per stage = 18432 B
#define ATTN_SMEM (2*ASTG_B)            // 36864 B

__global__ __launch_bounds__(128, 4) void attn_mma(const fp16* __restrict__ Qhi,
                                                   const fp16* __restrict__ Khi,
                                                   const fp16* __restrict__ Vhi,
                                                   fp16* __restrict__ Ohi,
                                                   fp16* __restrict__ Olo) {
    extern __shared__ __align__(16) char asm_[];
    const uint32_t sb = smem_u32(asm_);

    const int i0 = (int)(gridDim.x - 1 - blockIdx.x) * 64;   // reversed order
    const int h  = blockIdx.y;
    const int b  = blockIdx.z;
    const int tid  = threadIdx.x;
    const int w    = tid >> 5;
    const int lane = tid & 31;
    const int gid  = lane >> 2;
    const int tig  = lane & 3;
    const int r0   = w * 16;

    const size_t baseq = ((size_t)(b * LL + i0)) * DD + h * HD;

    auto issueKV = [&](uint32_t stg, int j0) {
        const size_t basekv = ((size_t)(b * LL + j0)) * DD + h * HD;
#pragma unroll
        for (int i = 0; i < 4; i++) {
            int c = tid + 128 * i;
            int r = c >> 3, q = c & 7;
            const size_t off = basekv + (size_t)r * DD + q * 8;
            const uint32_t d = stg + r * AROWB + q * 16;
            cp16(d,           Khi + off);
            cp16(d + ATILE_B, Vhi + off);
        }
        CP_COMMIT();
    };

    // ---- stage Q through stage-1 K buffer; prefetch KV tile 0 into stage 0 ----
#pragma unroll
    for (int i = 0; i < 4; i++) {
        int c = tid + 128 * i;
        int r = c >> 3, q = c & 7;
        const size_t off = baseq + (size_t)r * DD + q * 8;
        cp16(sb + ASTG_B + r * AROWB + q * 16, Qhi + off);
    }
    CP_COMMIT();
    issueKV(sb, 0);
    CP_WAIT(1);               // Q ready (KV0 may still be in flight)
    __syncthreads();

    const int a_r = lane & 15, a_h = lane >> 4;
    uint32_t qh[4][4];
#pragma unroll
    for (int ks = 0; ks < 4; ks++) {
        uint32_t off = (uint32_t)(r0 + a_r) * AROWB + (ks * 16 + a_h * 8) * 2;
        ldsm_x4(qh[ks][0], qh[ks][1], qh[ks][2], qh[ks][3], sb + ASTG_B + off);
    }
    __syncthreads();          // Q buffer free for KV reuse

    float o[8][4];
#pragma unroll
    for (int nt = 0; nt < 8; nt++)
#pragma unroll
        for (int k = 0; k < 4; k++) o[nt][k] = 0.f;
    float mrow0 = -1e30f, mrow1 = -1e30f, lrow0 = 0.f, lrow1 = 0.f;

    const int b_rr = lane & 7;
    const int b_nt = (lane >> 4) & 1;
    const int b_kh = (lane >> 3) & 1;

    const int T = i0 / 64 + 1;
    for (int t = 0; t < T; t++) {
        if (t + 1 < T) { issueKV(sb + ((t + 1) & 1) * ASTG_B, (t + 1) * 64); CP_WAIT(1); }
        else           { CP_WAIT(0); }
        __syncthreads();

        const uint32_t aKh = sb + (t & 1) * ASTG_B;
        const uint32_t aVh = aKh + ATILE_B;

        // ---- S = Q K^T (1-pass) ----
        float s[8][4];
#pragma unroll
        for (int nt = 0; nt < 8; nt++)
#pragma unroll
            for (int k = 0; k < 4; k++) s[nt][k] = 0.f;

#pragma unroll
        for (int ks = 0; ks < 4; ks++) {
            const int kk = ks * 16;
            uint32_t kh[8][2];
#pragma unroll
            for (int p = 0; p < 4; p++) {
                uint32_t off = (uint32_t)(p * 16 + b_nt * 8 + b_rr) * AROWB + (kk + b_kh * 8) * 2;
                ldsm_x4(kh[p*2][0], kh[p*2][1], kh[p*2+1][0], kh[p*2+1][1], aKh + off);
            }
#pragma unroll
            for (int nt = 0; nt < 8; nt++)
                mma4(s[nt], qh[ks], kh[nt]);
        }

        // ---- causal mask (diagonal tile only; reversed order: t==T-1) ----
        if (t == T - 1) {
#pragma unroll
            for (int nt = 0; nt < 8; nt++) {
                int col0 = nt * 8 + 2 * tig;
                int rowa = r0 + gid, rowb = rowa + 8;
                if (col0     > rowa) s[nt][0] = -1e30f;
                if (col0 + 1 > rowa) s[nt][1] = -1e30f;
                if (col0     > rowb) s[nt][2] = -1e30f;
                if (col0 + 1 > rowb) s[nt][3] = -1e30f;
            }
        }

        // ---- online softmax (quad reduction) ----
        float mxa = -1e30f, mxb = -1e30f;
#pragma unroll
        for (int nt = 0; nt < 8; nt++) {
            mxa = fmaxf(mxa, fmaxf(s[nt][0], s[nt][1]));
            mxb = fmaxf(mxb, fmaxf(s[nt][2], s[nt][3]));
        }
        mxa = fmaxf(mxa, __shfl_xor_sync(0xFFFFFFFFu, mxa, 1));
        mxa = fmaxf(mxa, __shfl_xor_sync(0xFFFFFFFFu, mxa, 2));
        mxb = fmaxf(mxb, __shfl_xor_sync(0xFFFFFFFFu, mxb, 1));
        mxb = fmaxf(mxb, __shfl_xor_sync(0xFFFFFFFFu, mxb, 2));

        float mna = fmaxf(mrow0, mxa), mnb = fmaxf(mrow1, mxb);
        float ala = __expf(mrow0 - mna), alb = __expf(mrow1 - mnb);
        float suma = 0.f, sumb = 0.f;
#pragma unroll
        for (int nt = 0; nt < 8; nt++) {
            s[nt][0] = __expf(s[nt][0] - mna); suma += s[nt][0];
            s[nt][1] = __expf(s[nt][1] - mna); suma += s[nt][1];
            s[nt][2] = __expf(s[nt][2] - mnb); sumb += s[nt][2];
            s[nt][3] = __expf(s[nt][3] - mnb); sumb += s[nt][3];
        }
        suma += __shfl_xor_sync(0xFFFFFFFFu, suma, 1);
        suma += __shfl_xor_sync(0xFFFFFFFFu, suma, 2);
        sumb += __shfl_xor_sync(0xFFFFFFFFu, sumb, 1);
        sumb += __shfl_xor_sync(0xFFFFFFFFu, sumb, 2);
        lrow0 = lrow0 * ala + suma; mrow0 = mna;
        lrow1 = lrow1 * alb + sumb; mrow1 = mnb;

#pragma unroll
        for (int nt = 0; nt < 8; nt++) {
            o[nt][0] *= ala; o[nt][1] *= ala;
            o[nt][2] *= alb; o[nt][3] *= alb;
        }

        // ---- O += P V (2-pass: (Ph + Pl) Vh; P frags from S regs) ----
#pragma unroll
        for (int ks2 = 0; ks2 < 4; ks2++) {
            const float* sa  = s[2*ks2];
            const float* sb2 = s[2*ks2 + 1];
            uint32_t phi[4], plo[4];
            {
                __half2 h0 = __floats2half2_rn(sa[0], sa[1]);
                __half2 h1 = __floats2half2_rn(sa[2], sa[3]);
                __half2 h2 = __floats2half2_rn(sb2[0], sb2[1]);
                __half2 h3 = __floats2half2_rn(sb2[2], sb2[3]);
                phi[0] = *reinterpret_cast<uint32_t*>(&h0);
                phi[1] = *reinterpret_cast<uint32_t*>(&h1);
                phi[2] = *reinterpret_cast<uint32_t*>(&h2);
                phi[3] = *reinterpret_cast<uint32_t*>(&h3);
                plo[0] = packh2(sa[0]  - __half2float(h0.x), sa[1]  - __half2float(h0.y));
                plo[1] = packh2(sa[2]  - __half2float(h1.x), sa[3]  - __half2float(h1.y));
                plo[2] = packh2(sb2[0] - __half2float(h2.x), sb2[1] - __half2float(h2.y));
                plo[3] = packh2(sb2[2] - __half2float(h3.x), sb2[3] - __half2float(h3.y));
            }
            uint32_t vh[8][2];
#pragma unroll
            for (int p = 0; p < 4; p++) {
                uint32_t off = (uint32_t)(ks2 * 16 + b_kh * 8 + b_rr) * AROWB
                             + (p * 16 + b_nt * 8) * 2;
                ldsm_x4t(vh[p*2][0], vh[p*2][1], vh[p*2+1][0], vh[p*2+1][1], aVh + off);
            }
#pragma unroll
            for (int nt = 0; nt < 8; nt++) {
                mma4(o[nt], phi, vh[nt]);
                mma4(o[nt], plo, vh[nt]);
            }
        }
        __syncthreads();
    }

    // ---- epilogue: normalize, split to hi/lo, store ----
    const float inv0 = 1.0f / lrow0;
    const float inv1 = 1.0f / lrow1;
    const size_t rowa = (size_t)(b * LL + i0 + r0 + gid) * DD + h * HD;
    const size_t rowb = rowa + (size_t)8 * DD;
#pragma unroll
    for (int nt = 0; nt < 8; nt++) {
        int col = nt * 8 + 2 * tig;
        float v0 = o[nt][0] * inv0, v1 = o[nt][1] * inv0;
        float v2 = o[nt][2] * inv1, v3 = o[nt][3] * inv1;
        __half2 ha = __floats2half2_rn(v0, v1);
        __half2 hb = __floats2half2_rn(v2, v3);
        __half2 la = __floats2half2_rn(v0 - __half2float(ha.x), v1 - __half2float(ha.y));
        __half2 lb = __floats2half2_rn(v2 - __half2float(hb.x), v3 - __half2float(hb.y));
        *reinterpret_cast<__half2*>(Ohi + rowa + col) = ha;
        *reinterpret_cast<__half2*>(Olo + rowa + col) = la;
        *reinterpret_cast<__half2*>(Ohi + rowb + col) = hb;
        *reinterpret_cast<__half2*>(Olo + rowb + col) = lb;
    }
}

// ---------------------------------------------------------------------------
extern "C" void kernel_launch(void* const* d_in, const int* in_sizes, int n_in,
                              void* d_out, int out_size) {
    const float* x  = (const float*)d_in[0];
    const float* WQ = (const float*)d_in[1];
    const float* bQ = (const float*)d_in[2];
    const float* WK = (const float*)d_in[3];
    const float* bK = (const float*)d_in[4];
    const float* WV = (const float*)d_in[5];
    const float* bV = (const float*)d_in[6];
    const float* Wc = (const float*)d_in[7];
    float* out = (float*)d_out;

    cudaFuncSetAttribute(gemm_hmma, cudaFuncAttributeMaxDynamicSharedMemorySize, GEMM_SMEM);
    cudaFuncSetAttribute(attn_mma,  cudaFuncAttributeMaxDynamicSharedMemorySize, ATTN_SMEM);

    fp16 *xhi, *xlo, *whi, *qhi, *khi, *vhi, *mhi, *mlo;
    cudaGetSymbolAddress((void**)&xhi, g_xhi);
    cudaGetSymbolAddress((void**)&xlo, g_xlo);
    cudaGetSymbolAddress((void**)&whi, g_whi);
    cudaGetSymbolAddress((void**)&qhi, g_qhi);
    cudaGetSymbolAddress((void**)&khi, g_khi);
    cudaGetSymbolAddress((void**)&vhi, g_vhi);
    cudaGetSymbolAddress((void**)&mhi, g_mhi);
    cudaGetSymbolAddress((void**)&mlo, g_mlo);

    const int nx4 = MM * DD / 4;
    const int nw4 = DD * DD / 4;

    split_x<<<(nx4 + 255) / 256, 256>>>(x, xhi, xlo, nx4);
    dim3 gw((nw4 + 255) / 256, 4);
    split_w<<<gw, 256>>>(WQ, WK, WV, Wc, whi, nw4);

    // Q,K: 1-pass (softmax-damped). V: 2-pass (direct path).
    GemmTask tq = {whi + 0*DD*DD, bQ, 0.125f, nullptr, qhi, nullptr, 0};
    GemmTask tk = {whi + 1*DD*DD, bK, 1.0f,   nullptr, khi, nullptr, 0};
    GemmTask tv = {whi + 2*DD*DD, bV, 1.0f,   nullptr, vhi, nullptr, 1};
    dim3 gqkv(DD / BN, MM / BM, 3);    // (16, 32, 3)
    gemm_hmma<<<gqkv, 256, GEMM_SMEM>>>(xhi, xlo, tq, tk, tv);

    dim3 ga(LL / 64, HH, BB);          // (32, 16, 2)
    attn_mma<<<ga, 128, ATTN_SMEM>>>(qhi, khi, vhi, mhi, mlo);

    // Final channel mix: 2-pass (direct path), fp32 out.
    GemmTask tc = {whi + 3*DD*DD, nullptr, 1.0f, out, nullptr, nullptr, 1};
    dim3 go(DD / BN, MM / BM, 1);      // (16, 32, 1)
    gemm_hmma<<<go, 256, GEMM_SMEM>>>(mhi, mlo, tc, tc, tc);
}

// round 9
// speedup vs baseline: 10.0402x; 1.3444x over previous
#include <cuda_runtime.h>
#include <cuda_fp16.h>
#include <cstdint>

// Problem shape (fixed)
#define BB 2
#define LL 2048
#define DD 1024
#define HH 16
#define HD 64
#define MM (BB*LL)   // 4096

typedef __half fp16;

// ---------------------------------------------------------------------------
// Scratch (__device__ globals: allocation-free rule)
// ---------------------------------------------------------------------------
__device__ fp16 g_xhi[MM*DD];
__device__ fp16 g_whi[4*DD*DD];
__device__ fp16 g_qhi[MM*DD];
__device__ fp16 g_khi[MM*DD];
__device__ fp16 g_vhi[MM*DD];
__device__ fp16 g_mhi[MM*DD];

// ---------------------------------------------------------------------------
// Helpers (portable ISA only)
// ---------------------------------------------------------------------------
__device__ __forceinline__ uint32_t smem_u32(const void* p) {
    uint32_t a;
    asm("{ .reg .u64 t; cvta.to.shared.u64 t, %1; cvt.u32.u64 %0, t; }" : "=r"(a) : "l"(p));
    return a;
}
__device__ __forceinline__ void ldsm_x4(uint32_t& r0, uint32_t& r1, uint32_t& r2, uint32_t& r3,
                                        uint32_t addr) {
    asm volatile("ldmatrix.sync.aligned.m8n8.x4.shared.b16 {%0,%1,%2,%3}, [%4];"
                 : "=r"(r0), "=r"(r1), "=r"(r2), "=r"(r3) : "r"(addr));
}
__device__ __forceinline__ void ldsm_x4t(uint32_t& r0, uint32_t& r1, uint32_t& r2, uint32_t& r3,
                                         uint32_t addr) {
    asm volatile("ldmatrix.sync.aligned.m8n8.x4.trans.shared.b16 {%0,%1,%2,%3}, [%4];"
                 : "=r"(r0), "=r"(r1), "=r"(r2), "=r"(r3) : "r"(addr));
}
__device__ __forceinline__ void mma4(float* c, const uint32_t* a, const uint32_t* b) {
    asm volatile("mma.sync.aligned.m16n8k16.row.col.f32.f16.f16.f32 "
                 "{%0,%1,%2,%3}, {%4,%5,%6,%7}, {%8,%9}, {%0,%1,%2,%3};"
                 : "+f"(c[0]), "+f"(c[1]), "+f"(c[2]), "+f"(c[3])
                 : "r"(a[0]), "r"(a[1]), "r"(a[2]), "r"(a[3]), "r"(b[0]), "r"(b[1]));
}
__device__ __forceinline__ void cp16(uint32_t dst, const void* src) {
    asm volatile("cp.async.cg.shared.global [%0], [%1], 16;" :: "r"(dst), "l"(src));
}
#define CP_COMMIT() asm volatile("cp.async.commit_group;" ::: "memory")
#define CP_WAIT(N)  asm volatile("cp.async.wait_group %0;" :: "n"(N) : "memory")

__device__ __forceinline__ uint32_t packh2(float a, float b) {
    __half2 t = __floats2half2_rn(a, b);
    return *reinterpret_cast<uint32_t*>(&t);
}

// ---------------------------------------------------------------------------
// fp32 -> rounded fp16 conversions
// ---------------------------------------------------------------------------
__global__ __launch_bounds__(256) void split_x(const float* __restrict__ in,
                                               fp16* __restrict__ hi, int n4) {
    int i = blockIdx.x * 256 + threadIdx.x;
    if (i >= n4) return;
    float4 v = reinterpret_cast<const float4*>(in)[i];
    __half2* H = reinterpret_cast<__half2*>(hi);
    H[2*i]   = __floats2half2_rn(v.x, v.y);
    H[2*i+1] = __floats2half2_rn(v.z, v.w);
}

// 4 weight matrices, rounded fp16.
__global__ __launch_bounds__(256) void split_w(const float* __restrict__ w0,
                                               const float* __restrict__ w1,
                                               const float* __restrict__ w2,
                                               const float* __restrict__ w3,
                                               fp16* __restrict__ hi, int n4) {
    int i = blockIdx.x * 256 + threadIdx.x;
    if (i >= n4) return;
    int z = blockIdx.y;
    const float* src = z == 0 ? w0 : z == 1 ? w1 : z == 2 ? w2 : w3;
    float4 v = reinterpret_cast<const float4*>(src)[i];
    __half2* H = reinterpret_cast<__half2*>(hi + (size_t)z * DD * DD);
    H[2*i]   = __floats2half2_rn(v.x, v.y);
    H[2*i+1] = __floats2half2_rn(v.z, v.w);
}

// ---------------------------------------------------------------------------
// HMMA GEMM, single-pass fp16, 3-stage cp.async pipeline, multi-task blockIdx.z.
// C = Ahi @ Whi^T + bias.  Epilogue: fp32 OR scaled fp16.
// CTA 128x64, BK=32, 256 threads (8 warps, 4x2, 32x32 each).
// ---------------------------------------------------------------------------
#define GK 1024
#define BM 128
#define BN 64
#define BK 32
#define SZ_A (BM*40*2)                // 10240 B (row stride 80 B)
#define SZ_W (BN*40*2)                // 5120 B
#define STG  (SZ_A + SZ_W)            // 15360 B per stage
#define NSTG 3
#define GEMM_SMEM (NSTG*STG)          // 46080 B

struct GemmTask {
    const fp16* Whi;
    const float* bias; float scale;
    float* Cf; fp16* Chi;
};

__global__ __launch_bounds__(256) void gemm_hmma(const fp16* __restrict__ Ahi,
                                                 GemmTask t0, GemmTask t1, GemmTask t2) {
    extern __shared__ __align__(16) char dsm[];
    const GemmTask tk = blockIdx.z == 0 ? t0 : blockIdx.z == 1 ? t1 : t2;
    const fp16* __restrict__ Whi = tk.Whi;

    const uint32_t sb0 = smem_u32(dsm);
    const int tid  = threadIdx.x;
    const int wid  = tid >> 5;
    const int lane = tid & 31;
    const int wm   = wid >> 1;
    const int wn   = wid & 1;
    const int bm   = blockIdx.y * BM;
    const int bn   = blockIdx.x * BN;

    float acc[2][4][4];
#pragma unroll
    for (int i = 0; i < 2; i++)
#pragma unroll
        for (int j = 0; j < 4; j++)
#pragma unroll
            for (int k = 0; k < 4; k++) acc[i][j][k] = 0.f;

    auto issue = [&](int stg, int k0) {
        uint32_t base = sb0 + stg * STG;
#pragma unroll
        for (int i = 0; i < 2; i++) {
            int c = tid + 256 * i;
            int r = c >> 2, q = c & 3;
            cp16(base + r * 80 + q * 16, Ahi + (size_t)(bm + r) * GK + k0 + q * 8);
        }
        {
            int r = tid >> 2, q = tid & 3;
            cp16(base + SZ_A + r * 80 + q * 16, Whi + (size_t)(bn + r) * GK + k0 + q * 8);
        }
        CP_COMMIT();
    };

    const int a_r    = lane & 15;
    const int a_half = lane >> 4;
    const int b_rr   = lane & 7;
    const int b_nt   = (lane >> 4) & 1;
    const int b_kh   = (lane >> 3) & 1;

    const int NIT = GK / BK;     // 32
    issue(0, 0);
    issue(1, BK);
    for (int it = 0; it < NIT; it++) {
        if (it + 2 < NIT) { issue((it + 2) % NSTG, (it + 2) * BK); CP_WAIT(2); }
        else if (it + 1 < NIT) { CP_WAIT(1); }
        else { CP_WAIT(0); }
        __syncthreads();

        const uint32_t base = sb0 + (it % NSTG) * STG;
        const uint32_t aAhi = base;
        const uint32_t aWhi = base + SZ_A;

#pragma unroll
        for (int ks = 0; ks < 2; ks++) {
            const int kk = ks * 16;
            uint32_t ah[2][4];
#pragma unroll
            for (int mt = 0; mt < 2; mt++) {
                uint32_t off = (uint32_t)(wm * 32 + mt * 16 + a_r) * 80 + (kk + a_half * 8) * 2;
                ldsm_x4(ah[mt][0], ah[mt][1], ah[mt][2], ah[mt][3], aAhi + off);
            }
            uint32_t bh[4][2];
#pragma unroll
            for (int p = 0; p < 2; p++) {
                uint32_t off = (uint32_t)(wn * 32 + p * 16 + b_nt * 8 + b_rr) * 80
                             + (kk + b_kh * 8) * 2;
                ldsm_x4(bh[p*2][0], bh[p*2][1], bh[p*2+1][0], bh[p*2+1][1], aWhi + off);
            }
#pragma unroll
            for (int mt = 0; mt < 2; mt++)
#pragma unroll
                for (int nt = 0; nt < 4; nt++)
                    mma4(acc[mt][nt], ah[mt], bh[nt]);
        }
        __syncthreads();
    }

    // ---- epilogue ----
    const int gid = lane >> 2;
    const int tig = lane & 3;
#pragma unroll
    for (int mt = 0; mt < 2; mt++) {
#pragma unroll
        for (int nt = 0; nt < 4; nt++) {
            int row = bm + wm * 32 + mt * 16 + gid;
            int col = bn + wn * 32 + nt * 8 + 2 * tig;
            float b0 = tk.bias ? tk.bias[col]     : 0.f;
            float b1 = tk.bias ? tk.bias[col + 1] : 0.f;
            float v00 = (acc[mt][nt][0] + b0) * tk.scale;
            float v01 = (acc[mt][nt][1] + b1) * tk.scale;
            float v10 = (acc[mt][nt][2] + b0) * tk.scale;
            float v11 = (acc[mt][nt][3] + b1) * tk.scale;
            if (tk.Cf) {
                *reinterpret_cast<float2*>(tk.Cf + (size_t)row * GK + col)       = make_float2(v00, v01);
                *reinterpret_cast<float2*>(tk.Cf + (size_t)(row + 8) * GK + col) = make_float2(v10, v11);
            } else {
                *reinterpret_cast<__half2*>(tk.Chi + (size_t)row * GK + col) =
                    __floats2half2_rn(v00, v01);
                *reinterpret_cast<__half2*>(tk.Chi + (size_t)(row + 8) * GK + col) =
                    __floats2half2_rn(v10, v11);
            }
        }
    }
}

// ---------------------------------------------------------------------------
// HMMA flash attention, double-buffered KV.
// S = Qhi Khi^T (1-pass); O += (Phi+Plo) Vhi (2-pass; P split in registers).
// Block = 128 threads (4 warps), 64 query rows, KV tiles of 64.
// smem/stage: Kh, Vh -> 36 KB total. Reversed i0 order.
// ---------------------------------------------------------------------------
#define AROWB 144                       // bytes per 64-col fp16 row (72 elems)
#define ATILE_B (64*AROWB)              // 9216 B per array
#define ASTG_B (2*ATILE_B)              // Kh,Vh per stage = 18432 B
#define ATTN_SMEM (2*ASTG_B)            // 36864 B

__global__ __launch_bounds__(128, 4) void attn_mma(const fp16* __restrict__ Qhi,
                                                   const fp16* __restrict__ Khi,
                                                   const fp16* __restrict__ Vhi,
                                                   fp16* __restrict__ Ohi) {
    extern __shared__ __align__(16) char asm_[];
    const uint32_t sb = smem_u32(asm_);

    const int i0 = (int)(gridDim.x - 1 - blockIdx.x) * 64;   // reversed order
    const int h  = blockIdx.y;
    const int b  = blockIdx.z;
    const int tid  = threadIdx.x;
    const int w    = tid >> 5;
    const int lane = tid & 31;
    const int gid  = lane >> 2;
    const int tig  = lane & 3;
    const int r0   = w * 16;

    const size_t baseq = ((size_t)(b * LL + i0)) * DD + h * HD;

    auto issueKV = [&](uint32_t stg, int j0) {
        const size_t basekv = ((size_t)(b * LL + j0)) * DD + h * HD;
#pragma unroll
        for (int i = 0; i < 4; i++) {
            int c = tid + 128 * i;
            int r = c >> 3, q = c & 7;
            const size_t off = basekv + (size_t)r * DD + q * 8;
            const uint32_t d = stg + r * AROWB + q * 16;
            cp16(d,           Khi + off);
            cp16(d + ATILE_B, Vhi + off);
        }
        CP_COMMIT();
    };

    // ---- stage Q through stage-1 K buffer; prefetch KV tile 0 into stage 0 ----
#pragma unroll
    for (int i = 0; i < 4; i++) {
        int c = tid + 128 * i;
        int r = c >> 3, q = c & 7;
        cp16(sb + ASTG_B + r * AROWB + q * 16, Qhi + baseq + (size_t)r * DD + q * 8);
    }
    CP_COMMIT();
    issueKV(sb, 0);
    CP_WAIT(1);               // Q ready (KV0 may still be in flight)
    __syncthreads();

    const int a_r = lane & 15, a_h = lane >> 4;
    uint32_t qh[4][4];
#pragma unroll
    for (int ks = 0; ks < 4; ks++) {
        uint32_t off = (uint32_t)(r0 + a_r) * AROWB + (ks * 16 + a_h * 8) * 2;
        ldsm_x4(qh[ks][0], qh[ks][1], qh[ks][2], qh[ks][3], sb + ASTG_B + off);
    }
    __syncthreads();          // Q buffer free for KV reuse

    float o[8][4];
#pragma unroll
    for (int nt = 0; nt < 8; nt++)
#pragma unroll
        for (int k = 0; k < 4; k++) o[nt][k] = 0.f;
    float mrow0 = -1e30f, mrow1 = -1e30f, lrow0 = 0.f, lrow1 = 0.f;

    const int b_rr = lane & 7;
    const int b_nt = (lane >> 4) & 1;
    const int b_kh = (lane >> 3) & 1;

    const int T = i0 / 64 + 1;
    for (int t = 0; t < T; t++) {
        if (t + 1 < T) { issueKV(sb + ((t + 1) & 1) * ASTG_B, (t + 1) * 64); CP_WAIT(1); }
        else           { CP_WAIT(0); }
        __syncthreads();

        const uint32_t aKh = sb + (t & 1) * ASTG_B;
        const uint32_t aVh = aKh + ATILE_B;

        // ---- S = Q K^T (1-pass) ----
        float s[8][4];
#pragma unroll
        for (int nt = 0; nt < 8; nt++)
#pragma unroll
            for (int k = 0; k < 4; k++) s[nt][k] = 0.f;

#pragma unroll
        for (int ks = 0; ks < 4; ks++) {
            const int kk = ks * 16;
            uint32_t kh[8][2];
#pragma unroll
            for (int p = 0; p < 4; p++) {
                uint32_t off = (uint32_t)(p * 16 + b_nt * 8 + b_rr) * AROWB + (kk + b_kh * 8) * 2;
                ldsm_x4(kh[p*2][0], kh[p*2][1], kh[p*2+1][0], kh[p*2+1][1], aKh + off);
            }
#pragma unroll
            for (int nt = 0; nt < 8; nt++)
                mma4(s[nt], qh[ks], kh[nt]);
        }

        // ---- causal mask (diagonal tile only; reversed order: t==T-1) ----
        if (t == T - 1) {
#pragma unroll
            for (int nt = 0; nt < 8; nt++) {
                int col0 = nt * 8 + 2 * tig;
                int rowa = r0 + gid, rowb = rowa + 8;
                if (col0     > rowa) s[nt][0] = -1e30f;
                if (col0 + 1 > rowa) s[nt][1] = -1e30f;
                if (col0     > rowb) s[nt][2] = -1e30f;
                if (col0 + 1 > rowb) s[nt][3] = -1e30f;
            }
        }

        // ---- online softmax (quad reduction) ----
        float mxa = -1e30f, mxb = -1e30f;
#pragma unroll
        for (int nt = 0; nt < 8; nt++) {
            mxa = fmaxf(mxa, fmaxf(s[nt][0], s[nt][1]));
            mxb = fmaxf(mxb, fmaxf(s[nt][2], s[nt][3]));
        }
        mxa = fmaxf(mxa, __shfl_xor_sync(0xFFFFFFFFu, mxa, 1));
        mxa = fmaxf(mxa, __shfl_xor_sync(0xFFFFFFFFu, mxa, 2));
        mxb = fmaxf(mxb, __shfl_xor_sync(0xFFFFFFFFu, mxb, 1));
        mxb = fmaxf(mxb, __shfl_xor_sync(0xFFFFFFFFu, mxb, 2));

        float mna = fmaxf(mrow0, mxa), mnb = fmaxf(mrow1, mxb);
        float ala = __expf(mrow0 - mna), alb = __expf(mrow1 - mnb);
        float suma = 0.f, sumb = 0.f;
#pragma unroll
        for (int nt = 0; nt < 8; nt++) {
            s[nt][0] = __expf(s[nt][0] - mna); suma += s[nt][0];
            s[nt][1] = __expf(s[nt][1] - mna); suma += s[nt][1];
            s[nt][2] = __expf(s[nt][2] - mnb); sumb += s[nt][2];
            s[nt][3] = __expf(s[nt][3] - mnb); sumb += s[nt][3];
        }
        suma += __shfl_xor_sync(0xFFFFFFFFu, suma, 1);
        suma += __shfl_xor_sync(0xFFFFFFFFu, suma, 2);
        sumb += __shfl_xor_sync(0xFFFFFFFFu, sumb, 1);
        sumb += __shfl_xor_sync(0xFFFFFFFFu, sumb, 2);
        lrow0 = lrow0 * ala + suma; mrow0 = mna;
        lrow1 = lrow1 * alb + sumb; mrow1 = mnb;

#pragma unroll
        for (int nt = 0; nt < 8; nt++) {
            o[nt][0] *= ala; o[nt][1] *= ala;
            o[nt][2] *= alb; o[nt][3] *= alb;
        }

        // ---- O += P V (2-pass: (Ph + Pl) Vh; P frags from S regs) ----
#pragma unroll
        for (int ks2 = 0; ks2 < 4; ks2++) {
            const float* sa  = s[2*ks2];
            const float* sb2 = s[2*ks2 + 1];
            uint32_t phi[4], plo[4];
            {
                __half2 h0 = __floats2half2_rn(sa[0], sa[1]);
                __half2 h1 = __floats2half2_rn(sa[2], sa[3]);
                __half2 h2 = __floats2half2_rn(sb2[0], sb2[1]);
                __half2 h3 = __floats2half2_rn(sb2[2], sb2[3]);
                phi[0] = *reinterpret_cast<uint32_t*>(&h0);
                phi[1] = *reinterpret_cast<uint32_t*>(&h1);
                phi[2] = *reinterpret_cast<uint32_t*>(&h2);
                phi[3] = *reinterpret_cast<uint32_t*>(&h3);
                plo[0] = packh2(sa[0]  - __half2float(h0.x), sa[1]  - __half2float(h0.y));
                plo[1] = packh2(sa[2]  - __half2float(h1.x), sa[3]  - __half2float(h1.y));
                plo[2] = packh2(sb2[0] - __half2float(h2.x), sb2[1] - __half2float(h2.y));
                plo[3] = packh2(sb2[2] - __half2float(h3.x), sb2[3] - __half2float(h3.y));
            }
            uint32_t vh[8][2];
#pragma unroll
            for (int p = 0; p < 4; p++) {
                uint32_t off = (uint32_t)(ks2 * 16 + b_kh * 8 + b_rr) * AROWB
                             + (p * 16 + b_nt * 8) * 2;
                ldsm_x4t(vh[p*2][0], vh[p*2][1], vh[p*2+1][0], vh[p*2+1][1], aVh + off);
            }
#pragma unroll
            for (int nt = 0; nt < 8; nt++) {
                mma4(o[nt], phi, vh[nt]);
                mma4(o[nt], plo, vh[nt]);
            }
        }
        __syncthreads();
    }

    // ---- epilogue: normalize, round to fp16, store ----
    const float inv0 = 1.0f / lrow0;
    const float inv1 = 1.0f / lrow1;
    const size_t rowa = (size_t)(b * LL + i0 + r0 + gid) * DD + h * HD;
    const size_t rowb = rowa + (size_t)8 * DD;
#pragma unroll
    for (int nt = 0; nt < 8; nt++) {
        int col = nt * 8 + 2 * tig;
        *reinterpret_cast<__half2*>(Ohi + rowa + col) =
            __floats2half2_rn(o[nt][0] * inv0, o[nt][1] * inv0);
        *reinterpret_cast<__half2*>(Ohi + rowb + col) =
            __floats2half2_rn(o[nt][2] * inv1, o[nt][3] * inv1);
    }
}

// ---------------------------------------------------------------------------
extern "C" void kernel_launch(void* const* d_in, const int* in_sizes, int n_in,
                              void* d_out, int out_size) {
    const float* x  = (const float*)d_in[0];
    const float* WQ = (const float*)d_in[1];
    const float* bQ = (const float*)d_in[2];
    const float* WK = (const float*)d_in[3];
    const float* bK = (const float*)d_in[4];
    const float* WV = (const float*)d_in[5];
    const float* bV = (const float*)d_in[6];
    const float* Wc = (const float*)d_in[7];
    float* out = (float*)d_out;

    cudaFuncSetAttribute(gemm_hmma, cudaFuncAttributeMaxDynamicSharedMemorySize, GEMM_SMEM);
    cudaFuncSetAttribute(attn_mma,  cudaFuncAttributeMaxDynamicSharedMemorySize, ATTN_SMEM);

    fp16 *xhi, *whi, *qhi, *khi, *vhi, *mhi;
    cudaGetSymbolAddress((void**)&xhi, g_xhi);
    cudaGetSymbolAddress((void**)&whi, g_whi);
    cudaGetSymbolAddress((void**)&qhi, g_qhi);
    cudaGetSymbolAddress((void**)&khi, g_khi);
    cudaGetSymbolAddress((void**)&vhi, g_vhi);
    cudaGetSymbolAddress((void**)&mhi, g_mhi);

    const int nx4 = MM * DD / 4;
    const int nw4 = DD * DD / 4;

    split_x<<<(nx4 + 255) / 256, 256>>>(x, xhi, nx4);
    dim3 gw((nw4 + 255) / 256, 4);
    split_w<<<gw, 256>>>(WQ, WK, WV, Wc, whi, nw4);

    GemmTask tq = {whi + 0*DD*DD, bQ, 0.125f, nullptr, qhi};
    GemmTask tk = {whi + 1*DD*DD, bK, 1.0f,   nullptr, khi};
    GemmTask tv = {whi + 2*DD*DD, bV, 1.0f,   nullptr, vhi};
    dim3 gqkv(DD / BN, MM / BM, 3);    // (16, 32, 3)
    gemm_hmma<<<gqkv, 256, GEMM_SMEM>>>(xhi, tq, tk, tv);

    dim3 ga(LL / 64, HH, BB);          // (32, 16, 2)
    attn_mma<<<ga, 128, ATTN_SMEM>>>(qhi, khi, vhi, mhi);

    GemmTask tc = {whi + 3*DD*DD, nullptr, 1.0f, out, nullptr};
    dim3 go(DD / BN, MM / BM, 1);      // (16, 32, 1)
    gemm_hmma<<<go, 256, GEMM_SMEM>>>(mhi, tc, tc, tc);
}

// round 10
// speedup vs baseline: 10.8761x; 1.0833x over previous
#include <cuda_runtime.h>
#include <cuda_fp16.h>
#include <cstdint>

// Problem shape (fixed)
#define BB 2
#define LL 2048
#define DD 1024
#define HH 16
#define HD 64
#define MM (BB*LL)   // 4096

typedef __half fp16;

// ---------------------------------------------------------------------------
// Scratch (__device__ globals: allocation-free rule)
// ---------------------------------------------------------------------------
__device__ fp16 g_xhi[MM*DD];
__device__ fp16 g_whi[4*DD*DD];
__device__ fp16 g_qhi[MM*DD];
__device__ fp16 g_khi[MM*DD];
__device__ fp16 g_vhi[MM*DD];
__device__ fp16 g_mhi[MM*DD];

// ---------------------------------------------------------------------------
// Helpers (portable ISA only)
// ---------------------------------------------------------------------------
__device__ __forceinline__ uint32_t smem_u32(const void* p) {
    uint32_t a;
    asm("{ .reg .u64 t; cvta.to.shared.u64 t, %1; cvt.u32.u64 %0, t; }" : "=r"(a) : "l"(p));
    return a;
}
__device__ __forceinline__ void ldsm_x4(uint32_t& r0, uint32_t& r1, uint32_t& r2, uint32_t& r3,
                                        uint32_t addr) {
    asm volatile("ldmatrix.sync.aligned.m8n8.x4.shared.b16 {%0,%1,%2,%3}, [%4];"
                 : "=r"(r0), "=r"(r1), "=r"(r2), "=r"(r3) : "r"(addr));
}
__device__ __forceinline__ void ldsm_x4t(uint32_t& r0, uint32_t& r1, uint32_t& r2, uint32_t& r3,
                                         uint32_t addr) {
    asm volatile("ldmatrix.sync.aligned.m8n8.x4.trans.shared.b16 {%0,%1,%2,%3}, [%4];"
                 : "=r"(r0), "=r"(r1), "=r"(r2), "=r"(r3) : "r"(addr));
}
__device__ __forceinline__ void mma4(float* c, const uint32_t* a, const uint32_t* b) {
    asm volatile("mma.sync.aligned.m16n8k16.row.col.f32.f16.f16.f32 "
                 "{%0,%1,%2,%3}, {%4,%5,%6,%7}, {%8,%9}, {%0,%1,%2,%3};"
                 : "+f"(c[0]), "+f"(c[1]), "+f"(c[2]), "+f"(c[3])
                 : "r"(a[0]), "r"(a[1]), "r"(a[2]), "r"(a[3]), "r"(b[0]), "r"(b[1]));
}
__device__ __forceinline__ void cp16(uint32_t dst, const void* src) {
    asm volatile("cp.async.cg.shared.global [%0], [%1], 16;" :: "r"(dst), "l"(src));
}
#define CP_COMMIT() asm volatile("cp.async.commit_group;" ::: "memory")
#define CP_WAIT(N)  asm volatile("cp.async.wait_group %0;" :: "n"(N) : "memory")

// ---------------------------------------------------------------------------
// fp32 -> rounded fp16 conversion: x + 4 weight matrices, one launch.
// blockIdx.y: 0..3 -> weights, 4 -> x (bigger n4; excess blocks exit).
// ---------------------------------------------------------------------------
__global__ __launch_bounds__(256) void split_all(const float* __restrict__ x,
                                                 const float* __restrict__ w0,
                                                 const float* __restrict__ w1,
                                                 const float* __restrict__ w2,
                                                 const float* __restrict__ w3,
                                                 fp16* __restrict__ xhi,
                                                 fp16* __restrict__ whi,
                                                 int nx4, int nw4) {
    int i = blockIdx.x * 256 + threadIdx.x;
    int z = blockIdx.y;
    const float* src;
    fp16* dst;
    int n4;
    if (z == 4) { src = x; dst = xhi; n4 = nx4; }
    else {
        src = z == 0 ? w0 : z == 1 ? w1 : z == 2 ? w2 : w3;
        dst = whi + (size_t)z * DD * DD;
        n4 = nw4;
    }
    if (i >= n4) return;
    float4 v = reinterpret_cast<const float4*>(src)[i];
    __half2* H = reinterpret_cast<__half2*>(dst);
    H[2*i]   = __floats2half2_rn(v.x, v.y);
    H[2*i+1] = __floats2half2_rn(v.z, v.w);
}

// ---------------------------------------------------------------------------
// HMMA GEMM, single-pass fp16, 3-stage cp.async pipeline, multi-task blockIdx.z.
// C = Ahi @ Whi^T + bias.  Epilogue: fp32 OR scaled fp16.
// CTA 128x64, BK=32, 256 threads (8 warps, 4x2, 32x32 each).
// ---------------------------------------------------------------------------
#define GK 1024
#define BM 128
#define BN 64
#define BK 32
#define SZ_A (BM*40*2)                // 10240 B (row stride 80 B)
#define SZ_W (BN*40*2)                // 5120 B
#define STG  (SZ_A + SZ_W)            // 15360 B per stage
#define NSTG 3
#define GEMM_SMEM (NSTG*STG)          // 46080 B

struct GemmTask {
    const fp16* Whi;
    const float* bias; float scale;
    float* Cf; fp16* Chi;
};

__global__ __launch_bounds__(256) void gemm_hmma(const fp16* __restrict__ Ahi,
                                                 GemmTask t0, GemmTask t1, GemmTask t2) {
    extern __shared__ __align__(16) char dsm[];
    const GemmTask tk = blockIdx.z == 0 ? t0 : blockIdx.z == 1 ? t1 : t2;
    const fp16* __restrict__ Whi = tk.Whi;

    const uint32_t sb0 = smem_u32(dsm);
    const int tid  = threadIdx.x;
    const int wid  = tid >> 5;
    const int lane = tid & 31;
    const int wm   = wid >> 1;
    const int wn   = wid & 1;
    const int bm   = blockIdx.y * BM;
    const int bn   = blockIdx.x * BN;

    float acc[2][4][4];
#pragma unroll
    for (int i = 0; i < 2; i++)
#pragma unroll
        for (int j = 0; j < 4; j++)
#pragma unroll
            for (int k = 0; k < 4; k++) acc[i][j][k] = 0.f;

    auto issue = [&](int stg, int k0) {
        uint32_t base = sb0 + stg * STG;
#pragma unroll
        for (int i = 0; i < 2; i++) {
            int c = tid + 256 * i;
            int r = c >> 2, q = c & 3;
            cp16(base + r * 80 + q * 16, Ahi + (size_t)(bm + r) * GK + k0 + q * 8);
        }
        {
            int r = tid >> 2, q = tid & 3;
            cp16(base + SZ_A + r * 80 + q * 16, Whi + (size_t)(bn + r) * GK + k0 + q * 8);
        }
        CP_COMMIT();
    };

    const int a_r    = lane & 15;
    const int a_half = lane >> 4;
    const int b_rr   = lane & 7;
    const int b_nt   = (lane >> 4) & 1;
    const int b_kh   = (lane >> 3) & 1;

    const int NIT = GK / BK;     // 32
    issue(0, 0);
    issue(1, BK);
    for (int it = 0; it < NIT; it++) {
        if (it + 2 < NIT) { issue((it + 2) % NSTG, (it + 2) * BK); CP_WAIT(2); }
        else if (it + 1 < NIT) { CP_WAIT(1); }
        else { CP_WAIT(0); }
        __syncthreads();

        const uint32_t base = sb0 + (it % NSTG) * STG;
        const uint32_t aAhi = base;
        const uint32_t aWhi = base + SZ_A;

#pragma unroll
        for (int ks = 0; ks < 2; ks++) {
            const int kk = ks * 16;
            uint32_t ah[2][4];
#pragma unroll
            for (int mt = 0; mt < 2; mt++) {
                uint32_t off = (uint32_t)(wm * 32 + mt * 16 + a_r) * 80 + (kk + a_half * 8) * 2;
                ldsm_x4(ah[mt][0], ah[mt][1], ah[mt][2], ah[mt][3], aAhi + off);
            }
            uint32_t bh[4][2];
#pragma unroll
            for (int p = 0; p < 2; p++) {
                uint32_t off = (uint32_t)(wn * 32 + p * 16 + b_nt * 8 + b_rr) * 80
                             + (kk + b_kh * 8) * 2;
                ldsm_x4(bh[p*2][0], bh[p*2][1], bh[p*2+1][0], bh[p*2+1][1], aWhi + off);
            }
#pragma unroll
            for (int mt = 0; mt < 2; mt++)
#pragma unroll
                for (int nt = 0; nt < 4; nt++)
                    mma4(acc[mt][nt], ah[mt], bh[nt]);
        }
        __syncthreads();
    }

    // ---- epilogue ----
    const int gid = lane >> 2;
    const int tig = lane & 3;
#pragma unroll
    for (int mt = 0; mt < 2; mt++) {
#pragma unroll
        for (int nt = 0; nt < 4; nt++) {
            int row = bm + wm * 32 + mt * 16 + gid;
            int col = bn + wn * 32 + nt * 8 + 2 * tig;
            float b0 = tk.bias ? tk.bias[col]     : 0.f;
            float b1 = tk.bias ? tk.bias[col + 1] : 0.f;
            float v00 = (acc[mt][nt][0] + b0) * tk.scale;
            float v01 = (acc[mt][nt][1] + b1) * tk.scale;
            float v10 = (acc[mt][nt][2] + b0) * tk.scale;
            float v11 = (acc[mt][nt][3] + b1) * tk.scale;
            if (tk.Cf) {
                *reinterpret_cast<float2*>(tk.Cf + (size_t)row * GK + col)       = make_float2(v00, v01);
                *reinterpret_cast<float2*>(tk.Cf + (size_t)(row + 8) * GK + col) = make_float2(v10, v11);
            } else {
                *reinterpret_cast<__half2*>(tk.Chi + (size_t)row * GK + col) =
                    __floats2half2_rn(v00, v01);
                *reinterpret_cast<__half2*>(tk.Chi + (size_t)(row + 8) * GK + col) =
                    __floats2half2_rn(v10, v11);
            }
        }
    }
}

// ---------------------------------------------------------------------------
// HMMA flash attention, double-buffered KV, all-fp16 single-pass MMAs.
// S = Qhi Khi^T; O += P Vhi (P rounded to fp16; fp32 online softmax).
// Block = 128 threads (4 warps), 64 query rows, KV tiles of 64.
// smem/stage: Kh, Vh -> 36 KB total. Reversed i0 order.
// ---------------------------------------------------------------------------
#define AROWB 144                       // bytes per 64-col fp16 row (72 elems)
#define ATILE_B (64*AROWB)              // 9216 B per array
#define ASTG_B (2*ATILE_B)              // Kh,Vh per stage = 18432 B
#define ATTN_SMEM (2*ASTG_B)            // 36864 B

__global__ __launch_bounds__(128, 4) void attn_mma(const fp16* __restrict__ Qhi,
                                                   const fp16* __restrict__ Khi,
                                                   const fp16* __restrict__ Vhi,
                                                   fp16* __restrict__ Ohi) {
    extern __shared__ __align__(16) char asm_[];
    const uint32_t sb = smem_u32(asm_);

    const int i0 = (int)(gridDim.x - 1 - blockIdx.x) * 64;   // reversed order
    const int h  = blockIdx.y;
    const int b  = blockIdx.z;
    const int tid  = threadIdx.x;
    const int w    = tid >> 5;
    const int lane = tid & 31;
    const int gid  = lane >> 2;
    const int tig  = lane & 3;
    const int r0   = w * 16;

    const size_t baseq = ((size_t)(b * LL + i0)) * DD + h * HD;

    auto issueKV = [&](uint32_t stg, int j0) {
        const size_t basekv = ((size_t)(b * LL + j0)) * DD + h * HD;
#pragma unroll
        for (int i = 0; i < 4; i++) {
            int c = tid + 128 * i;
            int r = c >> 3, q = c & 7;
            const size_t off = basekv + (size_t)r * DD + q * 8;
            const uint32_t d = stg + r * AROWB + q * 16;
            cp16(d,           Khi + off);
            cp16(d + ATILE_B, Vhi + off);
        }
        CP_COMMIT();
    };

    // ---- stage Q through stage-1 K buffer; prefetch KV tile 0 into stage 0 ----
#pragma unroll
    for (int i = 0; i < 4; i++) {
        int c = tid + 128 * i;
        int r = c >> 3, q = c & 7;
        cp16(sb + ASTG_B + r * AROWB + q * 16, Qhi + baseq + (size_t)r * DD + q * 8);
    }
    CP_COMMIT();
    issueKV(sb, 0);
    CP_WAIT(1);               // Q ready (KV0 may still be in flight)
    __syncthreads();

    const int a_r = lane & 15, a_h = lane >> 4;
    uint32_t qh[4][4];
#pragma unroll
    for (int ks = 0; ks < 4; ks++) {
        uint32_t off = (uint32_t)(r0 + a_r) * AROWB + (ks * 16 + a_h * 8) * 2;
        ldsm_x4(qh[ks][0], qh[ks][1], qh[ks][2], qh[ks][3], sb + ASTG_B + off);
    }
    __syncthreads();          // Q buffer free for KV reuse

    float o[8][4];
#pragma unroll
    for (int nt = 0; nt < 8; nt++)
#pragma unroll
        for (int k = 0; k < 4; k++) o[nt][k] = 0.f;
    float mrow0 = -1e30f, mrow1 = -1e30f, lrow0 = 0.f, lrow1 = 0.f;

    const int b_rr = lane & 7;
    const int b_nt = (lane >> 4) & 1;
    const int b_kh = (lane >> 3) & 1;

    const int T = i0 / 64 + 1;
    for (int t = 0; t < T; t++) {
        if (t + 1 < T) { issueKV(sb + ((t + 1) & 1) * ASTG_B, (t + 1) * 64); CP_WAIT(1); }
        else           { CP_WAIT(0); }
        __syncthreads();

        const uint32_t aKh = sb + (t & 1) * ASTG_B;
        const uint32_t aVh = aKh + ATILE_B;

        // ---- S = Q K^T (1-pass) ----
        float s[8][4];
#pragma unroll
        for (int nt = 0; nt < 8; nt++)
#pragma unroll
            for (int k = 0; k < 4; k++) s[nt][k] = 0.f;

#pragma unroll
        for (int ks = 0; ks < 4; ks++) {
            const int kk = ks * 16;
            uint32_t kh[8][2];
#pragma unroll
            for (int p = 0; p < 4; p++) {
                uint32_t off = (uint32_t)(p * 16 + b_nt * 8 + b_rr) * AROWB + (kk + b_kh * 8) * 2;
                ldsm_x4(kh[p*2][0], kh[p*2][1], kh[p*2+1][0], kh[p*2+1][1], aKh + off);
            }
#pragma unroll
            for (int nt = 0; nt < 8; nt++)
                mma4(s[nt], qh[ks], kh[nt]);
        }

        // ---- causal mask (diagonal tile only; reversed order: t==T-1) ----
        if (t == T - 1) {
#pragma unroll
            for (int nt = 0; nt < 8; nt++) {
                int col0 = nt * 8 + 2 * tig;
                int rowa = r0 + gid, rowb = rowa + 8;
                if (col0     > rowa) s[nt][0] = -1e30f;
                if (col0 + 1 > rowa) s[nt][1] = -1e30f;
                if (col0     > rowb) s[nt][2] = -1e30f;
                if (col0 + 1 > rowb) s[nt][3] = -1e30f;
            }
        }

        // ---- online softmax (quad reduction) ----
        float mxa = -1e30f, mxb = -1e30f;
#pragma unroll
        for (int nt = 0; nt < 8; nt++) {
            mxa = fmaxf(mxa, fmaxf(s[nt][0], s[nt][1]));
            mxb = fmaxf(mxb, fmaxf(s[nt][2], s[nt][3]));
        }
        mxa = fmaxf(mxa, __shfl_xor_sync(0xFFFFFFFFu, mxa, 1));
        mxa = fmaxf(mxa, __shfl_xor_sync(0xFFFFFFFFu, mxa, 2));
        mxb = fmaxf(mxb, __shfl_xor_sync(0xFFFFFFFFu, mxb, 1));
        mxb = fmaxf(mxb, __shfl_xor_sync(0xFFFFFFFFu, mxb, 2));

        float mna = fmaxf(mrow0, mxa), mnb = fmaxf(mrow1, mxb);
        float ala = __expf(mrow0 - mna), alb = __expf(mrow1 - mnb);
        float suma = 0.f, sumb = 0.f;
#pragma unroll
        for (int nt = 0; nt < 8; nt++) {
            s[nt][0] = __expf(s[nt][0] - mna); suma += s[nt][0];
            s[nt][1] = __expf(s[nt][1] - mna); suma += s[nt][1];
            s[nt][2] = __expf(s[nt][2] - mnb); sumb += s[nt][2];
            s[nt][3] = __expf(s[nt][3] - mnb); sumb += s[nt][3];
        }
        suma += __shfl_xor_sync(0xFFFFFFFFu, suma, 1);
        suma += __shfl_xor_sync(0xFFFFFFFFu, suma, 2);
        sumb += __shfl_xor_sync(0xFFFFFFFFu, sumb, 1);
        sumb += __shfl_xor_sync(0xFFFFFFFFu, sumb, 2);
        lrow0 = lrow0 * ala + suma; mrow0 = mna;
        lrow1 = lrow1 * alb + sumb; mrow1 = mnb;

#pragma unroll
        for (int nt = 0; nt < 8; nt++) {
            o[nt][0] *= ala; o[nt][1] *= ala;
            o[nt][2] *= alb; o[nt][3] *= alb;
        }

        // ---- O += P V (1-pass; P rounded to fp16 from S regs) ----
#pragma unroll
        for (int ks2 = 0; ks2 < 4; ks2++) {
            const float* sa  = s[2*ks2];
            const float* sb2 = s[2*ks2 + 1];
            uint32_t phi[4];
            {
                __half2 h0 = __floats2half2_rn(sa[0], sa[1]);
                __half2 h1 = __floats2half2_rn(sa[2], sa[3]);
                __half2 h2 = __floats2half2_rn(sb2[0], sb2[1]);
                __half2 h3 = __floats2half2_rn(sb2[2], sb2[3]);
                phi[0] = *reinterpret_cast<uint32_t*>(&h0);
                phi[1] = *reinterpret_cast<uint32_t*>(&h1);
                phi[2] = *reinterpret_cast<uint32_t*>(&h2);
                phi[3] = *reinterpret_cast<uint32_t*>(&h3);
            }
            uint32_t vh[8][2];
#pragma unroll
            for (int p = 0; p < 4; p++) {
                uint32_t off = (uint32_t)(ks2 * 16 + b_kh * 8 + b_rr) * AROWB
                             + (p * 16 + b_nt * 8) * 2;
                ldsm_x4t(vh[p*2][0], vh[p*2][1], vh[p*2+1][0], vh[p*2+1][1], aVh + off);
            }
#pragma unroll
            for (int nt = 0; nt < 8; nt++)
                mma4(o[nt], phi, vh[nt]);
        }
        __syncthreads();
    }

    // ---- epilogue: normalize, round to fp16, store ----
    const float inv0 = 1.0f / lrow0;
    const float inv1 = 1.0f / lrow1;
    const size_t rowa = (size_t)(b * LL + i0 + r0 + gid) * DD + h * HD;
    const size_t rowb = rowa + (size_t)8 * DD;
#pragma unroll
    for (int nt = 0; nt < 8; nt++) {
        int col = nt * 8 + 2 * tig;
        *reinterpret_cast<__half2*>(Ohi + rowa + col) =
            __floats2half2_rn(o[nt][0] * inv0, o[nt][1] * inv0);
        *reinterpret_cast<__half2*>(Ohi + rowb + col) =
            __floats2half2_rn(o[nt][2] * inv1, o[nt][3] * inv1);
    }
}

// ---------------------------------------------------------------------------
extern "C" void kernel_launch(void* const* d_in, const int* in_sizes, int n_in,
                              void* d_out, int out_size) {
    const float* x  = (const float*)d_in[0];
    const float* WQ = (const float*)d_in[1];
    const float* bQ = (const float*)d_in[2];
    const float* WK = (const float*)d_in[3];
    const float* bK = (const float*)d_in[4];
    const float* WV = (const float*)d_in[5];
    const float* bV = (const float*)d_in[6];
    const float* Wc = (const float*)d_in[7];
    float* out = (float*)d_out;

    cudaFuncSetAttribute(gemm_hmma, cudaFuncAttributeMaxDynamicSharedMemorySize, GEMM_SMEM);
    cudaFuncSetAttribute(attn_mma,  cudaFuncAttributeMaxDynamicSharedMemorySize, ATTN_SMEM);

    fp16 *xhi, *whi, *qhi, *khi, *vhi, *mhi;
    cudaGetSymbolAddress((void**)&xhi, g_xhi);
    cudaGetSymbolAddress((void**)&whi, g_whi);
    cudaGetSymbolAddress((void**)&qhi, g_qhi);
    cudaGetSymbolAddress((void**)&khi, g_khi);
    cudaGetSymbolAddress((void**)&vhi, g_vhi);
    cudaGetSymbolAddress((void**)&mhi, g_mhi);

    const int nx4 = MM * DD / 4;     // 1048576
    const int nw4 = DD * DD / 4;     // 262144

    dim3 gs((nx4 + 255) / 256, 5);   // y=0..3 weights, y=4 x
    split_all<<<gs, 256>>>(x, WQ, WK, WV, Wc, xhi, whi, nx4, nw4);

    GemmTask tq = {whi + 0*DD*DD, bQ, 0.125f, nullptr, qhi};
    GemmTask tk = {whi + 1*DD*DD, bK, 1.0f,   nullptr, khi};
    GemmTask tv = {whi + 2*DD*DD, bV, 1.0f,   nullptr, vhi};
    dim3 gqkv(DD / BN, MM / BM, 3);    // (16, 32, 3)
    gemm_hmma<<<gqkv, 256, GEMM_SMEM>>>(xhi, tq, tk, tv);

    dim3 ga(LL / 64, HH, BB);          // (32, 16, 2)
    attn_mma<<<ga, 128, ATTN_SMEM>>>(qhi, khi, vhi, mhi);

    GemmTask tc = {whi + 3*DD*DD, nullptr, 1.0f, out, nullptr};
    dim3 go(DD / BN, MM / BM, 1);      // (16, 32, 1)
    gemm_hmma<<<go, 256, GEMM_SMEM>>>(mhi, tc, tc, tc);
}

// round 11
// speedup vs baseline: 10.9807x; 1.0096x over previous
#include <cuda_runtime.h>
#include <cuda_fp16.h>
#include <cstdint>

// Problem shape (fixed)
#define BB 2
#define LL 2048
#define DD 1024
#define HH 16
#define HD 64
#define MM (BB*LL)   // 4096

typedef __half fp16;

// ---------------------------------------------------------------------------
// Scratch (__device__ globals: allocation-free rule)
// ---------------------------------------------------------------------------
__device__ fp16 g_xhi[MM*DD];
__device__ fp16 g_whi[4*DD*DD];
__device__ fp16 g_qhi[MM*DD];
__device__ fp16 g_khi[MM*DD];
__device__ fp16 g_vhi[MM*DD];
__device__ fp16 g_mhi[MM*DD];

// ---------------------------------------------------------------------------
// Helpers (portable ISA only)
// ---------------------------------------------------------------------------
__device__ __forceinline__ uint32_t smem_u32(const void* p) {
    uint32_t a;
    asm("{ .reg .u64 t; cvta.to.shared.u64 t, %1; cvt.u32.u64 %0, t; }" : "=r"(a) : "l"(p));
    return a;
}
__device__ __forceinline__ void ldsm_x4(uint32_t& r0, uint32_t& r1, uint32_t& r2, uint32_t& r3,
                                        uint32_t addr) {
    asm volatile("ldmatrix.sync.aligned.m8n8.x4.shared.b16 {%0,%1,%2,%3}, [%4];"
                 : "=r"(r0), "=r"(r1), "=r"(r2), "=r"(r3) : "r"(addr));
}
__device__ __forceinline__ void ldsm_x4t(uint32_t& r0, uint32_t& r1, uint32_t& r2, uint32_t& r3,
                                         uint32_t addr) {
    asm volatile("ldmatrix.sync.aligned.m8n8.x4.trans.shared.b16 {%0,%1,%2,%3}, [%4];"
                 : "=r"(r0), "=r"(r1), "=r"(r2), "=r"(r3) : "r"(addr));
}
__device__ __forceinline__ void mma4(float* c, const uint32_t* a, const uint32_t* b) {
    asm volatile("mma.sync.aligned.m16n8k16.row.col.f32.f16.f16.f32 "
                 "{%0,%1,%2,%3}, {%4,%5,%6,%7}, {%8,%9}, {%0,%1,%2,%3};"
                 : "+f"(c[0]), "+f"(c[1]), "+f"(c[2]), "+f"(c[3])
                 : "r"(a[0]), "r"(a[1]), "r"(a[2]), "r"(a[3]), "r"(b[0]), "r"(b[1]));
}
__device__ __forceinline__ void cp16(uint32_t dst, const void* src) {
    asm volatile("cp.async.cg.shared.global [%0], [%1], 16;" :: "r"(dst), "l"(src));
}
#define CP_COMMIT() asm volatile("cp.async.commit_group;" ::: "memory")
#define CP_WAIT(N)  asm volatile("cp.async.wait_group %0;" :: "n"(N) : "memory")

// ---------------------------------------------------------------------------
// fp32 -> rounded fp16 conversion: x + 4 weight matrices, one launch.
// blockIdx.y: 0..3 -> weights, 4 -> x (bigger n4; excess blocks exit).
// ---------------------------------------------------------------------------
__global__ __launch_bounds__(256) void split_all(const float* __restrict__ x,
                                                 const float* __restrict__ w0,
                                                 const float* __restrict__ w1,
                                                 const float* __restrict__ w2,
                                                 const float* __restrict__ w3,
                                                 fp16* __restrict__ xhi,
                                                 fp16* __restrict__ whi,
                                                 int nx4, int nw4) {
    int i = blockIdx.x * 256 + threadIdx.x;
    int z = blockIdx.y;
    const float* src;
    fp16* dst;
    int n4;
    if (z == 4) { src = x; dst = xhi; n4 = nx4; }
    else {
        src = z == 0 ? w0 : z == 1 ? w1 : z == 2 ? w2 : w3;
        dst = whi + (size_t)z * DD * DD;
        n4 = nw4;
    }
    if (i >= n4) return;
    float4 v = reinterpret_cast<const float4*>(src)[i];
    __half2* H = reinterpret_cast<__half2*>(dst);
    H[2*i]   = __floats2half2_rn(v.x, v.y);
    H[2*i+1] = __floats2half2_rn(v.z, v.w);
}

// ---------------------------------------------------------------------------
// HMMA GEMM, single-pass fp16, 3-stage cp.async pipeline, ONE sync per iter.
// C = Ahi @ Whi^T + bias.  Epilogue: fp32 OR scaled fp16.
// CTA 64x64, BK=32, 128 threads (4 warps, 2x2, warp tile 32x32).
// Small CTA -> ~7 CTAs/SM: latency-bound loop gets real occupancy.
// ---------------------------------------------------------------------------
#define GK 1024
#define BM 64
#define BN 64
#define BK 32
#define SZ_A (BM*40*2)                // 5120 B (row stride 80 B)
#define SZ_W (BN*40*2)                // 5120 B
#define STG  (SZ_A + SZ_W)            // 10240 B per stage
#define NSTG 3
#define GEMM_SMEM (NSTG*STG)          // 30720 B

struct GemmTask {
    const fp16* Whi;
    const float* bias; float scale;
    float* Cf; fp16* Chi;
};

__global__ __launch_bounds__(128) void gemm_hmma(const fp16* __restrict__ Ahi,
                                                 GemmTask t0, GemmTask t1, GemmTask t2) {
    extern __shared__ __align__(16) char dsm[];
    const GemmTask tk = blockIdx.z == 0 ? t0 : blockIdx.z == 1 ? t1 : t2;
    const fp16* __restrict__ Whi = tk.Whi;

    const uint32_t sb0 = smem_u32(dsm);
    const int tid  = threadIdx.x;
    const int wid  = tid >> 5;
    const int lane = tid & 31;
    const int wm   = wid >> 1;      // 0..1
    const int wn   = wid & 1;       // 0..1
    const int bm   = blockIdx.y * BM;
    const int bn   = blockIdx.x * BN;

    float acc[2][4][4];
#pragma unroll
    for (int i = 0; i < 2; i++)
#pragma unroll
        for (int j = 0; j < 4; j++)
#pragma unroll
            for (int k = 0; k < 4; k++) acc[i][j][k] = 0.f;

    auto issue = [&](int stg, int k0) {
        uint32_t base = sb0 + stg * STG;
#pragma unroll
        for (int i = 0; i < 2; i++) {
            int c = tid + 128 * i;
            int r = c >> 2, q = c & 3;
            cp16(base + r * 80 + q * 16,        Ahi + (size_t)(bm + r) * GK + k0 + q * 8);
            cp16(base + SZ_A + r * 80 + q * 16, Whi + (size_t)(bn + r) * GK + k0 + q * 8);
        }
        CP_COMMIT();
    };

    const int a_r    = lane & 15;
    const int a_half = lane >> 4;
    const int b_rr   = lane & 7;
    const int b_nt   = (lane >> 4) & 1;
    const int b_kh   = (lane >> 3) & 1;

    const int NIT = GK / BK;     // 32
    issue(0, 0);
    issue(1, BK);
    for (int it = 0; it < NIT; it++) {
        if (it + 1 < NIT) { CP_WAIT(1); } else { CP_WAIT(0); }
        __syncthreads();
        if (it + 2 < NIT) issue((it + 2) % NSTG, (it + 2) * BK);

        const uint32_t base = sb0 + (it % NSTG) * STG;
        const uint32_t aAhi = base;
        const uint32_t aWhi = base + SZ_A;

#pragma unroll
        for (int ks = 0; ks < 2; ks++) {
            const int kk = ks * 16;
            uint32_t ah[2][4];
#pragma unroll
            for (int mt = 0; mt < 2; mt++) {
                uint32_t off = (uint32_t)(wm * 32 + mt * 16 + a_r) * 80 + (kk + a_half * 8) * 2;
                ldsm_x4(ah[mt][0], ah[mt][1], ah[mt][2], ah[mt][3], aAhi + off);
            }
            uint32_t bh[4][2];
#pragma unroll
            for (int p = 0; p < 2; p++) {
                uint32_t off = (uint32_t)(wn * 32 + p * 16 + b_nt * 8 + b_rr) * 80
                             + (kk + b_kh * 8) * 2;
                ldsm_x4(bh[p*2][0], bh[p*2][1], bh[p*2+1][0], bh[p*2+1][1], aWhi + off);
            }
#pragma unroll
            for (int mt = 0; mt < 2; mt++)
#pragma unroll
                for (int nt = 0; nt < 4; nt++)
                    mma4(acc[mt][nt], ah[mt], bh[nt]);
        }
    }

    // ---- epilogue ----
    const int gid = lane >> 2;
    const int tig = lane & 3;
#pragma unroll
    for (int mt = 0; mt < 2; mt++) {
#pragma unroll
        for (int nt = 0; nt < 4; nt++) {
            int row = bm + wm * 32 + mt * 16 + gid;
            int col = bn + wn * 32 + nt * 8 + 2 * tig;
            float b0 = tk.bias ? tk.bias[col]     : 0.f;
            float b1 = tk.bias ? tk.bias[col + 1] : 0.f;
            float v00 = (acc[mt][nt][0] + b0) * tk.scale;
            float v01 = (acc[mt][nt][1] + b1) * tk.scale;
            float v10 = (acc[mt][nt][2] + b0) * tk.scale;
            float v11 = (acc[mt][nt][3] + b1) * tk.scale;
            if (tk.Cf) {
                *reinterpret_cast<float2*>(tk.Cf + (size_t)row * GK + col)       = make_float2(v00, v01);
                *reinterpret_cast<float2*>(tk.Cf + (size_t)(row + 8) * GK + col) = make_float2(v10, v11);
            } else {
                *reinterpret_cast<__half2*>(tk.Chi + (size_t)row * GK + col) =
                    __floats2half2_rn(v00, v01);
                *reinterpret_cast<__half2*>(tk.Chi + (size_t)(row + 8) * GK + col) =
                    __floats2half2_rn(v10, v11);
            }
        }
    }
}

// ---------------------------------------------------------------------------
// HMMA flash attention, double-buffered KV, ONE sync per KV tile.
// Q pre-scaled by 0.125*log2(e) -> softmax in exp2 domain (exact).
// S = Qhi Khi^T; O += P Vhi (P rounded fp16; fp32 online softmax).
// Block = 128 threads (4 warps), 64 query rows, KV tiles of 64.
// smem/stage: Kh, Vh -> 36 KB total. Reversed i0 order.
// ---------------------------------------------------------------------------
#define AROWB 144                       // bytes per 64-col fp16 row (72 elems)
#define ATILE_B (64*AROWB)              // 9216 B per array
#define ASTG_B (2*ATILE_B)              // Kh,Vh per stage = 18432 B
#define ATTN_SMEM (2*ASTG_B)            // 36864 B

__global__ __launch_bounds__(128, 4) void attn_mma(const fp16* __restrict__ Qhi,
                                                   const fp16* __restrict__ Khi,
                                                   const fp16* __restrict__ Vhi,
                                                   fp16* __restrict__ Ohi) {
    extern __shared__ __align__(16) char asm_[];
    const uint32_t sb = smem_u32(asm_);

    const int i0 = (int)(gridDim.x - 1 - blockIdx.x) * 64;   // reversed order
    const int h  = blockIdx.y;
    const int b  = blockIdx.z;
    const int tid  = threadIdx.x;
    const int w    = tid >> 5;
    const int lane = tid & 31;
    const int gid  = lane >> 2;
    const int tig  = lane & 3;
    const int r0   = w * 16;

    const size_t baseq = ((size_t)(b * LL + i0)) * DD + h * HD;

    auto issueKV = [&](uint32_t stg, int j0) {
        const size_t basekv = ((size_t)(b * LL + j0)) * DD + h * HD;
#pragma unroll
        for (int i = 0; i < 4; i++) {
            int c = tid + 128 * i;
            int r = c >> 3, q = c & 7;
            const size_t off = basekv + (size_t)r * DD + q * 8;
            const uint32_t d = stg + r * AROWB + q * 16;
            cp16(d,           Khi + off);
            cp16(d + ATILE_B, Vhi + off);
        }
        CP_COMMIT();
    };

    // ---- stage Q through stage-1 K buffer; prefetch KV tile 0 into stage 0 ----
#pragma unroll
    for (int i = 0; i < 4; i++) {
        int c = tid + 128 * i;
        int r = c >> 3, q = c & 7;
        cp16(sb + ASTG_B + r * AROWB + q * 16, Qhi + baseq + (size_t)r * DD + q * 8);
    }
    CP_COMMIT();
    issueKV(sb, 0);
    CP_WAIT(1);               // Q ready (KV0 may still be in flight)
    __syncthreads();

    const int a_r = lane & 15, a_h = lane >> 4;
    uint32_t qh[4][4];
#pragma unroll
    for (int ks = 0; ks < 4; ks++) {
        uint32_t off = (uint32_t)(r0 + a_r) * AROWB + (ks * 16 + a_h * 8) * 2;
        ldsm_x4(qh[ks][0], qh[ks][1], qh[ks][2], qh[ks][3], sb + ASTG_B + off);
    }
    // no sync needed: first overwrite of Q buffer (KV tile 1) is issued only
    // after the t=0 barrier, which all warps reach after their Q ldsm.

    float o[8][4];
#pragma unroll
    for (int nt = 0; nt < 8; nt++)
#pragma unroll
        for (int k = 0; k < 4; k++) o[nt][k] = 0.f;
    float mrow0 = -1e30f, mrow1 = -1e30f, lrow0 = 0.f, lrow1 = 0.f;

    const int b_rr = lane & 7;
    const int b_nt = (lane >> 4) & 1;
    const int b_kh = (lane >> 3) & 1;

    const int T = i0 / 64 + 1;
    for (int t = 0; t < T; t++) {
        CP_WAIT(0);           // KV_t complete (issued last iter -> fully overlapped)
        __syncthreads();      // also: everyone done reading stage (t+1)&1 from iter t-1
        if (t + 1 < T) issueKV(sb + ((t + 1) & 1) * ASTG_B, (t + 1) * 64);

        const uint32_t aKh = sb + (t & 1) * ASTG_B;
        const uint32_t aVh = aKh + ATILE_B;

        // ---- S = Q K^T (1-pass; exp2-domain scores) ----
        float s[8][4];
#pragma unroll
        for (int nt = 0; nt < 8; nt++)
#pragma unroll
            for (int k = 0; k < 4; k++) s[nt][k] = 0.f;

#pragma unroll
        for (int ks = 0; ks < 4; ks++) {
            const int kk = ks * 16;
            uint32_t kh[8][2];
#pragma unroll
            for (int p = 0; p < 4; p++) {
                uint32_t off = (uint32_t)(p * 16 + b_nt * 8 + b_rr) * AROWB + (kk + b_kh * 8) * 2;
                ldsm_x4(kh[p*2][0], kh[p*2][1], kh[p*2+1][0], kh[p*2+1][1], aKh + off);
            }
#pragma unroll
            for (int nt = 0; nt < 8; nt++)
                mma4(s[nt], qh[ks], kh[nt]);
        }

        // ---- causal mask (diagonal tile only; reversed order: t==T-1) ----
        if (t == T - 1) {
#pragma unroll
            for (int nt = 0; nt < 8; nt++) {
                int col0 = nt * 8 + 2 * tig;
                int rowa = r0 + gid, rowb = rowa + 8;
                if (col0     > rowa) s[nt][0] = -1e30f;
                if (col0 + 1 > rowa) s[nt][1] = -1e30f;
                if (col0     > rowb) s[nt][2] = -1e30f;
                if (col0 + 1 > rowb) s[nt][3] = -1e30f;
            }
        }

        // ---- online softmax, exp2 domain (quad reduction) ----
        float mxa = -1e30f, mxb = -1e30f;
#pragma unroll
        for (int nt = 0; nt < 8; nt++) {
            mxa = fmaxf(mxa, fmaxf(s[nt][0], s[nt][1]));
            mxb = fmaxf(mxb, fmaxf(s[nt][2], s[nt][3]));
        }
        mxa = fmaxf(mxa, __shfl_xor_sync(0xFFFFFFFFu, mxa, 1));
        mxa = fmaxf(mxa, __shfl_xor_sync(0xFFFFFFFFu, mxa, 2));
        mxb = fmaxf(mxb, __shfl_xor_sync(0xFFFFFFFFu, mxb, 1));
        mxb = fmaxf(mxb, __shfl_xor_sync(0xFFFFFFFFu, mxb, 2));

        float mna = fmaxf(mrow0, mxa), mnb = fmaxf(mrow1, mxb);
        float ala = exp2f(mrow0 - mna), alb = exp2f(mrow1 - mnb);
        float suma = 0.f, sumb = 0.f;
#pragma unroll
        for (int nt = 0; nt < 8; nt++) {
            s[nt][0] = exp2f(s[nt][0] - mna); suma += s[nt][0];
            s[nt][1] = exp2f(s[nt][1] - mna); suma += s[nt][1];
            s[nt][2] = exp2f(s[nt][2] - mnb); sumb += s[nt][2];
            s[nt][3] = exp2f(s[nt][3] - mnb); sumb += s[nt][3];
        }
        suma += __shfl_xor_sync(0xFFFFFFFFu, suma, 1);
        suma += __shfl_xor_sync(0xFFFFFFFFu, suma, 2);
        sumb += __shfl_xor_sync(0xFFFFFFFFu, sumb, 1);
        sumb += __shfl_xor_sync(0xFFFFFFFFu, sumb, 2);
        lrow0 = lrow0 * ala + suma; mrow0 = mna;
        lrow1 = lrow1 * alb + sumb; mrow1 = mnb;

#pragma unroll
        for (int nt = 0; nt < 8; nt++) {
            o[nt][0] *= ala; o[nt][1] *= ala;
            o[nt][2] *= alb; o[nt][3] *= alb;
        }

        // ---- O += P V (1-pass; P rounded to fp16 from S regs) ----
#pragma unroll
        for (int ks2 = 0; ks2 < 4; ks2++) {
            const float* sa  = s[2*ks2];
            const float* sb2 = s[2*ks2 + 1];
            uint32_t phi[4];
            {
                __half2 h0 = __floats2half2_rn(sa[0], sa[1]);
                __half2 h1 = __floats2half2_rn(sa[2], sa[3]);
                __half2 h2 = __floats2half2_rn(sb2[0], sb2[1]);
                __half2 h3 = __floats2half2_rn(sb2[2], sb2[3]);
                phi[0] = *reinterpret_cast<uint32_t*>(&h0);
                phi[1] = *reinterpret_cast<uint32_t*>(&h1);
                phi[2] = *reinterpret_cast<uint32_t*>(&h2);
                phi[3] = *reinterpret_cast<uint32_t*>(&h3);
            }
            uint32_t vh[8][2];
#pragma unroll
            for (int p = 0; p < 4; p++) {
                uint32_t off = (uint32_t)(ks2 * 16 + b_kh * 8 + b_rr) * AROWB
                             + (p * 16 + b_nt * 8) * 2;
                ldsm_x4t(vh[p*2][0], vh[p*2][1], vh[p*2+1][0], vh[p*2+1][1], aVh + off);
            }
#pragma unroll
            for (int nt = 0; nt < 8; nt++)
                mma4(o[nt], phi, vh[nt]);
        }
    }

    // ---- epilogue: normalize, round to fp16, store ----
    const float inv0 = 1.0f / lrow0;
    const float inv1 = 1.0f / lrow1;
    const size_t rowa = (size_t)(b * LL + i0 + r0 + gid) * DD + h * HD;
    const size_t rowb = rowa + (size_t)8 * DD;
#pragma unroll
    for (int nt = 0; nt < 8; nt++) {
        int col = nt * 8 + 2 * tig;
        *reinterpret_cast<__half2*>(Ohi + rowa + col) =
            __floats2half2_rn(o[nt][0] * inv0, o[nt][1] * inv0);
        *reinterpret_cast<__half2*>(Ohi + rowb + col) =
            __floats2half2_rn(o[nt][2] * inv1, o[nt][3] * inv1);
    }
}

// ---------------------------------------------------------------------------
extern "C" void kernel_launch(void* const* d_in, const int* in_sizes, int n_in,
                              void* d_out, int out_size) {
    const float* x  = (const float*)d_in[0];
    const float* WQ = (const float*)d_in[1];
    const float* bQ = (const float*)d_in[2];
    const float* WK = (const float*)d_in[3];
    const float* bK = (const float*)d_in[4];
    const float* WV = (const float*)d_in[5];
    const float* bV = (const float*)d_in[6];
    const float* Wc = (const float*)d_in[7];
    float* out = (float*)d_out;

    cudaFuncSetAttribute(gemm_hmma, cudaFuncAttributeMaxDynamicSharedMemorySize, GEMM_SMEM);
    cudaFuncSetAttribute(attn_mma,  cudaFuncAttributeMaxDynamicSharedMemorySize, ATTN_SMEM);

    fp16 *xhi, *whi, *qhi, *khi, *vhi, *mhi;
    cudaGetSymbolAddress((void**)&xhi, g_xhi);
    cudaGetSymbolAddress((void**)&whi, g_whi);
    cudaGetSymbolAddress((void**)&qhi, g_qhi);
    cudaGetSymbolAddress((void**)&khi, g_khi);
    cudaGetSymbolAddress((void**)&vhi, g_vhi);
    cudaGetSymbolAddress((void**)&mhi, g_mhi);

    const int nx4 = MM * DD / 4;     // 1048576
    const int nw4 = DD * DD / 4;     // 262144

    dim3 gs((nx4 + 255) / 256, 5);   // y=0..3 weights, y=4 x
    split_all<<<gs, 256>>>(x, WQ, WK, WV, Wc, xhi, whi, nx4, nw4);

    // Q scale folds in log2(e) so attention softmax runs in exp2 domain.
    const float QSCALE = 0.125f * 1.4426950408889634f;
    GemmTask tq = {whi + 0*DD*DD, bQ, QSCALE, nullptr, qhi};
    GemmTask tk = {whi + 1*DD*DD, bK, 1.0f,   nullptr, khi};
    GemmTask tv = {whi + 2*DD*DD, bV, 1.0f,   nullptr, vhi};
    dim3 gqkv(DD / BN, MM / BM, 3);    // (16, 64, 3)
    gemm_hmma<<<gqkv, 128, GEMM_SMEM>>>(xhi, tq, tk, tv);

    dim3 ga(LL / 64, HH, BB);          // (32, 16, 2)
    attn_mma<<<ga, 128, ATTN_SMEM>>>(qhi, khi, vhi, mhi);

    GemmTask tc = {whi + 3*DD*DD, nullptr, 1.0f, out, nullptr};
    dim3 go(DD / BN, MM / BM, 1);      // (16, 64, 1)
    gemm_hmma<<<go, 128, GEMM_SMEM>>>(mhi, tc, tc, tc);
}

// round 12
// speedup vs baseline: 11.2258x; 1.0223x over previous
#include <cuda_runtime.h>
#include <cuda_fp16.h>
#include <cstdint>

// Problem shape (fixed)
#define BB 2
#define LL 2048
#define DD 1024
#define HH 16
#define HD 64
#define MM (BB*LL)   // 4096

typedef __half fp16;

// ---------------------------------------------------------------------------
// Scratch (__device__ globals: allocation-free rule)
// ---------------------------------------------------------------------------
__device__ fp16 g_xhi[MM*DD];
__device__ fp16 g_whi[4*DD*DD];
__device__ fp16 g_qhi[MM*DD];
__device__ fp16 g_khi[MM*DD];
__device__ fp16 g_vhi[MM*DD];
__device__ fp16 g_mhi[MM*DD];

// ---------------------------------------------------------------------------
// Helpers (portable ISA only)
// ---------------------------------------------------------------------------
__device__ __forceinline__ uint32_t smem_u32(const void* p) {
    uint32_t a;
    asm("{ .reg .u64 t; cvta.to.shared.u64 t, %1; cvt.u32.u64 %0, t; }" : "=r"(a) : "l"(p));
    return a;
}
__device__ __forceinline__ void ldsm_x4(uint32_t& r0, uint32_t& r1, uint32_t& r2, uint32_t& r3,
                                        uint32_t addr) {
    asm volatile("ldmatrix.sync.aligned.m8n8.x4.shared.b16 {%0,%1,%2,%3}, [%4];"
                 : "=r"(r0), "=r"(r1), "=r"(r2), "=r"(r3) : "r"(addr));
}
__device__ __forceinline__ void ldsm_x4t(uint32_t& r0, uint32_t& r1, uint32_t& r2, uint32_t& r3,
                                         uint32_t addr) {
    asm volatile("ldmatrix.sync.aligned.m8n8.x4.trans.shared.b16 {%0,%1,%2,%3}, [%4];"
                 : "=r"(r0), "=r"(r1), "=r"(r2), "=r"(r3) : "r"(addr));
}
__device__ __forceinline__ void mma4(float* c, const uint32_t* a, const uint32_t* b) {
    asm volatile("mma.sync.aligned.m16n8k16.row.col.f32.f16.f16.f32 "
                 "{%0,%1,%2,%3}, {%4,%5,%6,%7}, {%8,%9}, {%0,%1,%2,%3};"
                 : "+f"(c[0]), "+f"(c[1]), "+f"(c[2]), "+f"(c[3])
                 : "r"(a[0]), "r"(a[1]), "r"(a[2]), "r"(a[3]), "r"(b[0]), "r"(b[1]));
}
__device__ __forceinline__ void cp16(uint32_t dst, const void* src) {
    asm volatile("cp.async.cg.shared.global [%0], [%1], 16;" :: "r"(dst), "l"(src));
}
#define CP_COMMIT() asm volatile("cp.async.commit_group;" ::: "memory")
#define CP_WAIT(N)  asm volatile("cp.async.wait_group %0;" :: "n"(N) : "memory")

// ---------------------------------------------------------------------------
// fp32 -> rounded fp16 conversion: x + 4 weight matrices, one launch.
// blockIdx.y: 0..3 -> weights, 4 -> x (bigger n4; excess blocks exit).
// ---------------------------------------------------------------------------
__global__ __launch_bounds__(256) void split_all(const float* __restrict__ x,
                                                 const float* __restrict__ w0,
                                                 const float* __restrict__ w1,
                                                 const float* __restrict__ w2,
                                                 const float* __restrict__ w3,
                                                 fp16* __restrict__ xhi,
                                                 fp16* __restrict__ whi,
                                                 int nx4, int nw4) {
    int i = blockIdx.x * 256 + threadIdx.x;
    int z = blockIdx.y;
    const float* src;
    fp16* dst;
    int n4;
    if (z == 4) { src = x; dst = xhi; n4 = nx4; }
    else {
        src = z == 0 ? w0 : z == 1 ? w1 : z == 2 ? w2 : w3;
        dst = whi + (size_t)z * DD * DD;
        n4 = nw4;
    }
    if (i >= n4) return;
    float4 v = reinterpret_cast<const float4*>(src)[i];
    __half2* H = reinterpret_cast<__half2*>(dst);
    H[2*i]   = __floats2half2_rn(v.x, v.y);
    H[2*i+1] = __floats2half2_rn(v.z, v.w);
}

// ---------------------------------------------------------------------------
// HMMA GEMM, single-pass fp16, 3-stage cp.async pipeline, one sync per iter.
// C = Ahi @ Whi^T + bias.  Epilogue: fp32 OR scaled fp16.
// CTA 128x128, BK=32, 256 threads. 8 warps in 2x4, warp tile 64x32.
// Intensity: 1 B/output elem of L2 traffic (half of 64x64 tiling);
// per-ks ldsm:mma = 6:16 (A frags reused over 4 n-tiles, B over 4 m-tiles).
// ---------------------------------------------------------------------------
#define GK 1024
#define BM 128
#define BN 128
#define BK 32
#define SZ_A (BM*40*2)                // 10240 B (row stride 80 B)
#define SZ_W (BN*40*2)                // 10240 B
#define STG  (SZ_A + SZ_W)            // 20480 B per stage
#define NSTG 3
#define GEMM_SMEM (NSTG*STG)          // 61440 B

struct GemmTask {
    const fp16* Whi;
    const float* bias; float scale;
    float* Cf; fp16* Chi;
};

__global__ __launch_bounds__(256) void gemm_hmma(const fp16* __restrict__ Ahi,
                                                 GemmTask t0, GemmTask t1, GemmTask t2) {
    extern __shared__ __align__(16) char dsm[];
    const GemmTask tk = blockIdx.z == 0 ? t0 : blockIdx.z == 1 ? t1 : t2;
    const fp16* __restrict__ Whi = tk.Whi;

    const uint32_t sb0 = smem_u32(dsm);
    const int tid  = threadIdx.x;
    const int wid  = tid >> 5;
    const int lane = tid & 31;
    const int wm   = wid >> 2;      // 0..1 -> 64-row slab
    const int wn   = wid & 3;       // 0..3 -> 32-col slab
    const int bm   = blockIdx.y * BM;
    const int bn   = blockIdx.x * BN;

    float acc[4][4][4];
#pragma unroll
    for (int i = 0; i < 4; i++)
#pragma unroll
        for (int j = 0; j < 4; j++)
#pragma unroll
            for (int k = 0; k < 4; k++) acc[i][j][k] = 0.f;

    auto issue = [&](int stg, int k0) {
        uint32_t base = sb0 + stg * STG;
#pragma unroll
        for (int i = 0; i < 2; i++) {
            int c = tid + 256 * i;          // 0..511
            int r = c >> 2, q = c & 3;      // 128 rows x 4 chunks
            cp16(base + r * 80 + q * 16,        Ahi + (size_t)(bm + r) * GK + k0 + q * 8);
            cp16(base + SZ_A + r * 80 + q * 16, Whi + (size_t)(bn + r) * GK + k0 + q * 8);
        }
        CP_COMMIT();
    };

    const int a_r    = lane & 15;
    const int a_half = lane >> 4;
    const int b_rr   = lane & 7;
    const int b_nt   = (lane >> 4) & 1;
    const int b_kh   = (lane >> 3) & 1;

    const int NIT = GK / BK;     // 32
    issue(0, 0);
    issue(1, BK);
    for (int it = 0; it < NIT; it++) {
        if (it + 1 < NIT) { CP_WAIT(1); } else { CP_WAIT(0); }
        __syncthreads();
        if (it + 2 < NIT) issue((it + 2) % NSTG, (it + 2) * BK);

        const uint32_t base = sb0 + (it % NSTG) * STG;
        const uint32_t aAhi = base;
        const uint32_t aWhi = base + SZ_A;

#pragma unroll
        for (int ks = 0; ks < 2; ks++) {
            const int kk = ks * 16;
            uint32_t ah[4][4];
#pragma unroll
            for (int mt = 0; mt < 4; mt++) {
                uint32_t off = (uint32_t)(wm * 64 + mt * 16 + a_r) * 80 + (kk + a_half * 8) * 2;
                ldsm_x4(ah[mt][0], ah[mt][1], ah[mt][2], ah[mt][3], aAhi + off);
            }
            uint32_t bh[4][2];
#pragma unroll
            for (int p = 0; p < 2; p++) {
                uint32_t off = (uint32_t)(wn * 32 + p * 16 + b_nt * 8 + b_rr) * 80
                             + (kk + b_kh * 8) * 2;
                ldsm_x4(bh[p*2][0], bh[p*2][1], bh[p*2+1][0], bh[p*2+1][1], aWhi + off);
            }
#pragma unroll
            for (int mt = 0; mt < 4; mt++)
#pragma unroll
                for (int nt = 0; nt < 4; nt++)
                    mma4(acc[mt][nt], ah[mt], bh[nt]);
        }
    }

    // ---- epilogue ----
    const int gid = lane >> 2;
    const int tig = lane & 3;
#pragma unroll
    for (int mt = 0; mt < 4; mt++) {
#pragma unroll
        for (int nt = 0; nt < 4; nt++) {
            int row = bm + wm * 64 + mt * 16 + gid;
            int col = bn + wn * 32 + nt * 8 + 2 * tig;
            float b0 = tk.bias ? tk.bias[col]     : 0.f;
            float b1 = tk.bias ? tk.bias[col + 1] : 0.f;
            float v00 = (acc[mt][nt][0] + b0) * tk.scale;
            float v01 = (acc[mt][nt][1] + b1) * tk.scale;
            float v10 = (acc[mt][nt][2] + b0) * tk.scale;
            float v11 = (acc[mt][nt][3] + b1) * tk.scale;
            if (tk.Cf) {
                *reinterpret_cast<float2*>(tk.Cf + (size_t)row * GK + col)       = make_float2(v00, v01);
                *reinterpret_cast<float2*>(tk.Cf + (size_t)(row + 8) * GK + col) = make_float2(v10, v11);
            } else {
                *reinterpret_cast<__half2*>(tk.Chi + (size_t)row * GK + col) =
                    __floats2half2_rn(v00, v01);
                *reinterpret_cast<__half2*>(tk.Chi + (size_t)(row + 8) * GK + col) =
                    __floats2half2_rn(v10, v11);
            }
        }
    }
}

// ---------------------------------------------------------------------------
// HMMA flash attention, double-buffered KV, ONE sync per KV tile.
// Q pre-scaled by 0.125*log2(e) -> softmax in exp2 domain (exact).
// S = Qhi Khi^T; O += P Vhi (P rounded fp16; fp32 online softmax).
// Block = 128 threads (4 warps), 64 query rows, KV tiles of 64.
// smem/stage: Kh, Vh -> 36 KB total. Reversed i0 order.
// ---------------------------------------------------------------------------
#define AROWB 144                       // bytes per 64-col fp16 row (72 elems)
#define ATILE_B (64*AROWB)              // 9216 B per array
#define ASTG_B (2*ATILE_B)              // Kh,Vh per stage = 18432 B
#define ATTN_SMEM (2*ASTG_B)            // 36864 B

__global__ __launch_bounds__(128, 4) void attn_mma(const fp16* __restrict__ Qhi,
                                                   const fp16* __restrict__ Khi,
                                                   const fp16* __restrict__ Vhi,
                                                   fp16* __restrict__ Ohi) {
    extern __shared__ __align__(16) char asm_[];
    const uint32_t sb = smem_u32(asm_);

    const int i0 = (int)(gridDim.x - 1 - blockIdx.x) * 64;   // reversed order
    const int h  = blockIdx.y;
    const int b  = blockIdx.z;
    const int tid  = threadIdx.x;
    const int w    = tid >> 5;
    const int lane = tid & 31;
    const int gid  = lane >> 2;
    const int tig  = lane & 3;
    const int r0   = w * 16;

    const size_t baseq = ((size_t)(b * LL + i0)) * DD + h * HD;

    auto issueKV = [&](uint32_t stg, int j0) {
        const size_t basekv = ((size_t)(b * LL + j0)) * DD + h * HD;
#pragma unroll
        for (int i = 0; i < 4; i++) {
            int c = tid + 128 * i;
            int r = c >> 3, q = c & 7;
            const size_t off = basekv + (size_t)r * DD + q * 8;
            const uint32_t d = stg + r * AROWB + q * 16;
            cp16(d,           Khi + off);
            cp16(d + ATILE_B, Vhi + off);
        }
        CP_COMMIT();
    };

    // ---- stage Q through stage-1 K buffer; prefetch KV tile 0 into stage 0 ----
#pragma unroll
    for (int i = 0; i < 4; i++) {
        int c = tid + 128 * i;
        int r = c >> 3, q = c & 7;
        cp16(sb + ASTG_B + r * AROWB + q * 16, Qhi + baseq + (size_t)r * DD + q * 8);
    }
    CP_COMMIT();
    issueKV(sb, 0);
    CP_WAIT(1);               // Q ready (KV0 may still be in flight)
    __syncthreads();

    const int a_r = lane & 15, a_h = lane >> 4;
    uint32_t qh[4][4];
#pragma unroll
    for (int ks = 0; ks < 4; ks++) {
        uint32_t off = (uint32_t)(r0 + a_r) * AROWB + (ks * 16 + a_h * 8) * 2;
        ldsm_x4(qh[ks][0], qh[ks][1], qh[ks][2], qh[ks][3], sb + ASTG_B + off);
    }
    // first overwrite of Q buffer (KV tile 1) is issued only after the t=0
    // barrier, which all warps reach after their Q ldsm -> no extra sync.

    float o[8][4];
#pragma unroll
    for (int nt = 0; nt < 8; nt++)
#pragma unroll
        for (int k = 0; k < 4; k++) o[nt][k] = 0.f;
    float mrow0 = -1e30f, mrow1 = -1e30f, lrow0 = 0.f, lrow1 = 0.f;

    const int b_rr = lane & 7;
    const int b_nt = (lane >> 4) & 1;
    const int b_kh = (lane >> 3) & 1;

    const int T = i0 / 64 + 1;
    for (int t = 0; t < T; t++) {
        CP_WAIT(0);           // KV_t complete (issued last iter -> fully overlapped)
        __syncthreads();      // also: everyone done reading stage (t+1)&1 from iter t-1
        if (t + 1 < T) issueKV(sb + ((t + 1) & 1) * ASTG_B, (t + 1) * 64);

        const uint32_t aKh = sb + (t & 1) * ASTG_B;
        const uint32_t aVh = aKh + ATILE_B;

        // ---- S = Q K^T (1-pass; exp2-domain scores) ----
        float s[8][4];
#pragma unroll
        for (int nt = 0; nt < 8; nt++)
#pragma unroll
            for (int k = 0; k < 4; k++) s[nt][k] = 0.f;

#pragma unroll
        for (int ks = 0; ks < 4; ks++) {
            const int kk = ks * 16;
            uint32_t kh[8][2];
#pragma unroll
            for (int p = 0; p < 4; p++) {
                uint32_t off = (uint32_t)(p * 16 + b_nt * 8 + b_rr) * AROWB + (kk + b_kh * 8) * 2;
                ldsm_x4(kh[p*2][0], kh[p*2][1], kh[p*2+1][0], kh[p*2+1][1], aKh + off);
            }
#pragma unroll
            for (int nt = 0; nt < 8; nt++)
                mma4(s[nt], qh[ks], kh[nt]);
        }

        // ---- causal mask (diagonal tile only; reversed order: t==T-1) ----
        if (t == T - 1) {
#pragma unroll
            for (int nt = 0; nt < 8; nt++) {
                int col0 = nt * 8 + 2 * tig;
                int rowa = r0 + gid, rowb = rowa + 8;
                if (col0     > rowa) s[nt][0] = -1e30f;
                if (col0 + 1 > rowa) s[nt][1] = -1e30f;
                if (col0     > rowb) s[nt][2] = -1e30f;
                if (col0 + 1 > rowb) s[nt][3] = -1e30f;
            }
        }

        // ---- online softmax, exp2 domain (quad reduction) ----
        float mxa = -1e30f, mxb = -1e30f;
#pragma unroll
        for (int nt = 0; nt < 8; nt++) {
            mxa = fmaxf(mxa, fmaxf(s[nt][0], s[nt][1]));
            mxb = fmaxf(mxb, fmaxf(s[nt][2], s[nt][3]));
        }
        mxa = fmaxf(mxa, __shfl_xor_sync(0xFFFFFFFFu, mxa, 1));
        mxa = fmaxf(mxa, __shfl_xor_sync(0xFFFFFFFFu, mxa, 2));
        mxb = fmaxf(mxb, __shfl_xor_sync(0xFFFFFFFFu, mxb, 1));
        mxb = fmaxf(mxb, __shfl_xor_sync(0xFFFFFFFFu, mxb, 2));

        float mna = fmaxf(mrow0, mxa), mnb = fmaxf(mrow1, mxb);
        float ala = exp2f(mrow0 - mna), alb = exp2f(mrow1 - mnb);
        float suma = 0.f, sumb = 0.f;
#pragma unroll
        for (int nt = 0; nt < 8; nt++) {
            s[nt][0] = exp2f(s[nt][0] - mna); suma += s[nt][0];
            s[nt][1] = exp2f(s[nt][1] - mna); suma += s[nt][1];
            s[nt][2] = exp2f(s[nt][2] - mnb); sumb += s[nt][2];
            s[nt][3] = exp2f(s[nt][3] - mnb); sumb += s[nt][3];
        }
        suma += __shfl_xor_sync(0xFFFFFFFFu, suma, 1);
        suma += __shfl_xor_sync(0xFFFFFFFFu, suma, 2);
        sumb += __shfl_xor_sync(0xFFFFFFFFu, sumb, 1);
        sumb += __shfl_xor_sync(0xFFFFFFFFu, sumb, 2);
        lrow0 = lrow0 * ala + suma; mrow0 = mna;
        lrow1 = lrow1 * alb + sumb; mrow1 = mnb;

#pragma unroll
        for (int nt = 0; nt < 8; nt++) {
            o[nt][0] *= ala; o[nt][1] *= ala;
            o[nt][2] *= alb; o[nt][3] *= alb;
        }

        // ---- O += P V (1-pass; P rounded to fp16 from S regs) ----
#pragma unroll
        for (int ks2 = 0; ks2 < 4; ks2++) {
            const float* sa  = s[2*ks2];
            const float* sb2 = s[2*ks2 + 1];
            uint32_t phi[4];
            {
                __half2 h0 = __floats2half2_rn(sa[0], sa[1]);
                __half2 h1 = __floats2half2_rn(sa[2], sa[3]);
                __half2 h2 = __floats2half2_rn(sb2[0], sb2[1]);
                __half2 h3 = __floats2half2_rn(sb2[2], sb2[3]);
                phi[0] = *reinterpret_cast<uint32_t*>(&h0);
                phi[1] = *reinterpret_cast<uint32_t*>(&h1);
                phi[2] = *reinterpret_cast<uint32_t*>(&h2);
                phi[3] = *reinterpret_cast<uint32_t*>(&h3);
            }
            uint32_t vh[8][2];
#pragma unroll
            for (int p = 0; p < 4; p++) {
                uint32_t off = (uint32_t)(ks2 * 16 + b_kh * 8 + b_rr) * AROWB
                             + (p * 16 + b_nt * 8) * 2;
                ldsm_x4t(vh[p*2][0], vh[p*2][1], vh[p*2+1][0], vh[p*2+1][1], aVh + off);
            }
#pragma unroll
            for (int nt = 0; nt < 8; nt++)
                mma4(o[nt], phi, vh[nt]);
        }
    }

    // ---- epilogue: normalize, round to fp16, store ----
    const float inv0 = 1.0f / lrow0;
    const float inv1 = 1.0f / lrow1;
    const size_t rowa = (size_t)(b * LL + i0 + r0 + gid) * DD + h * HD;
    const size_t rowb = rowa + (size_t)8 * DD;
#pragma unroll
    for (int nt = 0; nt < 8; nt++) {
        int col = nt * 8 + 2 * tig;
        *reinterpret_cast<__half2*>(Ohi + rowa + col) =
            __floats2half2_rn(o[nt][0] * inv0, o[nt][1] * inv0);
        *reinterpret_cast<__half2*>(Ohi + rowb + col) =
            __floats2half2_rn(o[nt][2] * inv1, o[nt][3] * inv1);
    }
}

// ---------------------------------------------------------------------------
extern "C" void kernel_launch(void* const* d_in, const int* in_sizes, int n_in,
                              void* d_out, int out_size) {
    const float* x  = (const float*)d_in[0];
    const float* WQ = (const float*)d_in[1];
    const float* bQ = (const float*)d_in[2];
    const float* WK = (const float*)d_in[3];
    const float* bK = (const float*)d_in[4];
    const float* WV = (const float*)d_in[5];
    const float* bV = (const float*)d_in[6];
    const float* Wc = (const float*)d_in[7];
    float* out = (float*)d_out;

    cudaFuncSetAttribute(gemm_hmma, cudaFuncAttributeMaxDynamicSharedMemorySize, GEMM_SMEM);
    cudaFuncSetAttribute(attn_mma,  cudaFuncAttributeMaxDynamicSharedMemorySize, ATTN_SMEM);

    fp16 *xhi, *whi, *qhi, *khi, *vhi, *mhi;
    cudaGetSymbolAddress((void**)&xhi, g_xhi);
    cudaGetSymbolAddress((void**)&whi, g_whi);
    cudaGetSymbolAddress((void**)&qhi, g_qhi);
    cudaGetSymbolAddress((void**)&khi, g_khi);
    cudaGetSymbolAddress((void**)&vhi, g_vhi);
    cudaGetSymbolAddress((void**)&mhi, g_mhi);

    const int nx4 = MM * DD / 4;     // 1048576
    const int nw4 = DD * DD / 4;     // 262144

    dim3 gs((nx4 + 255) / 256, 5);   // y=0..3 weights, y=4 x
    split_all<<<gs, 256>>>(x, WQ, WK, WV, Wc, xhi, whi, nx4, nw4);

    // Q scale folds in log2(e) so attention softmax runs in exp2 domain.
    const float QSCALE = 0.125f * 1.4426950408889634f;
    GemmTask tq = {whi + 0*DD*DD, bQ, QSCALE, nullptr, qhi};
    GemmTask tk = {whi + 1*DD*DD, bK, 1.0f,   nullptr, khi};
    GemmTask tv = {whi + 2*DD*DD, bV, 1.0f,   nullptr, vhi};
    dim3 gqkv(DD / BN, MM / BM, 3);    // (8, 32, 3)
    gemm_hmma<<<gqkv, 256, GEMM_SMEM>>>(xhi, tq, tk, tv);

    dim3 ga(LL / 64, HH, BB);          // (32, 16, 2)
    attn_mma<<<ga, 128, ATTN_SMEM>>>(qhi, khi, vhi, mhi);

    GemmTask tc = {whi + 3*DD*DD, nullptr, 1.0f, out, nullptr};
    dim3 go(DD / BN, MM / BM, 1);      // (8, 32, 1)
    gemm_hmma<<<go, 256, GEMM_SMEM>>>(mhi, tc, tc, tc);
}